// round 1
// baseline (speedup 1.0000x reference)
#include <cuda_runtime.h>
#include <math.h>
#include <stdint.h>

// ---------------- problem constants ----------------
#define HDIM   2048
#define NH     16
#define QLORA  1536
#define KVLORA 512
#define DN     128
#define DR     64
#define DV     128
#define QD     192          // DN + DR
#define BB     2
#define SS     2048
#define MTOT   (BB*SS)      // 4096
#define CKVW   (KVLORA+DR)  // 576
#define KVW    (NH*(DN+DV)) // 4096
#define QW     (NH*QD)      // 3072
#define OW     (NH*DV)      // 2048

// ---------------- scratch (device globals: allocation-free) ----------------
__device__ float d_qa  [(size_t)MTOT*QLORA];
__device__ float d_q   [(size_t)MTOT*QW];
__device__ float d_ckv [(size_t)MTOT*CKVW];
__device__ float d_kv  [(size_t)MTOT*KVW];
__device__ float d_kpe [(size_t)MTOT*DR];
__device__ float d_attn[(size_t)MTOT*OW];

// ---------------- SGEMM: C[M,N] = A[M,K] (lda) @ Bw[N,K]^T ----------------
// 128x128 block tile, BK=8, 8x8 per-thread micro-tile, 256 threads.
__global__ __launch_bounds__(256) void sgemm_tn(
    const float* __restrict__ A, const float* __restrict__ Bw, float* __restrict__ C,
    int M, int N, int K, int lda)
{
    __shared__ float As[8][128];
    __shared__ float Bs[8][128];
    const int tid = threadIdx.x;
    const int bm = blockIdx.y * 128;
    const int bn = blockIdx.x * 128;
    const int tx = tid & 15;
    const int ty = tid >> 4;
    const int lRow = tid >> 1;
    const int lCol = (tid & 1) * 4;

    const float* Aptr = A + (size_t)(bm + lRow) * lda + lCol;
    const float* Bptr = Bw + (size_t)(bn + lRow) * K + lCol;
    const bool bvalid = (bn + lRow) < N;

    float acc[8][8] = {};
    for (int k0 = 0; k0 < K; k0 += 8) {
        float4 av = *reinterpret_cast<const float4*>(Aptr + k0);
        float4 bv = bvalid ? *reinterpret_cast<const float4*>(Bptr + k0)
                           : make_float4(0.f, 0.f, 0.f, 0.f);
        As[lCol+0][lRow] = av.x; As[lCol+1][lRow] = av.y;
        As[lCol+2][lRow] = av.z; As[lCol+3][lRow] = av.w;
        Bs[lCol+0][lRow] = bv.x; Bs[lCol+1][lRow] = bv.y;
        Bs[lCol+2][lRow] = bv.z; Bs[lCol+3][lRow] = bv.w;
        __syncthreads();
        #pragma unroll
        for (int k = 0; k < 8; k++) {
            float4 a0 = *reinterpret_cast<const float4*>(&As[k][ty*8]);
            float4 a1 = *reinterpret_cast<const float4*>(&As[k][ty*8+4]);
            float4 b0 = *reinterpret_cast<const float4*>(&Bs[k][tx*8]);
            float4 b1 = *reinterpret_cast<const float4*>(&Bs[k][tx*8+4]);
            float aa[8] = {a0.x,a0.y,a0.z,a0.w,a1.x,a1.y,a1.z,a1.w};
            float bb[8] = {b0.x,b0.y,b0.z,b0.w,b1.x,b1.y,b1.z,b1.w};
            #pragma unroll
            for (int i = 0; i < 8; i++)
                #pragma unroll
                for (int j = 0; j < 8; j++)
                    acc[i][j] += aa[i] * bb[j];
        }
        __syncthreads();
    }
    #pragma unroll
    for (int i = 0; i < 8; i++) {
        const int row = bm + ty*8 + i;
        #pragma unroll
        for (int j = 0; j < 8; j += 4) {
            const int col = bn + tx*8 + j;
            if (col < N) {
                *reinterpret_cast<float4*>(&C[(size_t)row * N + col]) =
                    make_float4(acc[i][j], acc[i][j+1], acc[i][j+2], acc[i][j+3]);
            }
        }
    }
}

// ---------------- RMSNorm (in place): one block per row ----------------
__global__ void rmsnorm_kernel(float* __restrict__ x, const float* __restrict__ g,
                               int D, int stride)
{
    const int row = blockIdx.x;
    float* p = x + (size_t)row * stride;
    float ss = 0.f;
    for (int i = threadIdx.x; i < D; i += blockDim.x) { float v = p[i]; ss += v * v; }
    #pragma unroll
    for (int o = 16; o > 0; o >>= 1) ss += __shfl_xor_sync(0xffffffffu, ss, o);
    __shared__ float sred[8];
    if ((threadIdx.x & 31) == 0) sred[threadIdx.x >> 5] = ss;
    __syncthreads();
    if (threadIdx.x < 8) {
        float v = sred[threadIdx.x];
        #pragma unroll
        for (int o = 4; o > 0; o >>= 1) v += __shfl_xor_sync(0xffu, v, o);
        if (threadIdx.x == 0) sred[0] = v;
    }
    __syncthreads();
    const float inv = rsqrtf(sred[0] / (float)D + 1e-6f);
    for (int i = threadIdx.x; i < D; i += blockDim.x) p[i] = p[i] * inv * g[i];
}

// ---------------- RoPE ----------------
// grid: MTOT*NH blocks, 32 threads. In-place on q's pe slice (cols h*QD+DN .. +QD).
__global__ void rope_q_kernel(float* __restrict__ q)
{
    const int idx = blockIdx.x;
    const int row = idx / NH, h = idx % NH;
    const int t = row % SS;
    const int j = threadIdx.x;                 // 0..31
    const double inv = exp(-log(10000.0) * (2.0 * j) / (double)DR);
    const double ang = (double)t * inv;
    const float c = (float)cos(ang), s = (float)sin(ang);
    float* p = q + (size_t)row * QW + h * QD + DN;
    const float x0 = p[j], x1 = p[j + 32];
    p[j]      = x0 * c - x1 * s;
    p[j + 32] = x1 * c + x0 * s;
}

// grid: MTOT blocks, 32 threads. Reads ckv cols [512,576), writes roped kpe.
__global__ void rope_k_kernel(const float* __restrict__ ckv, float* __restrict__ kpe)
{
    const int row = blockIdx.x;
    const int t = row % SS;
    const int j = threadIdx.x;
    const double inv = exp(-log(10000.0) * (2.0 * j) / (double)DR);
    const double ang = (double)t * inv;
    const float c = (float)cos(ang), s = (float)sin(ang);
    const float* p = ckv + (size_t)row * CKVW + KVLORA;
    const float x0 = p[j], x1 = p[j + 32];
    kpe[(size_t)row * DR + j]      = x0 * c - x1 * s;
    kpe[(size_t)row * DR + j + 32] = x1 * c + x0 * s;
}

// ---------------- causal flash attention ----------------
// grid: (S/64, NH, B), 256 threads. BM=64 queries, BN=32 keys per iter.
// thread map: tx = tid&7 (column group), ty = tid>>3 (2 query rows each).
#define FA_BM 64
#define FA_BN 32
#define QSTR  196   // 192 + 4 pad
#define VSTR  132   // 128 + 4 pad
#define PSTR  33    // 32 + 1 pad

__global__ __launch_bounds__(256) void flash_kernel(
    const float* __restrict__ q,     // [MTOT][QW]
    const float* __restrict__ kv,    // [MTOT][KVW]
    const float* __restrict__ kpe,   // [MTOT][DR]
    float* __restrict__ attn)        // [MTOT][OW]
{
    extern __shared__ float smem[];
    float* Qs = smem;                       // [64][QSTR]
    float* Ks = Qs + FA_BM * QSTR;          // [32][QSTR]
    float* Vs = Ks + FA_BN * QSTR;          // [32][VSTR]
    float* Ps = Vs + FA_BN * VSTR;          // [64][PSTR]

    const int qb  = blockIdx.x;
    const int h   = blockIdx.y;
    const int b   = blockIdx.z;
    const int tid = threadIdx.x;
    const int tx  = tid & 7;
    const int ty  = tid >> 3;
    const int r0  = ty * 2, r1 = ty * 2 + 1;

    const int row0 = b * SS + qb * FA_BM;
    const float scale = rsqrtf((float)QD);

    // load Q tile (pre-scaled)
    for (int i = tid; i < FA_BM * (QD / 4); i += 256) {
        const int r = i / (QD / 4);
        const int d4 = (i % (QD / 4)) * 4;
        float4 v = *reinterpret_cast<const float4*>(&q[(size_t)(row0 + r) * QW + h * QD + d4]);
        float* dst = &Qs[r * QSTR + d4];
        dst[0] = v.x * scale; dst[1] = v.y * scale; dst[2] = v.z * scale; dst[3] = v.w * scale;
    }

    float m0 = -INFINITY, m1 = -INFINITY, l0 = 0.f, l1 = 0.f;
    float o0[16] = {}, o1[16] = {};
    const int n_tiles = 2 * (qb + 1);
    __syncthreads();

    for (int kt = 0; kt < n_tiles; kt++) {
        const int krow0 = b * SS + kt * FA_BN;
        // load K tile (nope from kv, pe from roped kpe)
        for (int i = tid; i < FA_BN * (QD / 4); i += 256) {
            const int c = i / (QD / 4);
            const int d4 = (i % (QD / 4)) * 4;
            float4 v;
            if (d4 < DN) v = *reinterpret_cast<const float4*>(&kv[(size_t)(krow0 + c) * KVW + h * (DN + DV) + d4]);
            else         v = *reinterpret_cast<const float4*>(&kpe[(size_t)(krow0 + c) * DR + (d4 - DN)]);
            float* dst = &Ks[c * QSTR + d4];
            dst[0] = v.x; dst[1] = v.y; dst[2] = v.z; dst[3] = v.w;
        }
        // load V tile
        for (int i = tid; i < FA_BN * (DV / 4); i += 256) {
            const int c = i / (DV / 4);
            const int d4 = (i % (DV / 4)) * 4;
            float4 v = *reinterpret_cast<const float4*>(&kv[(size_t)(krow0 + c) * KVW + h * (DN + DV) + DN + d4]);
            float* dst = &Vs[c * VSTR + d4];
            dst[0] = v.x; dst[1] = v.y; dst[2] = v.z; dst[3] = v.w;
        }
        __syncthreads();

        // scores: 2 rows x 4 cols per thread
        float sc[2][4] = {};
        const float* q0p = &Qs[r0 * QSTR];
        const float* q1p = &Qs[r1 * QSTR];
        #pragma unroll 8
        for (int d = 0; d < QD; d += 4) {
            float4 a0 = *reinterpret_cast<const float4*>(q0p + d);
            float4 a1 = *reinterpret_cast<const float4*>(q1p + d);
            #pragma unroll
            for (int j = 0; j < 4; j++) {
                float4 kk = *reinterpret_cast<const float4*>(&Ks[(tx * 4 + j) * QSTR + d]);
                sc[0][j] += a0.x * kk.x + a0.y * kk.y + a0.z * kk.z + a0.w * kk.w;
                sc[1][j] += a1.x * kk.x + a1.y * kk.y + a1.z * kk.z + a1.w * kk.w;
            }
        }

        // causal mask (only the last two tiles can cross the diagonal)
        if (kt >= 2 * qb) {
            #pragma unroll
            for (int j = 0; j < 4; j++) {
                const int kpos = kt * FA_BN + tx * 4 + j;
                if (kpos > qb * FA_BM + r0) sc[0][j] = -INFINITY;
                if (kpos > qb * FA_BM + r1) sc[1][j] = -INFINITY;
            }
        }

        // online softmax update
        float tm0 = fmaxf(fmaxf(sc[0][0], sc[0][1]), fmaxf(sc[0][2], sc[0][3]));
        float tm1 = fmaxf(fmaxf(sc[1][0], sc[1][1]), fmaxf(sc[1][2], sc[1][3]));
        #pragma unroll
        for (int o = 1; o < 8; o <<= 1) {
            tm0 = fmaxf(tm0, __shfl_xor_sync(0xffffffffu, tm0, o));
            tm1 = fmaxf(tm1, __shfl_xor_sync(0xffffffffu, tm1, o));
        }
        const float mn0 = fmaxf(m0, tm0), mn1 = fmaxf(m1, tm1);
        const float al0 = expf(m0 - mn0), al1 = expf(m1 - mn1);
        float p0[4], p1[4], ls0 = 0.f, ls1 = 0.f;
        #pragma unroll
        for (int j = 0; j < 4; j++) {
            p0[j] = expf(sc[0][j] - mn0); ls0 += p0[j];
            p1[j] = expf(sc[1][j] - mn1); ls1 += p1[j];
        }
        #pragma unroll
        for (int o = 1; o < 8; o <<= 1) {
            ls0 += __shfl_xor_sync(0xffffffffu, ls0, o);
            ls1 += __shfl_xor_sync(0xffffffffu, ls1, o);
        }
        l0 = l0 * al0 + ls0; l1 = l1 * al1 + ls1;
        m0 = mn0; m1 = mn1;
        #pragma unroll
        for (int c = 0; c < 16; c++) { o0[c] *= al0; o1[c] *= al1; }

        #pragma unroll
        for (int j = 0; j < 4; j++) {
            Ps[r0 * PSTR + tx * 4 + j] = p0[j];
            Ps[r1 * PSTR + tx * 4 + j] = p1[j];
        }
        __syncthreads();

        // O += P @ V  (thread owns cols cc*32 + tx*4 + j, cc=0..3)
        #pragma unroll 8
        for (int kk = 0; kk < FA_BN; kk++) {
            const float pa = Ps[r0 * PSTR + kk];
            const float pb = Ps[r1 * PSTR + kk];
            const float* vp = &Vs[kk * VSTR];
            #pragma unroll
            for (int cc = 0; cc < 4; cc++) {
                float4 v = *reinterpret_cast<const float4*>(vp + cc * 32 + tx * 4);
                o0[cc*4+0] += pa * v.x; o0[cc*4+1] += pa * v.y;
                o0[cc*4+2] += pa * v.z; o0[cc*4+3] += pa * v.w;
                o1[cc*4+0] += pb * v.x; o1[cc*4+1] += pb * v.y;
                o1[cc*4+2] += pb * v.z; o1[cc*4+3] += pb * v.w;
            }
        }
        __syncthreads();
    }

    const float il0 = 1.f / l0, il1 = 1.f / l1;
    #pragma unroll
    for (int cc = 0; cc < 4; cc++) {
        const int col = h * DV + cc * 32 + tx * 4;
        *reinterpret_cast<float4*>(&attn[(size_t)(row0 + r0) * OW + col]) =
            make_float4(o0[cc*4]*il0, o0[cc*4+1]*il0, o0[cc*4+2]*il0, o0[cc*4+3]*il0);
        *reinterpret_cast<float4*>(&attn[(size_t)(row0 + r1) * OW + col]) =
            make_float4(o1[cc*4]*il1, o1[cc*4+1]*il1, o1[cc*4+2]*il1, o1[cc*4+3]*il1);
    }
}

// ---------------- launch ----------------
extern "C" void kernel_launch(void* const* d_in, const int* in_sizes, int n_in,
                              void* d_out, int out_size)
{
    (void)in_sizes; (void)n_in; (void)out_size;
    const float* hidden = (const float*)d_in[0];
    const float* w_qa   = (const float*)d_in[1];
    const float* g_qa   = (const float*)d_in[2];
    const float* w_qb   = (const float*)d_in[3];
    const float* w_kva  = (const float*)d_in[4];
    const float* g_kva  = (const float*)d_in[5];
    const float* w_kvb  = (const float*)d_in[6];
    const float* w_o    = (const float*)d_in[7];
    float* out = (float*)d_out;

    float *qa, *q, *ckv, *kv, *kpe, *attn;
    cudaGetSymbolAddress((void**)&qa,   d_qa);
    cudaGetSymbolAddress((void**)&q,    d_q);
    cudaGetSymbolAddress((void**)&ckv,  d_ckv);
    cudaGetSymbolAddress((void**)&kv,   d_kv);
    cudaGetSymbolAddress((void**)&kpe,  d_kpe);
    cudaGetSymbolAddress((void**)&attn, d_attn);

    const dim3 blk(256);
    // q_a = hidden @ w_qa^T          [4096,1536]
    sgemm_tn<<<dim3(QLORA/128, MTOT/128), blk>>>(hidden, w_qa, qa, MTOT, QLORA, HDIM, HDIM);
    // ckv = hidden @ w_kva^T         [4096,576]
    sgemm_tn<<<dim3((CKVW+127)/128, MTOT/128), blk>>>(hidden, w_kva, ckv, MTOT, CKVW, HDIM, HDIM);
    // rmsnorms (in place)
    rmsnorm_kernel<<<MTOT, 256>>>(qa, g_qa, QLORA, QLORA);
    rmsnorm_kernel<<<MTOT, 256>>>(ckv, g_kva, KVLORA, CKVW);
    // q = rms(q_a) @ w_qb^T          [4096,3072]
    sgemm_tn<<<dim3(QW/128, MTOT/128), blk>>>(qa, w_qb, q, MTOT, QW, QLORA, QLORA);
    // kv = rms(ckv) @ w_kvb^T        [4096,4096]   (A stride = 576, K = 512)
    sgemm_tn<<<dim3(KVW/128, MTOT/128), blk>>>(ckv, w_kvb, kv, MTOT, KVW, KVLORA, CKVW);
    // rope
    rope_q_kernel<<<MTOT * NH, 32>>>(q);
    rope_k_kernel<<<MTOT, 32>>>(ckv, kpe);
    // causal flash attention
    const size_t shmem = (size_t)(FA_BM*QSTR + FA_BN*QSTR + FA_BN*VSTR + FA_BM*PSTR) * sizeof(float);
    cudaFuncSetAttribute(flash_kernel, cudaFuncAttributeMaxDynamicSharedMemorySize, (int)shmem);
    flash_kernel<<<dim3(SS/FA_BM, NH, BB), 256, shmem>>>(q, kv, kpe, attn);
    // out = attn @ w_o^T             [4096,2048]
    sgemm_tn<<<dim3(HDIM/128, MTOT/128), blk>>>(attn, w_o, out, MTOT, HDIM, OW, OW);
}

// round 2
// speedup vs baseline: 1.1478x; 1.1478x over previous
#include <cuda_runtime.h>
#include <math.h>
#include <stdint.h>

// ---------------- problem constants ----------------
#define HDIM   2048
#define NH     16
#define QLORA  1536
#define KVLORA 512
#define DN     128
#define DR     64
#define DV     128
#define QD     192          // DN + DR
#define BB     2
#define SS     2048
#define MTOT   (BB*SS)      // 4096
#define CKVW   (KVLORA+DR)  // 576
#define KVW    (NH*(DN+DV)) // 4096
#define QW     (NH*QD)      // 3072
#define OW     (NH*DV)      // 2048

// ---------------- scratch (device globals: allocation-free) ----------------
__device__ float d_qa  [(size_t)MTOT*QLORA];
__device__ float d_q   [(size_t)MTOT*QW];
__device__ float d_ckv [(size_t)MTOT*CKVW];
__device__ float d_kv  [(size_t)MTOT*KVW];
__device__ float d_kpe [(size_t)MTOT*DR];
__device__ float d_attn[(size_t)MTOT*OW];

// ---------------- 3xTF32 tensor-core GEMM ----------------
// C[M,N] = A[M,K] (lda) @ Bw[N,K]^T  via mma.m16n8k8 tf32, 3-pass hi/lo.
// 128x128 block tile, BK=16, 256 threads (8 warps, 32x64 warp tiles).

__device__ __forceinline__ float tf32r(float x) {
    float r;
    asm("cvt.rna.tf32.f32 %0, %1;" : "=f"(r) : "f"(x));
    return r;
}

__device__ __forceinline__ void mma_tf32(float c[4], uint32_t a0, uint32_t a1,
                                         uint32_t a2, uint32_t a3,
                                         uint32_t b0, uint32_t b1) {
    asm volatile(
        "mma.sync.aligned.m16n8k8.row.col.f32.tf32.tf32.f32 "
        "{%0,%1,%2,%3}, {%4,%5,%6,%7}, {%8,%9}, {%0,%1,%2,%3};"
        : "+f"(c[0]), "+f"(c[1]), "+f"(c[2]), "+f"(c[3])
        : "r"(a0), "r"(a1), "r"(a2), "r"(a3), "r"(b0), "r"(b1));
}

#define SK 20   // smem row stride (16 + 4 pad) -> conflict-free fragment loads

__global__ __launch_bounds__(256, 2) void gemm3x(
    const float* __restrict__ A, const float* __restrict__ Bw, float* __restrict__ C,
    int M, int N, int K, int lda)
{
    __shared__ float AsH[128 * SK];
    __shared__ float AsL[128 * SK];
    __shared__ float BsH[128 * SK];
    __shared__ float BsL[128 * SK];

    const int tid = threadIdx.x;
    const int bm = blockIdx.y * 128;
    const int bn = blockIdx.x * 128;

    // loader: each thread owns rows lr, lr+64; 4 cols starting lc
    const int lr = tid >> 2;
    const int lc = (tid & 3) * 4;
    const float* Ap = A + (size_t)(bm + lr) * lda + lc;
    const float* Bp = Bw + (size_t)(bn + lr) * K + lc;
    const bool bv0 = (bn + lr) < N;
    const bool bv1 = (bn + lr + 64) < N;

    // warp mapping
    const int w = tid >> 5, lane = tid & 31;
    const int g = lane >> 2, tig = lane & 3;
    const int m0 = (w & 3) * 32;
    const int n0 = (w >> 2) * 64;

    float acc[2][8][4] = {};
    float4 pa0, pa1, pb0, pb1;
    const float4 z4 = make_float4(0.f, 0.f, 0.f, 0.f);

    auto ldG = [&](int k0) {
        pa0 = *reinterpret_cast<const float4*>(Ap + k0);
        pa1 = *reinterpret_cast<const float4*>(Ap + (size_t)64 * lda + k0);
        pb0 = bv0 ? *reinterpret_cast<const float4*>(Bp + k0) : z4;
        pb1 = bv1 ? *reinterpret_cast<const float4*>(Bp + (size_t)64 * K + k0) : z4;
    };
    auto cvtst = [&](float* H, float* L, int off, float4 v) {
        float4 h, l;
        h.x = tf32r(v.x); l.x = tf32r(v.x - h.x);
        h.y = tf32r(v.y); l.y = tf32r(v.y - h.y);
        h.z = tf32r(v.z); l.z = tf32r(v.z - h.z);
        h.w = tf32r(v.w); l.w = tf32r(v.w - h.w);
        *reinterpret_cast<float4*>(H + off) = h;
        *reinterpret_cast<float4*>(L + off) = l;
    };
    auto stS = [&]() {
        cvtst(AsH, AsL, lr * SK + lc, pa0);
        cvtst(AsH, AsL, (lr + 64) * SK + lc, pa1);
        cvtst(BsH, BsL, lr * SK + lc, pb0);
        cvtst(BsH, BsL, (lr + 64) * SK + lc, pb1);
    };
    auto compute = [&]() {
        #pragma unroll
        for (int ks = 0; ks < 2; ks++) {
            const int k = ks * 8;
            #pragma unroll
            for (int pass = 0; pass < 3; pass++) {
                const float* Asrc = (pass == 2) ? AsL : AsH;
                const float* Bsrc = (pass == 1) ? BsL : BsH;
                uint32_t a[2][4];
                #pragma unroll
                for (int am = 0; am < 2; am++) {
                    const int r = m0 + am * 16;
                    a[am][0] = __float_as_uint(Asrc[(r + g) * SK + k + tig]);
                    a[am][1] = __float_as_uint(Asrc[(r + g + 8) * SK + k + tig]);
                    a[am][2] = __float_as_uint(Asrc[(r + g) * SK + k + tig + 4]);
                    a[am][3] = __float_as_uint(Asrc[(r + g + 8) * SK + k + tig + 4]);
                }
                #pragma unroll
                for (int an = 0; an < 8; an++) {
                    const uint32_t b0 = __float_as_uint(Bsrc[(n0 + an * 8 + g) * SK + k + tig]);
                    const uint32_t b1 = __float_as_uint(Bsrc[(n0 + an * 8 + g) * SK + k + tig + 4]);
                    mma_tf32(acc[0][an], a[0][0], a[0][1], a[0][2], a[0][3], b0, b1);
                    mma_tf32(acc[1][an], a[1][0], a[1][1], a[1][2], a[1][3], b0, b1);
                }
            }
        }
    };

    ldG(0);
    stS();
    __syncthreads();
    int k0 = 16;
    for (;;) {
        const bool more = (k0 < K);
        if (more) ldG(k0);
        compute();
        if (!more) break;
        __syncthreads();
        stS();
        __syncthreads();
        k0 += 16;
    }

    // store C
    #pragma unroll
    for (int am = 0; am < 2; am++) {
        #pragma unroll
        for (int an = 0; an < 8; an++) {
            const int col = bn + n0 + an * 8 + tig * 2;
            if (col < N) {
                const int r0 = bm + m0 + am * 16 + g;
                *reinterpret_cast<float2*>(&C[(size_t)r0 * N + col]) =
                    make_float2(acc[am][an][0], acc[am][an][1]);
                *reinterpret_cast<float2*>(&C[(size_t)(r0 + 8) * N + col]) =
                    make_float2(acc[am][an][2], acc[am][an][3]);
            }
        }
    }
}

// ---------------- RMSNorm (in place): one block per row ----------------
__global__ void rmsnorm_kernel(float* __restrict__ x, const float* __restrict__ g,
                               int D, int stride)
{
    const int row = blockIdx.x;
    float* p = x + (size_t)row * stride;
    float ss = 0.f;
    for (int i = threadIdx.x; i < D; i += blockDim.x) { float v = p[i]; ss += v * v; }
    #pragma unroll
    for (int o = 16; o > 0; o >>= 1) ss += __shfl_xor_sync(0xffffffffu, ss, o);
    __shared__ float sred[8];
    if ((threadIdx.x & 31) == 0) sred[threadIdx.x >> 5] = ss;
    __syncthreads();
    if (threadIdx.x < 8) {
        float v = sred[threadIdx.x];
        #pragma unroll
        for (int o = 4; o > 0; o >>= 1) v += __shfl_xor_sync(0xffu, v, o);
        if (threadIdx.x == 0) sred[0] = v;
    }
    __syncthreads();
    const float inv = rsqrtf(sred[0] / (float)D + 1e-6f);
    for (int i = threadIdx.x; i < D; i += blockDim.x) p[i] = p[i] * inv * g[i];
}

// ---------------- RoPE ----------------
__global__ void rope_q_kernel(float* __restrict__ q)
{
    const int idx = blockIdx.x;
    const int row = idx / NH, h = idx % NH;
    const int t = row % SS;
    const int j = threadIdx.x;                 // 0..31
    const double inv = exp(-log(10000.0) * (2.0 * j) / (double)DR);
    const double ang = (double)t * inv;
    const float c = (float)cos(ang), s = (float)sin(ang);
    float* p = q + (size_t)row * QW + h * QD + DN;
    const float x0 = p[j], x1 = p[j + 32];
    p[j]      = x0 * c - x1 * s;
    p[j + 32] = x1 * c + x0 * s;
}

__global__ void rope_k_kernel(const float* __restrict__ ckv, float* __restrict__ kpe)
{
    const int row = blockIdx.x;
    const int t = row % SS;
    const int j = threadIdx.x;
    const double inv = exp(-log(10000.0) * (2.0 * j) / (double)DR);
    const double ang = (double)t * inv;
    const float c = (float)cos(ang), s = (float)sin(ang);
    const float* p = ckv + (size_t)row * CKVW + KVLORA;
    const float x0 = p[j], x1 = p[j + 32];
    kpe[(size_t)row * DR + j]      = x0 * c - x1 * s;
    kpe[(size_t)row * DR + j + 32] = x1 * c + x0 * s;
}

// ---------------- causal flash attention ----------------
#define FA_BM 64
#define FA_BN 32
#define QSTR  196   // 192 + 4 pad
#define VSTR  132   // 128 + 4 pad
#define PSTR  33    // 32 + 1 pad

__global__ __launch_bounds__(256) void flash_kernel(
    const float* __restrict__ q,     // [MTOT][QW]
    const float* __restrict__ kv,    // [MTOT][KVW]
    const float* __restrict__ kpe,   // [MTOT][DR]
    float* __restrict__ attn)        // [MTOT][OW]
{
    extern __shared__ float smem[];
    float* Qs = smem;
    float* Ks = Qs + FA_BM * QSTR;
    float* Vs = Ks + FA_BN * QSTR;
    float* Ps = Vs + FA_BN * VSTR;

    const int qb  = blockIdx.x;
    const int h   = blockIdx.y;
    const int b   = blockIdx.z;
    const int tid = threadIdx.x;
    const int tx  = tid & 7;
    const int ty  = tid >> 3;
    const int r0  = ty * 2, r1 = ty * 2 + 1;

    const int row0 = b * SS + qb * FA_BM;
    const float scale = rsqrtf((float)QD);

    for (int i = tid; i < FA_BM * (QD / 4); i += 256) {
        const int r = i / (QD / 4);
        const int d4 = (i % (QD / 4)) * 4;
        float4 v = *reinterpret_cast<const float4*>(&q[(size_t)(row0 + r) * QW + h * QD + d4]);
        float* dst = &Qs[r * QSTR + d4];
        dst[0] = v.x * scale; dst[1] = v.y * scale; dst[2] = v.z * scale; dst[3] = v.w * scale;
    }

    float m0 = -INFINITY, m1 = -INFINITY, l0 = 0.f, l1 = 0.f;
    float o0[16] = {}, o1[16] = {};
    const int n_tiles = 2 * (qb + 1);
    __syncthreads();

    for (int kt = 0; kt < n_tiles; kt++) {
        const int krow0 = b * SS + kt * FA_BN;
        for (int i = tid; i < FA_BN * (QD / 4); i += 256) {
            const int c = i / (QD / 4);
            const int d4 = (i % (QD / 4)) * 4;
            float4 v;
            if (d4 < DN) v = *reinterpret_cast<const float4*>(&kv[(size_t)(krow0 + c) * KVW + h * (DN + DV) + d4]);
            else         v = *reinterpret_cast<const float4*>(&kpe[(size_t)(krow0 + c) * DR + (d4 - DN)]);
            float* dst = &Ks[c * QSTR + d4];
            dst[0] = v.x; dst[1] = v.y; dst[2] = v.z; dst[3] = v.w;
        }
        for (int i = tid; i < FA_BN * (DV / 4); i += 256) {
            const int c = i / (DV / 4);
            const int d4 = (i % (DV / 4)) * 4;
            float4 v = *reinterpret_cast<const float4*>(&kv[(size_t)(krow0 + c) * KVW + h * (DN + DV) + DN + d4]);
            float* dst = &Vs[c * VSTR + d4];
            dst[0] = v.x; dst[1] = v.y; dst[2] = v.z; dst[3] = v.w;
        }
        __syncthreads();

        float sc[2][4] = {};
        const float* q0p = &Qs[r0 * QSTR];
        const float* q1p = &Qs[r1 * QSTR];
        #pragma unroll 8
        for (int d = 0; d < QD; d += 4) {
            float4 a0 = *reinterpret_cast<const float4*>(q0p + d);
            float4 a1 = *reinterpret_cast<const float4*>(q1p + d);
            #pragma unroll
            for (int j = 0; j < 4; j++) {
                float4 kk = *reinterpret_cast<const float4*>(&Ks[(tx * 4 + j) * QSTR + d]);
                sc[0][j] += a0.x * kk.x + a0.y * kk.y + a0.z * kk.z + a0.w * kk.w;
                sc[1][j] += a1.x * kk.x + a1.y * kk.y + a1.z * kk.z + a1.w * kk.w;
            }
        }

        if (kt >= 2 * qb) {
            #pragma unroll
            for (int j = 0; j < 4; j++) {
                const int kpos = kt * FA_BN + tx * 4 + j;
                if (kpos > qb * FA_BM + r0) sc[0][j] = -INFINITY;
                if (kpos > qb * FA_BM + r1) sc[1][j] = -INFINITY;
            }
        }

        float tm0 = fmaxf(fmaxf(sc[0][0], sc[0][1]), fmaxf(sc[0][2], sc[0][3]));
        float tm1 = fmaxf(fmaxf(sc[1][0], sc[1][1]), fmaxf(sc[1][2], sc[1][3]));
        #pragma unroll
        for (int o = 1; o < 8; o <<= 1) {
            tm0 = fmaxf(tm0, __shfl_xor_sync(0xffffffffu, tm0, o));
            tm1 = fmaxf(tm1, __shfl_xor_sync(0xffffffffu, tm1, o));
        }
        const float mn0 = fmaxf(m0, tm0), mn1 = fmaxf(m1, tm1);
        const float al0 = expf(m0 - mn0), al1 = expf(m1 - mn1);
        float p0[4], p1[4], ls0 = 0.f, ls1 = 0.f;
        #pragma unroll
        for (int j = 0; j < 4; j++) {
            p0[j] = expf(sc[0][j] - mn0); ls0 += p0[j];
            p1[j] = expf(sc[1][j] - mn1); ls1 += p1[j];
        }
        #pragma unroll
        for (int o = 1; o < 8; o <<= 1) {
            ls0 += __shfl_xor_sync(0xffffffffu, ls0, o);
            ls1 += __shfl_xor_sync(0xffffffffu, ls1, o);
        }
        l0 = l0 * al0 + ls0; l1 = l1 * al1 + ls1;
        m0 = mn0; m1 = mn1;
        #pragma unroll
        for (int c = 0; c < 16; c++) { o0[c] *= al0; o1[c] *= al1; }

        #pragma unroll
        for (int j = 0; j < 4; j++) {
            Ps[r0 * PSTR + tx * 4 + j] = p0[j];
            Ps[r1 * PSTR + tx * 4 + j] = p1[j];
        }
        __syncthreads();

        #pragma unroll 8
        for (int kk = 0; kk < FA_BN; kk++) {
            const float pa = Ps[r0 * PSTR + kk];
            const float pb = Ps[r1 * PSTR + kk];
            const float* vp = &Vs[kk * VSTR];
            #pragma unroll
            for (int cc = 0; cc < 4; cc++) {
                float4 v = *reinterpret_cast<const float4*>(vp + cc * 32 + tx * 4);
                o0[cc*4+0] += pa * v.x; o0[cc*4+1] += pa * v.y;
                o0[cc*4+2] += pa * v.z; o0[cc*4+3] += pa * v.w;
                o1[cc*4+0] += pb * v.x; o1[cc*4+1] += pb * v.y;
                o1[cc*4+2] += pb * v.z; o1[cc*4+3] += pb * v.w;
            }
        }
        __syncthreads();
    }

    const float il0 = 1.f / l0, il1 = 1.f / l1;
    #pragma unroll
    for (int cc = 0; cc < 4; cc++) {
        const int col = h * DV + cc * 32 + tx * 4;
        *reinterpret_cast<float4*>(&attn[(size_t)(row0 + r0) * OW + col]) =
            make_float4(o0[cc*4]*il0, o0[cc*4+1]*il0, o0[cc*4+2]*il0, o0[cc*4+3]*il0);
        *reinterpret_cast<float4*>(&attn[(size_t)(row0 + r1) * OW + col]) =
            make_float4(o1[cc*4]*il1, o1[cc*4+1]*il1, o1[cc*4+2]*il1, o1[cc*4+3]*il1);
    }
}

// ---------------- launch ----------------
extern "C" void kernel_launch(void* const* d_in, const int* in_sizes, int n_in,
                              void* d_out, int out_size)
{
    (void)in_sizes; (void)n_in; (void)out_size;
    const float* hidden = (const float*)d_in[0];
    const float* w_qa   = (const float*)d_in[1];
    const float* g_qa   = (const float*)d_in[2];
    const float* w_qb   = (const float*)d_in[3];
    const float* w_kva  = (const float*)d_in[4];
    const float* g_kva  = (const float*)d_in[5];
    const float* w_kvb  = (const float*)d_in[6];
    const float* w_o    = (const float*)d_in[7];
    float* out = (float*)d_out;

    float *qa, *q, *ckv, *kv, *kpe, *attn;
    cudaGetSymbolAddress((void**)&qa,   d_qa);
    cudaGetSymbolAddress((void**)&q,    d_q);
    cudaGetSymbolAddress((void**)&ckv,  d_ckv);
    cudaGetSymbolAddress((void**)&kv,   d_kv);
    cudaGetSymbolAddress((void**)&kpe,  d_kpe);
    cudaGetSymbolAddress((void**)&attn, d_attn);

    const dim3 blk(256);
    // q_a = hidden @ w_qa^T          [4096,1536]
    gemm3x<<<dim3(QLORA/128, MTOT/128), blk>>>(hidden, w_qa, qa, MTOT, QLORA, HDIM, HDIM);
    // ckv = hidden @ w_kva^T         [4096,576]
    gemm3x<<<dim3((CKVW+127)/128, MTOT/128), blk>>>(hidden, w_kva, ckv, MTOT, CKVW, HDIM, HDIM);
    // rmsnorms (in place)
    rmsnorm_kernel<<<MTOT, 256>>>(qa, g_qa, QLORA, QLORA);
    rmsnorm_kernel<<<MTOT, 256>>>(ckv, g_kva, KVLORA, CKVW);
    // q = rms(q_a) @ w_qb^T          [4096,3072]
    gemm3x<<<dim3(QW/128, MTOT/128), blk>>>(qa, w_qb, q, MTOT, QW, QLORA, QLORA);
    // kv = rms(ckv) @ w_kvb^T        [4096,4096]
    gemm3x<<<dim3(KVW/128, MTOT/128), blk>>>(ckv, w_kvb, kv, MTOT, KVW, KVLORA, CKVW);
    // rope
    rope_q_kernel<<<MTOT * NH, 32>>>(q);
    rope_k_kernel<<<MTOT, 32>>>(ckv, kpe);
    // causal flash attention
    const size_t shmem = (size_t)(FA_BM*QSTR + FA_BN*QSTR + FA_BN*VSTR + FA_BM*PSTR) * sizeof(float);
    cudaFuncSetAttribute(flash_kernel, cudaFuncAttributeMaxDynamicSharedMemorySize, (int)shmem);
    flash_kernel<<<dim3(SS/FA_BM, NH, BB), 256, shmem>>>(q, kv, kpe, attn);
    // out = attn @ w_o^T             [4096,2048]
    gemm3x<<<dim3(HDIM/128, MTOT/128), blk>>>(attn, w_o, out, MTOT, HDIM, OW, OW);
}

// round 4
// speedup vs baseline: 1.3101x; 1.1414x over previous
#include <cuda_runtime.h>
#include <cuda_bf16.h>
#include <math.h>
#include <stdint.h>

// ---------------- problem constants ----------------
#define HDIM   2048
#define NH     16
#define QLORA  1536
#define KVLORA 512
#define DN     128
#define DR     64
#define DV     128
#define QD     192
#define BB     2
#define SS     2048
#define MTOT   (BB*SS)      // 4096
#define CKVW   (KVLORA+DR)  // 576
#define KVW    (NH*(DN+DV)) // 4096
#define QW     (NH*QD)      // 3072
#define OW     (NH*DV)      // 2048

// ---------------- scratch ----------------
__device__ float d_qa  [(size_t)MTOT*QLORA];
__device__ float d_q   [(size_t)MTOT*QW];
__device__ float d_ckv [(size_t)MTOT*CKVW];
__device__ float d_kv  [(size_t)MTOT*KVW];
__device__ float d_kpe [(size_t)MTOT*DR];
__device__ float d_attn[(size_t)MTOT*OW];

// ---------------- helpers ----------------
__device__ __forceinline__ uint32_t smem_u32(const void* p) {
    uint32_t a;
    asm("{ .reg .u64 t; cvta.to.shared.u64 t, %1; cvt.u32.u64 %0, t; }" : "=r"(a) : "l"(p));
    return a;
}

__device__ __forceinline__ void ldsm4(uint32_t r[4], uint32_t addr) {
    asm volatile("ldmatrix.sync.aligned.m8n8.x4.shared.b16 {%0,%1,%2,%3}, [%4];"
                 : "=r"(r[0]), "=r"(r[1]), "=r"(r[2]), "=r"(r[3]) : "r"(addr));
}

__device__ __forceinline__ void mma_bf16(float c[4], const uint32_t a[4],
                                         uint32_t b0, uint32_t b1) {
    asm volatile(
        "mma.sync.aligned.m16n8k16.row.col.f32.bf16.bf16.f32 "
        "{%0,%1,%2,%3}, {%4,%5,%6,%7}, {%8,%9}, {%0,%1,%2,%3};"
        : "+f"(c[0]), "+f"(c[1]), "+f"(c[2]), "+f"(c[3])
        : "r"(a[0]), "r"(a[1]), "r"(a[2]), "r"(a[3]), "r"(b0), "r"(b1));
}

// split two fp32 into packed bf16 hi / lo pairs
__device__ __forceinline__ void split2(float x, float y, uint32_t& hp, uint32_t& lp) {
    __nv_bfloat16 hx = __float2bfloat16(x), hy = __float2bfloat16(y);
    __nv_bfloat16 lx = __float2bfloat16(x - __bfloat162float(hx));
    __nv_bfloat16 ly = __float2bfloat16(y - __bfloat162float(hy));
    hp = ((uint32_t)__bfloat16_as_ushort(hy) << 16) | __bfloat16_as_ushort(hx);
    lp = ((uint32_t)__bfloat16_as_ushort(ly) << 16) | __bfloat16_as_ushort(lx);
}

// SW64-style swizzle on a [128][32] bf16 tile (64B rows): xor chunk by row bits
__device__ __forceinline__ uint32_t sw64(uint32_t o) { return o ^ ((o >> 3) & 0x30); }

// ---------------- bf16x3 mma.sync GEMM ----------------
// C[M,N] = A[M,K](lda) @ Bw[N,K]^T.  M%128==0, K%32==0, N arbitrary.
// 128x128 tile, BK=32, 256 threads, warp tile 64x32, single smem buffer +
// register prefetch. smem tiles (bf16, SW64 swizzle): Ah|Al|Bh|Bl @ 8KB each.
#define TILE_AH 0
#define TILE_AL 8192
#define TILE_BH 16384
#define TILE_BL 24576
#define GEMM_SMEM 32768

__global__ __launch_bounds__(256, 1) void gemm_mx(
    const float* __restrict__ A, const float* __restrict__ Bw, float* __restrict__ C,
    int M, int N, int K, int lda)
{
    extern __shared__ char sm[];
    const uint32_t sb = smem_u32(sm);

    const int tid = threadIdx.x;
    const int bm = blockIdx.y * 128;
    const int bn = blockIdx.x * 128;

    // loader: thread -> (row = tid>>1, k half = (tid&1)*16)
    const int lrow = tid >> 1;
    const int lk   = (tid & 1) * 16;
    const float* Ap = A + (size_t)(bm + lrow) * lda + lk;
    const float* Bp = Bw + (size_t)(bn + lrow) * K + lk;
    const bool bok = (bn + lrow) < N;

    // warp / fragment geometry
    const int w = tid >> 5, lane = tid & 31;
    const int wm = (w & 1) * 64;
    const int wn = (w >> 1) * 32;
    const int mi  = lane >> 3;
    const int aro = (lane & 7) + (mi & 1) * 8;        // A: row within m16
    const int aks = (mi >> 1) * 8;                    // A: k sub-offset
    const int bro = (lane & 7) + ((mi >> 1) & 1) * 8; // B: row within n16
    const int bks = (mi & 1) * 8;                     // B: k sub-offset

    float acc[4][4][4] = {};
    float4 pa[4], pb[4];

    auto ldG = [&](int k0) {
        #pragma unroll
        for (int j = 0; j < 4; j++) {
            pa[j] = *reinterpret_cast<const float4*>(Ap + k0 + j * 4);
            pb[j] = bok ? *reinterpret_cast<const float4*>(Bp + k0 + j * 4)
                        : make_float4(0.f, 0.f, 0.f, 0.f);
        }
    };
    auto stS = [&]() {
        #pragma unroll
        for (int j = 0; j < 4; j++) {
            const uint32_t x = (uint32_t)(lrow * 64 + (lk + j * 4) * 2);
            const uint32_t swo = sw64(x);
            uint32_t h0, l0, h1, l1;
            split2(pa[j].x, pa[j].y, h0, l0);
            split2(pa[j].z, pa[j].w, h1, l1);
            *reinterpret_cast<uint2*>(sm + TILE_AH + swo) = make_uint2(h0, h1);
            *reinterpret_cast<uint2*>(sm + TILE_AL + swo) = make_uint2(l0, l1);
            split2(pb[j].x, pb[j].y, h0, l0);
            split2(pb[j].z, pb[j].w, h1, l1);
            *reinterpret_cast<uint2*>(sm + TILE_BH + swo) = make_uint2(h0, h1);
            *reinterpret_cast<uint2*>(sm + TILE_BL + swo) = make_uint2(l0, l1);
        }
    };
    auto compute = [&]() {
        #pragma unroll
        for (int k16 = 0; k16 < 32; k16 += 16) {
            uint32_t Ah[4][4], Bh[2][4];
            #pragma unroll
            for (int f = 0; f < 4; f++) {
                const uint32_t x = (uint32_t)((wm + f * 16 + aro) * 64 + (k16 + aks) * 2);
                ldsm4(Ah[f], sb + TILE_AH + sw64(x));
            }
            #pragma unroll
            for (int g2 = 0; g2 < 2; g2++) {
                const uint32_t x = (uint32_t)((wn + g2 * 16 + bro) * 64 + (k16 + bks) * 2);
                ldsm4(Bh[g2], sb + TILE_BH + sw64(x));
            }
            // pass 1: Ah * Bh
            #pragma unroll
            for (int f = 0; f < 4; f++)
                #pragma unroll
                for (int ni = 0; ni < 4; ni++)
                    mma_bf16(acc[f][ni], Ah[f], Bh[ni >> 1][(ni & 1) * 2],
                             Bh[ni >> 1][(ni & 1) * 2 + 1]);
            // pass 2: Ah * Bl
            {
                uint32_t Bl[2][4];
                #pragma unroll
                for (int g2 = 0; g2 < 2; g2++) {
                    const uint32_t x = (uint32_t)((wn + g2 * 16 + bro) * 64 + (k16 + bks) * 2);
                    ldsm4(Bl[g2], sb + TILE_BL + sw64(x));
                }
                #pragma unroll
                for (int f = 0; f < 4; f++)
                    #pragma unroll
                    for (int ni = 0; ni < 4; ni++)
                        mma_bf16(acc[f][ni], Ah[f], Bl[ni >> 1][(ni & 1) * 2],
                                 Bl[ni >> 1][(ni & 1) * 2 + 1]);
            }
            // pass 3: Al * Bh
            {
                uint32_t Al[4][4];
                #pragma unroll
                for (int f = 0; f < 4; f++) {
                    const uint32_t x = (uint32_t)((wm + f * 16 + aro) * 64 + (k16 + aks) * 2);
                    ldsm4(Al[f], sb + TILE_AL + sw64(x));
                }
                #pragma unroll
                for (int f = 0; f < 4; f++)
                    #pragma unroll
                    for (int ni = 0; ni < 4; ni++)
                        mma_bf16(acc[f][ni], Al[f], Bh[ni >> 1][(ni & 1) * 2],
                                 Bh[ni >> 1][(ni & 1) * 2 + 1]);
            }
        }
    };

    ldG(0);
    stS();
    __syncthreads();
    int k0 = 32;
    for (;;) {
        const bool more = (k0 < K);
        if (more) ldG(k0);
        compute();
        if (!more) break;
        __syncthreads();
        stS();
        __syncthreads();
        k0 += 32;
    }

    // epilogue
    const int gq = lane >> 2, t4 = lane & 3;
    #pragma unroll
    for (int f = 0; f < 4; f++) {
        #pragma unroll
        for (int ni = 0; ni < 4; ni++) {
            const int col = bn + wn + ni * 8 + t4 * 2;
            if (col < N) {
                const int r = bm + wm + f * 16 + gq;
                *reinterpret_cast<float2*>(&C[(size_t)r * N + col]) =
                    make_float2(acc[f][ni][0], acc[f][ni][1]);
                *reinterpret_cast<float2*>(&C[(size_t)(r + 8) * N + col]) =
                    make_float2(acc[f][ni][2], acc[f][ni][3]);
            }
        }
    }
}

// ---------------- RMSNorm ----------------
__global__ void rmsnorm_kernel(float* __restrict__ x, const float* __restrict__ g,
                               int D, int stride)
{
    const int row = blockIdx.x;
    float* p = x + (size_t)row * stride;
    float ss = 0.f;
    for (int i = threadIdx.x; i < D; i += blockDim.x) { float v = p[i]; ss += v * v; }
    #pragma unroll
    for (int o = 16; o > 0; o >>= 1) ss += __shfl_xor_sync(0xffffffffu, ss, o);
    __shared__ float sred[8];
    if ((threadIdx.x & 31) == 0) sred[threadIdx.x >> 5] = ss;
    __syncthreads();
    if (threadIdx.x < 8) {
        float v = sred[threadIdx.x];
        #pragma unroll
        for (int o = 4; o > 0; o >>= 1) v += __shfl_xor_sync(0xffu, v, o);
        if (threadIdx.x == 0) sred[0] = v;
    }
    __syncthreads();
    const float inv = rsqrtf(sred[0] / (float)D + 1e-6f);
    for (int i = threadIdx.x; i < D; i += blockDim.x) p[i] = p[i] * inv * g[i];
}

// ---------------- RoPE ----------------
__global__ void rope_q_kernel(float* __restrict__ q)
{
    const int idx = blockIdx.x;
    const int row = idx / NH, h = idx % NH;
    const int t = row % SS;
    const int j = threadIdx.x;
    const double inv = exp(-log(10000.0) * (2.0 * j) / (double)DR);
    const double ang = (double)t * inv;
    const float c = (float)cos(ang), s = (float)sin(ang);
    float* p = q + (size_t)row * QW + h * QD + DN;
    const float x0 = p[j], x1 = p[j + 32];
    p[j]      = x0 * c - x1 * s;
    p[j + 32] = x1 * c + x0 * s;
}

__global__ void rope_k_kernel(const float* __restrict__ ckv, float* __restrict__ kpe)
{
    const int row = blockIdx.x;
    const int t = row % SS;
    const int j = threadIdx.x;
    const double inv = exp(-log(10000.0) * (2.0 * j) / (double)DR);
    const double ang = (double)t * inv;
    const float c = (float)cos(ang), s = (float)sin(ang);
    const float* p = ckv + (size_t)row * CKVW + KVLORA;
    const float x0 = p[j], x1 = p[j + 32];
    kpe[(size_t)row * DR + j]      = x0 * c - x1 * s;
    kpe[(size_t)row * DR + j + 32] = x1 * c + x0 * s;
}

// ---------------- causal flash attention ----------------
#define FA_BM 64
#define FA_BN 32
#define QSTR  196
#define VSTR  132
#define PSTR  33

__global__ __launch_bounds__(256) void flash_kernel(
    const float* __restrict__ q,
    const float* __restrict__ kv,
    const float* __restrict__ kpe,
    float* __restrict__ attn)
{
    extern __shared__ float smem[];
    float* Qs = smem;
    float* Ks = Qs + FA_BM * QSTR;
    float* Vs = Ks + FA_BN * QSTR;
    float* Ps = Vs + FA_BN * VSTR;

    const int qb  = blockIdx.x;
    const int h   = blockIdx.y;
    const int b   = blockIdx.z;
    const int tid = threadIdx.x;
    const int tx  = tid & 7;
    const int ty  = tid >> 3;
    const int r0  = ty * 2, r1 = ty * 2 + 1;

    const int row0 = b * SS + qb * FA_BM;
    const float scale = rsqrtf((float)QD);

    for (int i = tid; i < FA_BM * (QD / 4); i += 256) {
        const int r = i / (QD / 4);
        const int d4 = (i % (QD / 4)) * 4;
        float4 v = *reinterpret_cast<const float4*>(&q[(size_t)(row0 + r) * QW + h * QD + d4]);
        float* dst = &Qs[r * QSTR + d4];
        dst[0] = v.x * scale; dst[1] = v.y * scale; dst[2] = v.z * scale; dst[3] = v.w * scale;
    }

    float m0 = -INFINITY, m1 = -INFINITY, l0 = 0.f, l1 = 0.f;
    float o0[16] = {}, o1[16] = {};
    const int n_tiles = 2 * (qb + 1);
    __syncthreads();

    for (int kt = 0; kt < n_tiles; kt++) {
        const int krow0 = b * SS + kt * FA_BN;
        for (int i = tid; i < FA_BN * (QD / 4); i += 256) {
            const int c = i / (QD / 4);
            const int d4 = (i % (QD / 4)) * 4;
            float4 v;
            if (d4 < DN) v = *reinterpret_cast<const float4*>(&kv[(size_t)(krow0 + c) * KVW + h * (DN + DV) + d4]);
            else         v = *reinterpret_cast<const float4*>(&kpe[(size_t)(krow0 + c) * DR + (d4 - DN)]);
            float* dst = &Ks[c * QSTR + d4];
            dst[0] = v.x; dst[1] = v.y; dst[2] = v.z; dst[3] = v.w;
        }
        for (int i = tid; i < FA_BN * (DV / 4); i += 256) {
            const int c = i / (DV / 4);
            const int d4 = (i % (DV / 4)) * 4;
            float4 v = *reinterpret_cast<const float4*>(&kv[(size_t)(krow0 + c) * KVW + h * (DN + DV) + DN + d4]);
            float* dst = &Vs[c * VSTR + d4];
            dst[0] = v.x; dst[1] = v.y; dst[2] = v.z; dst[3] = v.w;
        }
        __syncthreads();

        float sc[2][4] = {};
        const float* q0p = &Qs[r0 * QSTR];
        const float* q1p = &Qs[r1 * QSTR];
        #pragma unroll 8
        for (int d = 0; d < QD; d += 4) {
            float4 a0 = *reinterpret_cast<const float4*>(q0p + d);
            float4 a1 = *reinterpret_cast<const float4*>(q1p + d);
            #pragma unroll
            for (int j = 0; j < 4; j++) {
                float4 kk = *reinterpret_cast<const float4*>(&Ks[(tx * 4 + j) * QSTR + d]);
                sc[0][j] += a0.x * kk.x + a0.y * kk.y + a0.z * kk.z + a0.w * kk.w;
                sc[1][j] += a1.x * kk.x + a1.y * kk.y + a1.z * kk.z + a1.w * kk.w;
            }
        }

        if (kt >= 2 * qb) {
            #pragma unroll
            for (int j = 0; j < 4; j++) {
                const int kpos = kt * FA_BN + tx * 4 + j;
                if (kpos > qb * FA_BM + r0) sc[0][j] = -INFINITY;
                if (kpos > qb * FA_BM + r1) sc[1][j] = -INFINITY;
            }
        }

        float tm0 = fmaxf(fmaxf(sc[0][0], sc[0][1]), fmaxf(sc[0][2], sc[0][3]));
        float tm1 = fmaxf(fmaxf(sc[1][0], sc[1][1]), fmaxf(sc[1][2], sc[1][3]));
        #pragma unroll
        for (int o = 1; o < 8; o <<= 1) {
            tm0 = fmaxf(tm0, __shfl_xor_sync(0xffffffffu, tm0, o));
            tm1 = fmaxf(tm1, __shfl_xor_sync(0xffffffffu, tm1, o));
        }
        const float mn0 = fmaxf(m0, tm0), mn1 = fmaxf(m1, tm1);
        const float al0 = expf(m0 - mn0), al1 = expf(m1 - mn1);
        float p0[4], p1[4], ls0 = 0.f, ls1 = 0.f;
        #pragma unroll
        for (int j = 0; j < 4; j++) {
            p0[j] = expf(sc[0][j] - mn0); ls0 += p0[j];
            p1[j] = expf(sc[1][j] - mn1); ls1 += p1[j];
        }
        #pragma unroll
        for (int o = 1; o < 8; o <<= 1) {
            ls0 += __shfl_xor_sync(0xffffffffu, ls0, o);
            ls1 += __shfl_xor_sync(0xffffffffu, ls1, o);
        }
        l0 = l0 * al0 + ls0; l1 = l1 * al1 + ls1;
        m0 = mn0; m1 = mn1;
        #pragma unroll
        for (int c = 0; c < 16; c++) { o0[c] *= al0; o1[c] *= al1; }

        #pragma unroll
        for (int j = 0; j < 4; j++) {
            Ps[r0 * PSTR + tx * 4 + j] = p0[j];
            Ps[r1 * PSTR + tx * 4 + j] = p1[j];
        }
        __syncthreads();

        #pragma unroll 8
        for (int kk = 0; kk < FA_BN; kk++) {
            const float pa = Ps[r0 * PSTR + kk];
            const float pb = Ps[r1 * PSTR + kk];
            const float* vp = &Vs[kk * VSTR];
            #pragma unroll
            for (int cc = 0; cc < 4; cc++) {
                float4 v = *reinterpret_cast<const float4*>(vp + cc * 32 + tx * 4);
                o0[cc*4+0] += pa * v.x; o0[cc*4+1] += pa * v.y;
                o0[cc*4+2] += pa * v.z; o0[cc*4+3] += pa * v.w;
                o1[cc*4+0] += pb * v.x; o1[cc*4+1] += pb * v.y;
                o1[cc*4+2] += pb * v.z; o1[cc*4+3] += pb * v.w;
            }
        }
        __syncthreads();
    }

    const float il0 = 1.f / l0, il1 = 1.f / l1;
    #pragma unroll
    for (int cc = 0; cc < 4; cc++) {
        const int col = h * DV + cc * 32 + tx * 4;
        *reinterpret_cast<float4*>(&attn[(size_t)(row0 + r0) * OW + col]) =
            make_float4(o0[cc*4]*il0, o0[cc*4+1]*il0, o0[cc*4+2]*il0, o0[cc*4+3]*il0);
        *reinterpret_cast<float4*>(&attn[(size_t)(row0 + r1) * OW + col]) =
            make_float4(o1[cc*4]*il1, o1[cc*4+1]*il1, o1[cc*4+2]*il1, o1[cc*4+3]*il1);
    }
}

// ---------------- launch ----------------
extern "C" void kernel_launch(void* const* d_in, const int* in_sizes, int n_in,
                              void* d_out, int out_size)
{
    (void)in_sizes; (void)n_in; (void)out_size;
    const float* hidden = (const float*)d_in[0];
    const float* w_qa   = (const float*)d_in[1];
    const float* g_qa   = (const float*)d_in[2];
    const float* w_qb   = (const float*)d_in[3];
    const float* w_kva  = (const float*)d_in[4];
    const float* g_kva  = (const float*)d_in[5];
    const float* w_kvb  = (const float*)d_in[6];
    const float* w_o    = (const float*)d_in[7];
    float* out = (float*)d_out;

    float *qa, *q, *ckv, *kv, *kpe, *attn;
    cudaGetSymbolAddress((void**)&qa,   d_qa);
    cudaGetSymbolAddress((void**)&q,    d_q);
    cudaGetSymbolAddress((void**)&ckv,  d_ckv);
    cudaGetSymbolAddress((void**)&kv,   d_kv);
    cudaGetSymbolAddress((void**)&kpe,  d_kpe);
    cudaGetSymbolAddress((void**)&attn, d_attn);

    const dim3 blk(256);
    // q_a = hidden @ w_qa^T          [4096,1536]
    gemm_mx<<<dim3(QLORA/128, MTOT/128), blk, GEMM_SMEM>>>(hidden, w_qa, qa, MTOT, QLORA, HDIM, HDIM);
    // ckv = hidden @ w_kva^T         [4096,576]
    gemm_mx<<<dim3((CKVW+127)/128, MTOT/128), blk, GEMM_SMEM>>>(hidden, w_kva, ckv, MTOT, CKVW, HDIM, HDIM);
    // rmsnorms
    rmsnorm_kernel<<<MTOT, 256>>>(qa, g_qa, QLORA, QLORA);
    rmsnorm_kernel<<<MTOT, 256>>>(ckv, g_kva, KVLORA, CKVW);
    // q = rms(q_a) @ w_qb^T          [4096,3072]
    gemm_mx<<<dim3(QW/128, MTOT/128), blk, GEMM_SMEM>>>(qa, w_qb, q, MTOT, QW, QLORA, QLORA);
    // kv = rms(ckv) @ w_kvb^T        [4096,4096]
    gemm_mx<<<dim3(KVW/128, MTOT/128), blk, GEMM_SMEM>>>(ckv, w_kvb, kv, MTOT, KVW, KVLORA, CKVW);
    // rope
    rope_q_kernel<<<MTOT * NH, 32>>>(q);
    rope_k_kernel<<<MTOT, 32>>>(ckv, kpe);
    // flash attention
    const size_t shmem = (size_t)(FA_BM*QSTR + FA_BN*QSTR + FA_BN*VSTR + FA_BM*PSTR) * sizeof(float);
    cudaFuncSetAttribute(flash_kernel, cudaFuncAttributeMaxDynamicSharedMemorySize, (int)shmem);
    flash_kernel<<<dim3(SS/FA_BM, NH, BB), 256, shmem>>>(q, kv, kpe, attn);
    // out = attn @ w_o^T             [4096,2048]
    gemm_mx<<<dim3(HDIM/128, MTOT/128), blk, GEMM_SMEM>>>(attn, w_o, out, MTOT, HDIM, OW, OW);
}

// round 5
// speedup vs baseline: 4.0997x; 3.1294x over previous
#include <cuda_runtime.h>
#include <cuda_bf16.h>
#include <math.h>
#include <stdint.h>

// ---------------- problem constants ----------------
#define HDIM   2048
#define NH     16
#define QLORA  1536
#define KVLORA 512
#define DN     128
#define DR     64
#define DV     128
#define QD     192
#define BB     2
#define SS     2048
#define MTOT   (BB*SS)      // 4096
#define CKVW   (KVLORA+DR)  // 576
#define KVW    (NH*(DN+DV)) // 4096
#define QW     (NH*QD)      // 3072
#define OW     (NH*DV)      // 2048

// ---------------- fp32 scratch ----------------
__device__ float d_qa  [(size_t)MTOT*QLORA];
__device__ float d_q   [(size_t)MTOT*QW];
__device__ float d_ckv [(size_t)MTOT*CKVW];
__device__ float d_kv  [(size_t)MTOT*KVW];
__device__ float d_kpe [(size_t)MTOT*DR];
__device__ float d_attn[(size_t)MTOT*OW];

// ---------------- bf16 hi/lo scratch ----------------
__device__ __nv_bfloat16 d_hidh [(size_t)MTOT*HDIM],   d_hidl [(size_t)MTOT*HDIM];
__device__ __nv_bfloat16 d_wqah [(size_t)QLORA*HDIM],  d_wqal [(size_t)QLORA*HDIM];
__device__ __nv_bfloat16 d_wkvah[(size_t)CKVW*HDIM],   d_wkval[(size_t)CKVW*HDIM];
__device__ __nv_bfloat16 d_wqbh [(size_t)QW*QLORA],    d_wqbl [(size_t)QW*QLORA];
__device__ __nv_bfloat16 d_wkvbh[(size_t)KVW*KVLORA],  d_wkvbl[(size_t)KVW*KVLORA];
__device__ __nv_bfloat16 d_woh  [(size_t)HDIM*OW],     d_wol  [(size_t)HDIM*OW];
__device__ __nv_bfloat16 d_qanh [(size_t)MTOT*QLORA],  d_qanl [(size_t)MTOT*QLORA];
__device__ __nv_bfloat16 d_ckvnh[(size_t)MTOT*KVLORA], d_ckvnl[(size_t)MTOT*KVLORA];
__device__ __nv_bfloat16 d_atth [(size_t)MTOT*OW],     d_attl [(size_t)MTOT*OW];

// ---------------- helpers ----------------
__device__ __forceinline__ uint32_t smem_u32(const void* p) {
    uint32_t a;
    asm("{ .reg .u64 t; cvta.to.shared.u64 t, %1; cvt.u32.u64 %0, t; }" : "=r"(a) : "l"(p));
    return a;
}

__device__ __forceinline__ void ldsm4(uint32_t r[4], uint32_t addr) {
    asm volatile("ldmatrix.sync.aligned.m8n8.x4.shared.b16 {%0,%1,%2,%3}, [%4];"
                 : "=r"(r[0]), "=r"(r[1]), "=r"(r[2]), "=r"(r[3]) : "r"(addr));
}

__device__ __forceinline__ void mma_bf16(float c[4], const uint32_t a[4],
                                         uint32_t b0, uint32_t b1) {
    asm volatile(
        "mma.sync.aligned.m16n8k16.row.col.f32.bf16.bf16.f32 "
        "{%0,%1,%2,%3}, {%4,%5,%6,%7}, {%8,%9}, {%0,%1,%2,%3};"
        : "+f"(c[0]), "+f"(c[1]), "+f"(c[2]), "+f"(c[3])
        : "r"(a[0]), "r"(a[1]), "r"(a[2]), "r"(a[3]), "r"(b0), "r"(b1));
}

__device__ __forceinline__ void split2(float x, float y, uint32_t& hp, uint32_t& lp) {
    __nv_bfloat16 hx = __float2bfloat16(x), hy = __float2bfloat16(y);
    __nv_bfloat16 lx = __float2bfloat16(x - __bfloat162float(hx));
    __nv_bfloat16 ly = __float2bfloat16(y - __bfloat162float(hy));
    hp = ((uint32_t)__bfloat16_as_ushort(hy) << 16) | __bfloat16_as_ushort(hx);
    lp = ((uint32_t)__bfloat16_as_ushort(ly) << 16) | __bfloat16_as_ushort(lx);
}

__device__ __forceinline__ uint32_t sw64(uint32_t o) { return o ^ ((o >> 3) & 0x30); }

__device__ __forceinline__ void cpa16(uint32_t dst, const void* src, bool valid) {
    int sz = valid ? 16 : 0;
    asm volatile("cp.async.cg.shared.global [%0], [%1], 16, %2;"
                 :: "r"(dst), "l"(src), "r"(sz));
}
#define CPA_COMMIT() asm volatile("cp.async.commit_group;" ::: "memory")
#define CPA_WAIT1()  asm volatile("cp.async.wait_group 1;" ::: "memory")
#define CPA_WAIT0()  asm volatile("cp.async.wait_group 0;" ::: "memory")

// ---------------- fp32 -> bf16 hi/lo split ----------------
__global__ void split_kernel(const float* __restrict__ src, int lda, int cols,
                             __nv_bfloat16* __restrict__ h, __nv_bfloat16* __restrict__ l)
{
    const int row = blockIdx.x;
    const float* p = src + (size_t)row * lda;
    uint32_t* hp = reinterpret_cast<uint32_t*>(h + (size_t)row * cols);
    uint32_t* lp = reinterpret_cast<uint32_t*>(l + (size_t)row * cols);
    for (int i = threadIdx.x * 4; i < cols; i += blockDim.x * 4) {
        float4 v = *reinterpret_cast<const float4*>(p + i);
        uint32_t h0, l0, h1, l1;
        split2(v.x, v.y, h0, l0);
        split2(v.z, v.w, h1, l1);
        hp[i/2] = h0; hp[i/2+1] = h1;
        lp[i/2] = l0; lp[i/2+1] = l1;
    }
}

// ---------------- bf16x3 GEMM with cp.async double buffering ----------------
// C[M,N] = A[M,K] @ Bw[N,K]^T, inputs pre-split bf16 hi/lo, row stride K.
// 128x128 tile, BK=32, 256 threads, warp tile 64x32.
// smem per stage: Ah|Al|Bh|Bl @ 8KB = 32KB; 2 stages = 64KB.
#define GS_AH 0
#define GS_AL 8192
#define GS_BH 16384
#define GS_BL 24576
#define GS_STAGE 32768
#define GEMM_SMEM (2*GS_STAGE)

__global__ __launch_bounds__(256) void gemm_bf(
    const __nv_bfloat16* __restrict__ Ah, const __nv_bfloat16* __restrict__ Al,
    const __nv_bfloat16* __restrict__ Bh, const __nv_bfloat16* __restrict__ Bl,
    float* __restrict__ C, int M, int N, int K)
{
    extern __shared__ char sm[];
    const uint32_t sb = smem_u32(sm);

    const int tid = threadIdx.x;
    const int bm = blockIdx.y * 128;
    const int bn = blockIdx.x * 128;
    const int NC = K >> 5;

    // loader: idx = i*256+tid (i=0,1): row = idx>>2, c16 = idx&3  (4x16B per 64B row)
    const int lrow = tid >> 1;           // base rows: covers 0..127 over i via idx
    (void)lrow;

    const int w = tid >> 5, lane = tid & 31;
    const int wm = (w & 1) * 64;
    const int wn = (w >> 1) * 32;
    const int mi  = lane >> 3;
    const int aro = (lane & 7) + (mi & 1) * 8;
    const int aks = (mi >> 1) * 8;
    const int bro = (lane & 7) + ((mi >> 1) & 1) * 8;
    const int bks = (mi & 1) * 8;

    float acc[4][4][4] = {};

    auto issue = [&](int c) {
        const int k0 = c << 5;
        const uint32_t st = sb + (c & 1) * GS_STAGE;
        #pragma unroll
        for (int i = 0; i < 2; i++) {
            const int idx = i * 256 + tid;
            const int row = idx >> 2;
            const int c16 = idx & 3;
            const uint32_t dsto = sw64((uint32_t)(row * 64 + c16 * 16));
            const size_t go = (size_t)(bm + row) * K + k0 + c16 * 8;
            cpa16(st + GS_AH + dsto, Ah + go, true);
            cpa16(st + GS_AL + dsto, Al + go, true);
            const bool bok = (bn + row) < N;
            const size_t gb = (size_t)(bn + row) * K + k0 + c16 * 8;
            cpa16(st + GS_BH + dsto, Bh + gb, bok);
            cpa16(st + GS_BL + dsto, Bl + gb, bok);
        }
        CPA_COMMIT();
    };

    auto compute = [&](int c) {
        const uint32_t st = sb + (c & 1) * GS_STAGE;
        #pragma unroll
        for (int k16 = 0; k16 < 32; k16 += 16) {
            uint32_t A_h[4][4], B_h[2][4];
            #pragma unroll
            for (int f = 0; f < 4; f++) {
                const uint32_t x = (uint32_t)((wm + f * 16 + aro) * 64 + (k16 + aks) * 2);
                ldsm4(A_h[f], st + GS_AH + sw64(x));
            }
            #pragma unroll
            for (int g2 = 0; g2 < 2; g2++) {
                const uint32_t x = (uint32_t)((wn + g2 * 16 + bro) * 64 + (k16 + bks) * 2);
                ldsm4(B_h[g2], st + GS_BH + sw64(x));
            }
            #pragma unroll
            for (int f = 0; f < 4; f++)
                #pragma unroll
                for (int ni = 0; ni < 4; ni++)
                    mma_bf16(acc[f][ni], A_h[f], B_h[ni >> 1][(ni & 1) * 2],
                             B_h[ni >> 1][(ni & 1) * 2 + 1]);
            {
                uint32_t B_l[2][4];
                #pragma unroll
                for (int g2 = 0; g2 < 2; g2++) {
                    const uint32_t x = (uint32_t)((wn + g2 * 16 + bro) * 64 + (k16 + bks) * 2);
                    ldsm4(B_l[g2], st + GS_BL + sw64(x));
                }
                #pragma unroll
                for (int f = 0; f < 4; f++)
                    #pragma unroll
                    for (int ni = 0; ni < 4; ni++)
                        mma_bf16(acc[f][ni], A_h[f], B_l[ni >> 1][(ni & 1) * 2],
                                 B_l[ni >> 1][(ni & 1) * 2 + 1]);
            }
            {
                uint32_t A_l[4][4];
                #pragma unroll
                for (int f = 0; f < 4; f++) {
                    const uint32_t x = (uint32_t)((wm + f * 16 + aro) * 64 + (k16 + aks) * 2);
                    ldsm4(A_l[f], st + GS_AL + sw64(x));
                }
                #pragma unroll
                for (int f = 0; f < 4; f++)
                    #pragma unroll
                    for (int ni = 0; ni < 4; ni++)
                        mma_bf16(acc[f][ni], A_l[f], B_h[ni >> 1][(ni & 1) * 2],
                                 B_h[ni >> 1][(ni & 1) * 2 + 1]);
            }
        }
    };

    issue(0);
    for (int c = 0; c < NC; c++) {
        if (c + 1 < NC) { issue(c + 1); CPA_WAIT1(); } else { CPA_WAIT0(); }
        __syncthreads();
        compute(c);
        __syncthreads();
    }

    const int gq = lane >> 2, t4 = lane & 3;
    #pragma unroll
    for (int f = 0; f < 4; f++) {
        #pragma unroll
        for (int ni = 0; ni < 4; ni++) {
            const int col = bn + wn + ni * 8 + t4 * 2;
            if (col < N) {
                const int r = bm + wm + f * 16 + gq;
                *reinterpret_cast<float2*>(&C[(size_t)r * N + col]) =
                    make_float2(acc[f][ni][0], acc[f][ni][1]);
                *reinterpret_cast<float2*>(&C[(size_t)(r + 8) * N + col]) =
                    make_float2(acc[f][ni][2], acc[f][ni][3]);
            }
        }
    }
}

// ---------------- RMSNorm ----------------
__global__ void rmsnorm_kernel(float* __restrict__ x, const float* __restrict__ g,
                               int D, int stride)
{
    const int row = blockIdx.x;
    float* p = x + (size_t)row * stride;
    float ss = 0.f;
    for (int i = threadIdx.x; i < D; i += blockDim.x) { float v = p[i]; ss += v * v; }
    #pragma unroll
    for (int o = 16; o > 0; o >>= 1) ss += __shfl_xor_sync(0xffffffffu, ss, o);
    __shared__ float sred[8];
    if ((threadIdx.x & 31) == 0) sred[threadIdx.x >> 5] = ss;
    __syncthreads();
    if (threadIdx.x < 8) {
        float v = sred[threadIdx.x];
        #pragma unroll
        for (int o = 4; o > 0; o >>= 1) v += __shfl_xor_sync(0xffu, v, o);
        if (threadIdx.x == 0) sred[0] = v;
    }
    __syncthreads();
    const float inv = rsqrtf(sred[0] / (float)D + 1e-6f);
    for (int i = threadIdx.x; i < D; i += blockDim.x) p[i] = p[i] * inv * g[i];
}

// ---------------- RoPE ----------------
__global__ void rope_q_kernel(float* __restrict__ q)
{
    const int idx = blockIdx.x;
    const int row = idx / NH, h = idx % NH;
    const int t = row % SS;
    const int j = threadIdx.x;
    const double inv = exp(-log(10000.0) * (2.0 * j) / (double)DR);
    const double ang = (double)t * inv;
    const float c = (float)cos(ang), s = (float)sin(ang);
    float* p = q + (size_t)row * QW + h * QD + DN;
    const float x0 = p[j], x1 = p[j + 32];
    p[j]      = x0 * c - x1 * s;
    p[j + 32] = x1 * c + x0 * s;
}

__global__ void rope_k_kernel(const float* __restrict__ ckv, float* __restrict__ kpe)
{
    const int row = blockIdx.x;
    const int t = row % SS;
    const int j = threadIdx.x;
    const double inv = exp(-log(10000.0) * (2.0 * j) / (double)DR);
    const double ang = (double)t * inv;
    const float c = (float)cos(ang), s = (float)sin(ang);
    const float* p = ckv + (size_t)row * CKVW + KVLORA;
    const float x0 = p[j], x1 = p[j + 32];
    kpe[(size_t)row * DR + j]      = x0 * c - x1 * s;
    kpe[(size_t)row * DR + j + 32] = x1 * c + x0 * s;
}

// ---------------- tensor-core causal flash attention ----------------
// BM=128 q-rows per block, BN=64 keys per tile, 8 warps (warp w owns rows w*16..+16).
// Q/K hi/lo in smem subtiles ([rows][32] bf16, 64B rows, sw64); V^T likewise.
// 3 bf16 passes for both QK^T and PV. P built in registers from score fragments.
#define FQH 0            // 6 subtiles x 8192 = 49152  ([128][32])
#define FQL 49152
#define FKH 98304        // 6 subtiles x 4096 = 24576  ([64][32])
#define FKL 122880
#define FVH 147456       // 2 subtiles x 8192 = 16384  ([128dv][32key])
#define FVL 163840
#define FLASH_SMEM 180224

__global__ __launch_bounds__(256) void flash_tc(
    const float* __restrict__ q,     // [MTOT][QW] (roped)
    const float* __restrict__ kv,    // [MTOT][KVW]
    const float* __restrict__ kpe,   // [MTOT][DR] (roped)
    float* __restrict__ attn)        // [MTOT][OW]
{
    extern __shared__ char sm[];
    const uint32_t sb = smem_u32(sm);

    const int qb = blockIdx.x, h = blockIdx.y, b = blockIdx.z;
    const int tid = threadIdx.x;
    const int w = tid >> 5, lane = tid & 31;
    const int g = lane >> 2, t4 = lane & 3;
    const int mi  = lane >> 3;
    const int aro = (lane & 7) + (mi & 1) * 8;
    const int aks = (mi >> 1) * 8;
    const int bro = (lane & 7) + ((mi >> 1) & 1) * 8;
    const int bks = (mi & 1) * 8;

    const int q0 = qb * 128;
    const int row0 = b * SS + q0;
    const float scale = rsqrtf((float)QD);

    // load Q (scaled) -> hi/lo subtiles
    #pragma unroll
    for (int t = 0; t < 24; t++) {
        const int idx = t * 256 + tid;
        const int r = idx / 48;
        const int c4 = (idx % 48) * 4;
        float4 v = *reinterpret_cast<const float4*>(&q[(size_t)(row0 + r) * QW + h * QD + c4]);
        v.x *= scale; v.y *= scale; v.z *= scale; v.w *= scale;
        const uint32_t off = (uint32_t)(c4 >> 5) * 8192 + sw64((uint32_t)(r * 64 + (c4 & 31) * 2));
        uint32_t h0, l0, h1, l1;
        split2(v.x, v.y, h0, l0);
        split2(v.z, v.w, h1, l1);
        *reinterpret_cast<uint2*>(sm + FQH + off) = make_uint2(h0, h1);
        *reinterpret_cast<uint2*>(sm + FQL + off) = make_uint2(l0, l1);
    }
    __syncthreads();

    float of[16][4] = {};
    float m0 = -INFINITY, m1 = -INFINITY, l0 = 0.f, l1 = 0.f;
    const int n_tiles = 2 * qb + 2;

    for (int kt = 0; kt < n_tiles; kt++) {
        const int k0 = kt * 64;
        const int krow = b * SS + k0;

        // load K (nope + roped pe) -> hi/lo subtiles [64][32]
        #pragma unroll
        for (int t = 0; t < 12; t++) {
            const int idx = t * 256 + tid;
            const int r = idx / 48;
            const int c4 = (idx % 48) * 4;
            float4 v;
            if (c4 < DN) v = *reinterpret_cast<const float4*>(&kv[(size_t)(krow + r) * KVW + h * (DN + DV) + c4]);
            else         v = *reinterpret_cast<const float4*>(&kpe[(size_t)(krow + r) * DR + (c4 - DN)]);
            const uint32_t off = (uint32_t)(c4 >> 5) * 4096 + sw64((uint32_t)(r * 64 + (c4 & 31) * 2));
            uint32_t h0, l0p, h1, l1p;
            split2(v.x, v.y, h0, l0p);
            split2(v.z, v.w, h1, l1p);
            *reinterpret_cast<uint2*>(sm + FKH + off) = make_uint2(h0, h1);
            *reinterpret_cast<uint2*>(sm + FKL + off) = make_uint2(l0p, l1p);
        }
        // load V transposed -> [dv][key] hi/lo subtiles [128][32]
        #pragma unroll
        for (int t = 0; t < 8; t++) {
            const int idx = t * 256 + tid;
            const int key = idx & 63;
            const int dv = (idx >> 6) * 4;
            float4 v = *reinterpret_cast<const float4*>(&kv[(size_t)(krow + key) * KVW + h * (DN + DV) + DN + dv]);
            const uint32_t subt = (uint32_t)(key >> 5) * 8192;
            const int kl = (key & 31) * 2;
            float vv[4] = {v.x, v.y, v.z, v.w};
            #pragma unroll
            for (int i = 0; i < 4; i++) {
                __nv_bfloat16 hb = __float2bfloat16(vv[i]);
                __nv_bfloat16 lb = __float2bfloat16(vv[i] - __bfloat162float(hb));
                const uint32_t o = subt + sw64((uint32_t)((dv + i) * 64 + kl));
                *reinterpret_cast<__nv_bfloat16*>(sm + FVH + o) = hb;
                *reinterpret_cast<__nv_bfloat16*>(sm + FVL + o) = lb;
            }
        }
        __syncthreads();

        // S = Q @ K^T  (3 passes)
        float sf[8][4] = {};
        const uint32_t qax = (uint32_t)((w * 16 + aro) * 64 + aks * 2);
        #pragma unroll
        for (int s = 0; s < 12; s++) {
            uint32_t ah[4], al[4];
            const uint32_t qoff = (uint32_t)(s >> 1) * 8192 + sw64(qax + (s & 1) * 32);
            ldsm4(ah, sb + FQH + qoff);
            ldsm4(al, sb + FQL + qoff);
            #pragma unroll
            for (int g2 = 0; g2 < 4; g2++) {
                const uint32_t kx = (uint32_t)((g2 * 16 + bro) * 64 + bks * 2);
                const uint32_t koff = (uint32_t)(s >> 1) * 4096 + sw64(kx + (s & 1) * 32);
                uint32_t bh[4], bl[4];
                ldsm4(bh, sb + FKH + koff);
                ldsm4(bl, sb + FKL + koff);
                #pragma unroll
                for (int sub = 0; sub < 2; sub++) {
                    const int ni = g2 * 2 + sub;
                    mma_bf16(sf[ni], ah, bh[sub * 2], bh[sub * 2 + 1]);
                    mma_bf16(sf[ni], ah, bl[sub * 2], bl[sub * 2 + 1]);
                    mma_bf16(sf[ni], al, bh[sub * 2], bh[sub * 2 + 1]);
                }
            }
        }

        // causal mask
        if (kt >= 2 * qb) {
            const int qr0 = q0 + w * 16 + g;
            const int qr8 = qr0 + 8;
            #pragma unroll
            for (int ni = 0; ni < 8; ni++) {
                const int kp0 = k0 + ni * 8 + 2 * t4;
                const int kp1 = kp0 + 1;
                if (kp0 > qr0) sf[ni][0] = -1e30f;
                if (kp1 > qr0) sf[ni][1] = -1e30f;
                if (kp0 > qr8) sf[ni][2] = -1e30f;
                if (kp1 > qr8) sf[ni][3] = -1e30f;
            }
        }

        // online softmax (rows g and g+8, per-warp local)
        float tm0 = -INFINITY, tm1 = -INFINITY;
        #pragma unroll
        for (int ni = 0; ni < 8; ni++) {
            tm0 = fmaxf(tm0, fmaxf(sf[ni][0], sf[ni][1]));
            tm1 = fmaxf(tm1, fmaxf(sf[ni][2], sf[ni][3]));
        }
        #pragma unroll
        for (int o = 1; o < 4; o <<= 1) {
            tm0 = fmaxf(tm0, __shfl_xor_sync(0xffffffffu, tm0, o));
            tm1 = fmaxf(tm1, __shfl_xor_sync(0xffffffffu, tm1, o));
        }
        const float mn0 = fmaxf(m0, tm0), mn1 = fmaxf(m1, tm1);
        const float a0 = __expf(m0 - mn0), a1 = __expf(m1 - mn1);
        float ls0 = 0.f, ls1 = 0.f;
        #pragma unroll
        for (int ni = 0; ni < 8; ni++) {
            sf[ni][0] = __expf(sf[ni][0] - mn0); ls0 += sf[ni][0];
            sf[ni][1] = __expf(sf[ni][1] - mn0); ls0 += sf[ni][1];
            sf[ni][2] = __expf(sf[ni][2] - mn1); ls1 += sf[ni][2];
            sf[ni][3] = __expf(sf[ni][3] - mn1); ls1 += sf[ni][3];
        }
        #pragma unroll
        for (int o = 1; o < 4; o <<= 1) {
            ls0 += __shfl_xor_sync(0xffffffffu, ls0, o);
            ls1 += __shfl_xor_sync(0xffffffffu, ls1, o);
        }
        l0 = l0 * a0 + ls0; l1 = l1 * a1 + ls1;
        m0 = mn0; m1 = mn1;
        #pragma unroll
        for (int ni = 0; ni < 16; ni++) {
            of[ni][0] *= a0; of[ni][1] *= a0;
            of[ni][2] *= a1; of[ni][3] *= a1;
        }

        // O += P @ V   (P fragments from registers, 3 passes)
        #pragma unroll
        for (int ks = 0; ks < 4; ks++) {
            uint32_t ph[4], pl[4];
            split2(sf[2*ks][0],   sf[2*ks][1],   ph[0], pl[0]);
            split2(sf[2*ks][2],   sf[2*ks][3],   ph[1], pl[1]);
            split2(sf[2*ks+1][0], sf[2*ks+1][1], ph[2], pl[2]);
            split2(sf[2*ks+1][2], sf[2*ks+1][3], ph[3], pl[3]);
            #pragma unroll
            for (int g2 = 0; g2 < 8; g2++) {
                const uint32_t vx = (uint32_t)((g2 * 16 + bro) * 64 + bks * 2);
                const uint32_t voff = (uint32_t)(ks >> 1) * 8192 + sw64(vx + (ks & 1) * 32);
                uint32_t vh[4], vl[4];
                ldsm4(vh, sb + FVH + voff);
                ldsm4(vl, sb + FVL + voff);
                #pragma unroll
                for (int sub = 0; sub < 2; sub++) {
                    const int ni = g2 * 2 + sub;
                    mma_bf16(of[ni], ph, vh[sub * 2], vh[sub * 2 + 1]);
                    mma_bf16(of[ni], ph, vl[sub * 2], vl[sub * 2 + 1]);
                    mma_bf16(of[ni], pl, vh[sub * 2], vh[sub * 2 + 1]);
                }
            }
        }
        __syncthreads();
    }

    const float il0 = 1.f / l0, il1 = 1.f / l1;
    const int rg = row0 + w * 16 + g;
    #pragma unroll
    for (int ni = 0; ni < 16; ni++) {
        const int col = h * DV + ni * 8 + t4 * 2;
        *reinterpret_cast<float2*>(&attn[(size_t)rg * OW + col]) =
            make_float2(of[ni][0] * il0, of[ni][1] * il0);
        *reinterpret_cast<float2*>(&attn[(size_t)(rg + 8) * OW + col]) =
            make_float2(of[ni][2] * il1, of[ni][3] * il1);
    }
}

// ---------------- launch ----------------
extern "C" void kernel_launch(void* const* d_in, const int* in_sizes, int n_in,
                              void* d_out, int out_size)
{
    (void)in_sizes; (void)n_in; (void)out_size;
    const float* hidden = (const float*)d_in[0];
    const float* w_qa   = (const float*)d_in[1];
    const float* g_qa   = (const float*)d_in[2];
    const float* w_qb   = (const float*)d_in[3];
    const float* w_kva  = (const float*)d_in[4];
    const float* g_kva  = (const float*)d_in[5];
    const float* w_kvb  = (const float*)d_in[6];
    const float* w_o    = (const float*)d_in[7];
    float* out = (float*)d_out;

    float *qa, *q, *ckv, *kv, *kpe, *attn;
    cudaGetSymbolAddress((void**)&qa,   d_qa);
    cudaGetSymbolAddress((void**)&q,    d_q);
    cudaGetSymbolAddress((void**)&ckv,  d_ckv);
    cudaGetSymbolAddress((void**)&kv,   d_kv);
    cudaGetSymbolAddress((void**)&kpe,  d_kpe);
    cudaGetSymbolAddress((void**)&attn, d_attn);

    __nv_bfloat16 *hidh,*hidl,*wqah,*wqal,*wkvah,*wkval,*wqbh,*wqbl,*wkvbh,*wkvbl,*woh,*wol;
    __nv_bfloat16 *qanh,*qanl,*ckvnh,*ckvnl,*atth,*attl;
    cudaGetSymbolAddress((void**)&hidh, d_hidh);   cudaGetSymbolAddress((void**)&hidl, d_hidl);
    cudaGetSymbolAddress((void**)&wqah, d_wqah);   cudaGetSymbolAddress((void**)&wqal, d_wqal);
    cudaGetSymbolAddress((void**)&wkvah, d_wkvah); cudaGetSymbolAddress((void**)&wkval, d_wkval);
    cudaGetSymbolAddress((void**)&wqbh, d_wqbh);   cudaGetSymbolAddress((void**)&wqbl, d_wqbl);
    cudaGetSymbolAddress((void**)&wkvbh, d_wkvbh); cudaGetSymbolAddress((void**)&wkvbl, d_wkvbl);
    cudaGetSymbolAddress((void**)&woh, d_woh);     cudaGetSymbolAddress((void**)&wol, d_wol);
    cudaGetSymbolAddress((void**)&qanh, d_qanh);   cudaGetSymbolAddress((void**)&qanl, d_qanl);
    cudaGetSymbolAddress((void**)&ckvnh, d_ckvnh); cudaGetSymbolAddress((void**)&ckvnl, d_ckvnl);
    cudaGetSymbolAddress((void**)&atth, d_atth);   cudaGetSymbolAddress((void**)&attl, d_attl);

    cudaFuncSetAttribute(gemm_bf, cudaFuncAttributeMaxDynamicSharedMemorySize, GEMM_SMEM);
    cudaFuncSetAttribute(flash_tc, cudaFuncAttributeMaxDynamicSharedMemorySize, FLASH_SMEM);

    const dim3 blk(256);

    // split inputs
    split_kernel<<<MTOT, 256>>>(hidden, HDIM, HDIM, hidh, hidl);
    split_kernel<<<QLORA, 256>>>(w_qa, HDIM, HDIM, wqah, wqal);
    split_kernel<<<CKVW, 256>>>(w_kva, HDIM, HDIM, wkvah, wkval);
    split_kernel<<<QW, 256>>>(w_qb, QLORA, QLORA, wqbh, wqbl);
    split_kernel<<<KVW, 256>>>(w_kvb, KVLORA, KVLORA, wkvbh, wkvbl);
    split_kernel<<<HDIM, 256>>>(w_o, OW, OW, woh, wol);

    // q_a = hidden @ w_qa^T   [4096,1536]
    gemm_bf<<<dim3(QLORA/128, MTOT/128), blk, GEMM_SMEM>>>(hidh, hidl, wqah, wqal, qa, MTOT, QLORA, HDIM);
    // ckv = hidden @ w_kva^T  [4096,576]
    gemm_bf<<<dim3((CKVW+127)/128, MTOT/128), blk, GEMM_SMEM>>>(hidh, hidl, wkvah, wkval, ckv, MTOT, CKVW, HDIM);
    // rmsnorms
    rmsnorm_kernel<<<MTOT, 256>>>(qa, g_qa, QLORA, QLORA);
    rmsnorm_kernel<<<MTOT, 256>>>(ckv, g_kva, KVLORA, CKVW);
    // split normalized activations
    split_kernel<<<MTOT, 256>>>(qa, QLORA, QLORA, qanh, qanl);
    split_kernel<<<MTOT, 256>>>(ckv, CKVW, KVLORA, ckvnh, ckvnl);
    // q = rms(q_a) @ w_qb^T   [4096,3072]
    gemm_bf<<<dim3(QW/128, MTOT/128), blk, GEMM_SMEM>>>(qanh, qanl, wqbh, wqbl, q, MTOT, QW, QLORA);
    // kv = rms(ckv) @ w_kvb^T [4096,4096]
    gemm_bf<<<dim3(KVW/128, MTOT/128), blk, GEMM_SMEM>>>(ckvnh, ckvnl, wkvbh, wkvbl, kv, MTOT, KVW, KVLORA);
    // rope
    rope_q_kernel<<<MTOT * NH, 32>>>(q);
    rope_k_kernel<<<MTOT, 32>>>(ckv, kpe);
    // tensor-core flash attention
    flash_tc<<<dim3(SS/128, NH, BB), 256, FLASH_SMEM>>>(q, kv, kpe, attn);
    // out = attn @ w_o^T      [4096,2048]
    split_kernel<<<MTOT, 256>>>(attn, OW, OW, atth, attl);
    gemm_bf<<<dim3(HDIM/128, MTOT/128), blk, GEMM_SMEM>>>(atth, attl, woh, wol, out, MTOT, HDIM, OW);
}

// round 6
// speedup vs baseline: 4.1833x; 1.0204x over previous
#include <cuda_runtime.h>
#include <cuda_bf16.h>
#include <math.h>
#include <stdint.h>

// ---------------- problem constants ----------------
#define HDIM   2048
#define NH     16
#define QLORA  1536
#define KVLORA 512
#define DN     128
#define DR     64
#define DV     128
#define QD     192
#define BB     2
#define SS     2048
#define MTOT   (BB*SS)      // 4096
#define CKVW   (KVLORA+DR)  // 576
#define KVW    (NH*(DN+DV)) // 4096
#define QW     (NH*QD)      // 3072
#define OW     (NH*DV)      // 2048

// ---------------- fp32 scratch ----------------
__device__ float d_qa  [(size_t)MTOT*QLORA];
__device__ float d_q   [(size_t)MTOT*QW];
__device__ float d_ckv [(size_t)MTOT*CKVW];

// ---------------- bf16 hi/lo scratch ----------------
__device__ __nv_bfloat16 d_hidh [(size_t)MTOT*HDIM],   d_hidl [(size_t)MTOT*HDIM];
__device__ __nv_bfloat16 d_wqah [(size_t)QLORA*HDIM],  d_wqal [(size_t)QLORA*HDIM];
__device__ __nv_bfloat16 d_wkvah[(size_t)CKVW*HDIM],   d_wkval[(size_t)CKVW*HDIM];
__device__ __nv_bfloat16 d_wqbh [(size_t)QW*QLORA],    d_wqbl [(size_t)QW*QLORA];
__device__ __nv_bfloat16 d_wkvbh[(size_t)KVW*KVLORA],  d_wkvbl[(size_t)KVW*KVLORA];
__device__ __nv_bfloat16 d_woh  [(size_t)HDIM*OW],     d_wol  [(size_t)HDIM*OW];
__device__ __nv_bfloat16 d_qanh [(size_t)MTOT*QLORA],  d_qanl [(size_t)MTOT*QLORA];
__device__ __nv_bfloat16 d_ckvnh[(size_t)MTOT*KVLORA], d_ckvnl[(size_t)MTOT*KVLORA];
__device__ __nv_bfloat16 d_kvh  [(size_t)MTOT*KVW],    d_kvl  [(size_t)MTOT*KVW];
__device__ __nv_bfloat16 d_kpeh [(size_t)MTOT*DR],     d_kpel [(size_t)MTOT*DR];
__device__ __nv_bfloat16 d_atth [(size_t)MTOT*OW],     d_attl [(size_t)MTOT*OW];

// ---------------- helpers ----------------
__device__ __forceinline__ uint32_t smem_u32(const void* p) {
    uint32_t a;
    asm("{ .reg .u64 t; cvta.to.shared.u64 t, %1; cvt.u32.u64 %0, t; }" : "=r"(a) : "l"(p));
    return a;
}

__device__ __forceinline__ void ldsm4(uint32_t r[4], uint32_t addr) {
    asm volatile("ldmatrix.sync.aligned.m8n8.x4.shared.b16 {%0,%1,%2,%3}, [%4];"
                 : "=r"(r[0]), "=r"(r[1]), "=r"(r[2]), "=r"(r[3]) : "r"(addr));
}

__device__ __forceinline__ void ldsm4t(uint32_t r[4], uint32_t addr) {
    asm volatile("ldmatrix.sync.aligned.m8n8.x4.trans.shared.b16 {%0,%1,%2,%3}, [%4];"
                 : "=r"(r[0]), "=r"(r[1]), "=r"(r[2]), "=r"(r[3]) : "r"(addr));
}

__device__ __forceinline__ void mma_bf16(float c[4], const uint32_t a[4],
                                         uint32_t b0, uint32_t b1) {
    asm volatile(
        "mma.sync.aligned.m16n8k16.row.col.f32.bf16.bf16.f32 "
        "{%0,%1,%2,%3}, {%4,%5,%6,%7}, {%8,%9}, {%0,%1,%2,%3};"
        : "+f"(c[0]), "+f"(c[1]), "+f"(c[2]), "+f"(c[3])
        : "r"(a[0]), "r"(a[1]), "r"(a[2]), "r"(a[3]), "r"(b0), "r"(b1));
}

__device__ __forceinline__ void split2(float x, float y, uint32_t& hp, uint32_t& lp) {
    __nv_bfloat16 hx = __float2bfloat16(x), hy = __float2bfloat16(y);
    __nv_bfloat16 lx = __float2bfloat16(x - __bfloat162float(hx));
    __nv_bfloat16 ly = __float2bfloat16(y - __bfloat162float(hy));
    hp = ((uint32_t)__bfloat16_as_ushort(hy) << 16) | __bfloat16_as_ushort(hx);
    lp = ((uint32_t)__bfloat16_as_ushort(ly) << 16) | __bfloat16_as_ushort(lx);
}

__device__ __forceinline__ uint32_t sw64(uint32_t o)   { return o ^ ((o >> 3) & 0x30); }
__device__ __forceinline__ uint32_t swz256(uint32_t o) { return o ^ (((o >> 8) & 7) << 4); }

__device__ __forceinline__ void cpa16(uint32_t dst, const void* src) {
    asm volatile("cp.async.cg.shared.global [%0], [%1], 16;" :: "r"(dst), "l"(src));
}
__device__ __forceinline__ void cpa16p(uint32_t dst, const void* src, bool valid) {
    int sz = valid ? 16 : 0;
    asm volatile("cp.async.cg.shared.global [%0], [%1], 16, %2;" :: "r"(dst), "l"(src), "r"(sz));
}
#define CPA_COMMIT() asm volatile("cp.async.commit_group;" ::: "memory")
#define CPA_WAIT1()  asm volatile("cp.async.wait_group 1;" ::: "memory")
#define CPA_WAIT0()  asm volatile("cp.async.wait_group 0;" ::: "memory")

// ---------------- fp32 -> bf16 hi/lo split ----------------
__global__ void split_kernel(const float* __restrict__ src, int lda, int cols,
                             __nv_bfloat16* __restrict__ h, __nv_bfloat16* __restrict__ l)
{
    const int row = blockIdx.x;
    const float* p = src + (size_t)row * lda;
    uint32_t* hp = reinterpret_cast<uint32_t*>(h + (size_t)row * cols);
    uint32_t* lp = reinterpret_cast<uint32_t*>(l + (size_t)row * cols);
    for (int i = threadIdx.x * 4; i < cols; i += blockDim.x * 4) {
        float4 v = *reinterpret_cast<const float4*>(p + i);
        uint32_t h0, l0, h1, l1;
        split2(v.x, v.y, h0, l0);
        split2(v.z, v.w, h1, l1);
        hp[i/2] = h0; hp[i/2+1] = h1;
        lp[i/2] = l0; lp[i/2+1] = l1;
    }
}

// ---------------- fused RMSNorm + split ----------------
__global__ void rmsnorm_split(const float* __restrict__ x, const float* __restrict__ g,
                              int D, int lda,
                              __nv_bfloat16* __restrict__ h, __nv_bfloat16* __restrict__ l)
{
    const int row = blockIdx.x;
    const float* p = x + (size_t)row * lda;
    float ss = 0.f;
    for (int i = threadIdx.x; i < D; i += blockDim.x) { float v = p[i]; ss += v * v; }
    #pragma unroll
    for (int o = 16; o > 0; o >>= 1) ss += __shfl_xor_sync(0xffffffffu, ss, o);
    __shared__ float sred[8];
    if ((threadIdx.x & 31) == 0) sred[threadIdx.x >> 5] = ss;
    __syncthreads();
    if (threadIdx.x < 8) {
        float v = sred[threadIdx.x];
        #pragma unroll
        for (int o = 4; o > 0; o >>= 1) v += __shfl_xor_sync(0xffu, v, o);
        if (threadIdx.x == 0) sred[0] = v;
    }
    __syncthreads();
    const float inv = rsqrtf(sred[0] / (float)D + 1e-6f);
    uint32_t* hp = reinterpret_cast<uint32_t*>(h + (size_t)row * D);
    uint32_t* lp = reinterpret_cast<uint32_t*>(l + (size_t)row * D);
    for (int i = threadIdx.x * 4; i < D; i += blockDim.x * 4) {
        float4 v = *reinterpret_cast<const float4*>(p + i);
        v.x *= inv * g[i]; v.y *= inv * g[i+1]; v.z *= inv * g[i+2]; v.w *= inv * g[i+3];
        uint32_t h0, l0, h1, l1;
        split2(v.x, v.y, h0, l0);
        split2(v.z, v.w, h1, l1);
        hp[i/2] = h0; hp[i/2+1] = h1;
        lp[i/2] = l0; lp[i/2+1] = l1;
    }
}

// ---------------- bf16x3 GEMM with cp.async double buffering ----------------
#define GS_AH 0
#define GS_AL 8192
#define GS_BH 16384
#define GS_BL 24576
#define GS_STAGE 32768
#define GEMM_SMEM (2*GS_STAGE)

__global__ __launch_bounds__(256) void gemm_bf(
    const __nv_bfloat16* __restrict__ Ah, const __nv_bfloat16* __restrict__ Al,
    const __nv_bfloat16* __restrict__ Bh, const __nv_bfloat16* __restrict__ Bl,
    float* __restrict__ C, __nv_bfloat16* __restrict__ Ch, __nv_bfloat16* __restrict__ Cl,
    int M, int N, int K)
{
    extern __shared__ char sm[];
    const uint32_t sb = smem_u32(sm);

    const int tid = threadIdx.x;
    const int bm = blockIdx.y * 128;
    const int bn = blockIdx.x * 128;
    const int NC = K >> 5;

    const int w = tid >> 5, lane = tid & 31;
    const int wm = (w & 1) * 64;
    const int wn = (w >> 1) * 32;
    const int mi  = lane >> 3;
    const int aro = (lane & 7) + (mi & 1) * 8;
    const int aks = (mi >> 1) * 8;
    const int bro = (lane & 7) + ((mi >> 1) & 1) * 8;
    const int bks = (mi & 1) * 8;

    float acc[4][4][4] = {};

    auto issue = [&](int c) {
        const int k0 = c << 5;
        const uint32_t st = sb + (c & 1) * GS_STAGE;
        #pragma unroll
        for (int i = 0; i < 2; i++) {
            const int idx = i * 256 + tid;
            const int row = idx >> 2;
            const int c16 = idx & 3;
            const uint32_t dsto = sw64((uint32_t)(row * 64 + c16 * 16));
            const size_t go = (size_t)(bm + row) * K + k0 + c16 * 8;
            cpa16(st + GS_AH + dsto, Ah + go);
            cpa16(st + GS_AL + dsto, Al + go);
            const bool bok = (bn + row) < N;
            const size_t gb = (size_t)(bn + row) * K + k0 + c16 * 8;
            cpa16p(st + GS_BH + dsto, Bh + gb, bok);
            cpa16p(st + GS_BL + dsto, Bl + gb, bok);
        }
        CPA_COMMIT();
    };

    auto compute = [&](int c) {
        const uint32_t st = sb + (c & 1) * GS_STAGE;
        #pragma unroll
        for (int k16 = 0; k16 < 32; k16 += 16) {
            uint32_t A_h[4][4], B_h[2][4];
            #pragma unroll
            for (int f = 0; f < 4; f++) {
                const uint32_t x = (uint32_t)((wm + f * 16 + aro) * 64 + (k16 + aks) * 2);
                ldsm4(A_h[f], st + GS_AH + sw64(x));
            }
            #pragma unroll
            for (int g2 = 0; g2 < 2; g2++) {
                const uint32_t x = (uint32_t)((wn + g2 * 16 + bro) * 64 + (k16 + bks) * 2);
                ldsm4(B_h[g2], st + GS_BH + sw64(x));
            }
            #pragma unroll
            for (int f = 0; f < 4; f++)
                #pragma unroll
                for (int ni = 0; ni < 4; ni++)
                    mma_bf16(acc[f][ni], A_h[f], B_h[ni >> 1][(ni & 1) * 2],
                             B_h[ni >> 1][(ni & 1) * 2 + 1]);
            {
                uint32_t B_l[2][4];
                #pragma unroll
                for (int g2 = 0; g2 < 2; g2++) {
                    const uint32_t x = (uint32_t)((wn + g2 * 16 + bro) * 64 + (k16 + bks) * 2);
                    ldsm4(B_l[g2], st + GS_BL + sw64(x));
                }
                #pragma unroll
                for (int f = 0; f < 4; f++)
                    #pragma unroll
                    for (int ni = 0; ni < 4; ni++)
                        mma_bf16(acc[f][ni], A_h[f], B_l[ni >> 1][(ni & 1) * 2],
                                 B_l[ni >> 1][(ni & 1) * 2 + 1]);
            }
            {
                uint32_t A_l[4][4];
                #pragma unroll
                for (int f = 0; f < 4; f++) {
                    const uint32_t x = (uint32_t)((wm + f * 16 + aro) * 64 + (k16 + aks) * 2);
                    ldsm4(A_l[f], st + GS_AL + sw64(x));
                }
                #pragma unroll
                for (int f = 0; f < 4; f++)
                    #pragma unroll
                    for (int ni = 0; ni < 4; ni++)
                        mma_bf16(acc[f][ni], A_l[f], B_h[ni >> 1][(ni & 1) * 2],
                                 B_h[ni >> 1][(ni & 1) * 2 + 1]);
            }
        }
    };

    issue(0);
    for (int c = 0; c < NC; c++) {
        if (c + 1 < NC) { issue(c + 1); CPA_WAIT1(); } else { CPA_WAIT0(); }
        __syncthreads();
        compute(c);
        __syncthreads();
    }

    const int gq = lane >> 2, t4 = lane & 3;
    if (C) {
        #pragma unroll
        for (int f = 0; f < 4; f++)
            #pragma unroll
            for (int ni = 0; ni < 4; ni++) {
                const int col = bn + wn + ni * 8 + t4 * 2;
                if (col < N) {
                    const int r = bm + wm + f * 16 + gq;
                    *reinterpret_cast<float2*>(&C[(size_t)r * N + col]) =
                        make_float2(acc[f][ni][0], acc[f][ni][1]);
                    *reinterpret_cast<float2*>(&C[(size_t)(r + 8) * N + col]) =
                        make_float2(acc[f][ni][2], acc[f][ni][3]);
                }
            }
    } else {
        #pragma unroll
        for (int f = 0; f < 4; f++)
            #pragma unroll
            for (int ni = 0; ni < 4; ni++) {
                const int col = bn + wn + ni * 8 + t4 * 2;
                if (col < N) {
                    const int r = bm + wm + f * 16 + gq;
                    uint32_t hp, lp;
                    split2(acc[f][ni][0], acc[f][ni][1], hp, lp);
                    *reinterpret_cast<uint32_t*>(&Ch[(size_t)r * N + col]) = hp;
                    *reinterpret_cast<uint32_t*>(&Cl[(size_t)r * N + col]) = lp;
                    split2(acc[f][ni][2], acc[f][ni][3], hp, lp);
                    *reinterpret_cast<uint32_t*>(&Ch[(size_t)(r + 8) * N + col]) = hp;
                    *reinterpret_cast<uint32_t*>(&Cl[(size_t)(r + 8) * N + col]) = lp;
                }
            }
    }
}

// ---------------- RoPE ----------------
__global__ void rope_q_kernel(float* __restrict__ q)
{
    const int idx = blockIdx.x;
    const int row = idx / NH, h = idx % NH;
    const int t = row % SS;
    const int j = threadIdx.x;
    const double inv = exp(-log(10000.0) * (2.0 * j) / (double)DR);
    const double ang = (double)t * inv;
    const float c = (float)cos(ang), s = (float)sin(ang);
    float* p = q + (size_t)row * QW + h * QD + DN;
    const float x0 = p[j], x1 = p[j + 32];
    p[j]      = x0 * c - x1 * s;
    p[j + 32] = x1 * c + x0 * s;
}

__global__ void rope_k_split(const float* __restrict__ ckv,
                             __nv_bfloat16* __restrict__ kpeh, __nv_bfloat16* __restrict__ kpel)
{
    const int row = blockIdx.x;
    const int t = row % SS;
    const int j = threadIdx.x;
    const double inv = exp(-log(10000.0) * (2.0 * j) / (double)DR);
    const double ang = (double)t * inv;
    const float c = (float)cos(ang), s = (float)sin(ang);
    const float* p = ckv + (size_t)row * CKVW + KVLORA;
    const float x0 = p[j], x1 = p[j + 32];
    const float y0 = x0 * c - x1 * s;
    const float y1 = x1 * c + x0 * s;
    __nv_bfloat16 h0 = __float2bfloat16(y0);
    __nv_bfloat16 h1 = __float2bfloat16(y1);
    kpeh[(size_t)row * DR + j]      = h0;
    kpeh[(size_t)row * DR + j + 32] = h1;
    kpel[(size_t)row * DR + j]      = __float2bfloat16(y0 - __bfloat162float(h0));
    kpel[(size_t)row * DR + j + 32] = __float2bfloat16(y1 - __bfloat162float(h1));
}

// ---------------- tensor-core causal flash attention v2 ----------------
// BM=128, BN=64, 8 warps each owning 16 q-rows.
// Q hi/lo: 6 subtiles [128][32] each (sw64) — loaded once from fp32 q.
// K hi/lo: 6 subtiles [64][32] per stage (sw64), cp.async from kvh/kvl + kpeh/kpel, 2 stages.
// V hi/lo: [64 key][128 dv] bf16, 256B rows (swz256), cp.async, single buffer;
//          PV B-fragments via ldmatrix.x4.trans.
#define FQH 0                 // 6*8192 = 49152
#define FQL 49152
#define FKB 98304             // stage s at FKB + s*49152; KH +0, KL +24576
#define FVB 196608            // VH +0, VL +16384
#define FLASH_SMEM 229376

__global__ __launch_bounds__(256) void flash_tc(
    const float* __restrict__ q,
    const __nv_bfloat16* __restrict__ kvh, const __nv_bfloat16* __restrict__ kvl,
    const __nv_bfloat16* __restrict__ kpeh, const __nv_bfloat16* __restrict__ kpel,
    __nv_bfloat16* __restrict__ atth, __nv_bfloat16* __restrict__ attl)
{
    extern __shared__ char sm[];
    const uint32_t sb = smem_u32(sm);

    const int qb = blockIdx.x, h = blockIdx.y, b = blockIdx.z;
    const int tid = threadIdx.x;
    const int w = tid >> 5, lane = tid & 31;
    const int g = lane >> 2, t4 = lane & 3;
    const int mi  = lane >> 3;
    const int aro = (lane & 7) + (mi & 1) * 8;
    const int aks = (mi >> 1) * 8;
    const int bro = (lane & 7) + ((mi >> 1) & 1) * 8;
    const int bks = (mi & 1) * 8;
    const int hoff = h * (DN + DV);

    const int q0 = qb * 128;
    const int row0 = b * SS + q0;
    const int brow = b * SS;
    const float scale = rsqrtf((float)QD);
    const int n_tiles = 2 * qb + 2;

    // K tile loader: 24 16B-chunks per key per (hi|lo): c<16 -> nope, c>=16 -> pe
    auto issueK = [&](int kt) {
        const uint32_t base = sb + FKB + (kt & 1) * 49152;
        const int krow = brow + kt * 64;
        #pragma unroll
        for (int t = 0; t < 12; t++) {
            const int idx = t * 256 + tid;
            const int half = idx >= 1536;
            const int cidx = half ? idx - 1536 : idx;
            const int key = cidx / 24;
            const int c = cidx % 24;
            const int d = (c < 16) ? c * 8 : 128 + (c - 16) * 8;
            const uint32_t dst = base + (half ? 24576u : 0u) + (uint32_t)(d >> 5) * 4096
                               + sw64((uint32_t)(key * 64 + (d & 31) * 2));
            const __nv_bfloat16* src;
            if (c < 16) src = (half ? kvl : kvh) + (size_t)(krow + key) * KVW + hoff + d;
            else        src = (half ? kpel : kpeh) + (size_t)(krow + key) * DR + (d - 128);
            cpa16(dst, src);
        }
    };
    // V tile loader: [key][dv] 256B rows, 16 chunks per key per (hi|lo)
    auto issueV = [&](int kt) {
        const int krow = brow + kt * 64;
        #pragma unroll
        for (int t = 0; t < 8; t++) {
            const int idx = t * 256 + tid;
            const int half = idx >= 1024;
            const int cidx = idx & 1023;
            const int key = cidx >> 4;
            const int d = (cidx & 15) * 8;
            const uint32_t dst = sb + FVB + (half ? 16384u : 0u)
                               + swz256((uint32_t)(key * 256 + d * 2));
            const __nv_bfloat16* src = (half ? kvl : kvh) + (size_t)(krow + key) * KVW + hoff + DN + d;
            cpa16(dst, src);
        }
    };

    // load Q (scaled, fp32 source) -> hi/lo subtiles
    #pragma unroll
    for (int t = 0; t < 24; t++) {
        const int idx = t * 256 + tid;
        const int r = idx / 48;
        const int c4 = (idx % 48) * 4;
        float4 v = *reinterpret_cast<const float4*>(&q[(size_t)(row0 + r) * QW + h * QD + c4]);
        v.x *= scale; v.y *= scale; v.z *= scale; v.w *= scale;
        const uint32_t off = (uint32_t)(c4 >> 5) * 8192 + sw64((uint32_t)(r * 64 + (c4 & 31) * 2));
        uint32_t h0, l0, h1, l1;
        split2(v.x, v.y, h0, l0);
        split2(v.z, v.w, h1, l1);
        *reinterpret_cast<uint2*>(sm + FQH + off) = make_uint2(h0, h1);
        *reinterpret_cast<uint2*>(sm + FQL + off) = make_uint2(l0, l1);
    }

    issueK(0);
    issueV(0);
    CPA_COMMIT();

    float of[16][4] = {};
    float m0 = -INFINITY, m1 = -INFINITY, l0 = 0.f, l1 = 0.f;

    for (int kt = 0; kt < n_tiles; kt++) {
        if (kt + 1 < n_tiles) { issueK(kt + 1); CPA_COMMIT(); CPA_WAIT1(); }
        else                  { CPA_WAIT0(); }
        __syncthreads();

        const int k0 = kt * 64;
        const uint32_t kbase = sb + FKB + (kt & 1) * 49152;

        // S = Q @ K^T (3 passes)
        float sf[8][4] = {};
        const uint32_t qax = (uint32_t)((w * 16 + aro) * 64 + aks * 2);
        #pragma unroll
        for (int s = 0; s < 12; s++) {
            uint32_t ah[4], al[4];
            const uint32_t qoff = (uint32_t)(s >> 1) * 8192 + sw64(qax + (s & 1) * 32);
            ldsm4(ah, sb + FQH + qoff);
            ldsm4(al, sb + FQL + qoff);
            #pragma unroll
            for (int g2 = 0; g2 < 4; g2++) {
                const uint32_t kx = (uint32_t)((g2 * 16 + bro) * 64 + bks * 2);
                const uint32_t koff = (uint32_t)(s >> 1) * 4096 + sw64(kx + (s & 1) * 32);
                uint32_t bh[4], bl[4];
                ldsm4(bh, kbase + koff);
                ldsm4(bl, kbase + 24576 + koff);
                #pragma unroll
                for (int sub = 0; sub < 2; sub++) {
                    const int ni = g2 * 2 + sub;
                    mma_bf16(sf[ni], ah, bh[sub * 2], bh[sub * 2 + 1]);
                    mma_bf16(sf[ni], ah, bl[sub * 2], bl[sub * 2 + 1]);
                    mma_bf16(sf[ni], al, bh[sub * 2], bh[sub * 2 + 1]);
                }
            }
        }

        // causal mask
        if (kt >= 2 * qb) {
            const int qr0 = q0 + w * 16 + g;
            const int qr8 = qr0 + 8;
            #pragma unroll
            for (int ni = 0; ni < 8; ni++) {
                const int kp0 = k0 + ni * 8 + 2 * t4;
                const int kp1 = kp0 + 1;
                if (kp0 > qr0) sf[ni][0] = -1e30f;
                if (kp1 > qr0) sf[ni][1] = -1e30f;
                if (kp0 > qr8) sf[ni][2] = -1e30f;
                if (kp1 > qr8) sf[ni][3] = -1e30f;
            }
        }

        // online softmax
        float tm0 = -INFINITY, tm1 = -INFINITY;
        #pragma unroll
        for (int ni = 0; ni < 8; ni++) {
            tm0 = fmaxf(tm0, fmaxf(sf[ni][0], sf[ni][1]));
            tm1 = fmaxf(tm1, fmaxf(sf[ni][2], sf[ni][3]));
        }
        #pragma unroll
        for (int o = 1; o < 4; o <<= 1) {
            tm0 = fmaxf(tm0, __shfl_xor_sync(0xffffffffu, tm0, o));
            tm1 = fmaxf(tm1, __shfl_xor_sync(0xffffffffu, tm1, o));
        }
        const float mn0 = fmaxf(m0, tm0), mn1 = fmaxf(m1, tm1);
        const float a0 = __expf(m0 - mn0), a1 = __expf(m1 - mn1);
        float ls0 = 0.f, ls1 = 0.f;
        #pragma unroll
        for (int ni = 0; ni < 8; ni++) {
            sf[ni][0] = __expf(sf[ni][0] - mn0); ls0 += sf[ni][0];
            sf[ni][1] = __expf(sf[ni][1] - mn0); ls0 += sf[ni][1];
            sf[ni][2] = __expf(sf[ni][2] - mn1); ls1 += sf[ni][2];
            sf[ni][3] = __expf(sf[ni][3] - mn1); ls1 += sf[ni][3];
        }
        #pragma unroll
        for (int o = 1; o < 4; o <<= 1) {
            ls0 += __shfl_xor_sync(0xffffffffu, ls0, o);
            ls1 += __shfl_xor_sync(0xffffffffu, ls1, o);
        }
        l0 = l0 * a0 + ls0; l1 = l1 * a1 + ls1;
        m0 = mn0; m1 = mn1;
        #pragma unroll
        for (int ni = 0; ni < 16; ni++) {
            of[ni][0] *= a0; of[ni][1] *= a0;
            of[ni][2] *= a1; of[ni][3] *= a1;
        }

        // O += P @ V   (B-fragments via ldmatrix.trans on [key][dv] tile)
        #pragma unroll
        for (int ks = 0; ks < 4; ks++) {
            uint32_t ph[4], pl[4];
            split2(sf[2*ks][0],   sf[2*ks][1],   ph[0], pl[0]);
            split2(sf[2*ks][2],   sf[2*ks][3],   ph[1], pl[1]);
            split2(sf[2*ks+1][0], sf[2*ks+1][1], ph[2], pl[2]);
            split2(sf[2*ks+1][2], sf[2*ks+1][3], ph[3], pl[3]);
            const int vkey = ks * 16 + (mi & 1) * 8 + (lane & 7);
            const int vdvo = (mi >> 1) * 8;
            #pragma unroll
            for (int g2 = 0; g2 < 8; g2++) {
                const uint32_t vo = swz256((uint32_t)(vkey * 256 + (g2 * 16 + vdvo) * 2));
                uint32_t vh[4], vl[4];
                ldsm4t(vh, sb + FVB + vo);
                ldsm4t(vl, sb + FVB + 16384 + vo);
                #pragma unroll
                for (int sub = 0; sub < 2; sub++) {
                    const int ni = g2 * 2 + sub;
                    mma_bf16(of[ni], ph, vh[sub * 2], vh[sub * 2 + 1]);
                    mma_bf16(of[ni], ph, vl[sub * 2], vl[sub * 2 + 1]);
                    mma_bf16(of[ni], pl, vh[sub * 2], vh[sub * 2 + 1]);
                }
            }
        }
        __syncthreads();
        if (kt + 1 < n_tiles) { issueV(kt + 1); CPA_COMMIT(); }
    }

    const float il0 = 1.f / l0, il1 = 1.f / l1;
    const int rg = row0 + w * 16 + g;
    #pragma unroll
    for (int ni = 0; ni < 16; ni++) {
        const int col = h * DV + ni * 8 + t4 * 2;
        uint32_t hp, lp;
        split2(of[ni][0] * il0, of[ni][1] * il0, hp, lp);
        *reinterpret_cast<uint32_t*>(&atth[(size_t)rg * OW + col]) = hp;
        *reinterpret_cast<uint32_t*>(&attl[(size_t)rg * OW + col]) = lp;
        split2(of[ni][2] * il1, of[ni][3] * il1, hp, lp);
        *reinterpret_cast<uint32_t*>(&atth[(size_t)(rg + 8) * OW + col]) = hp;
        *reinterpret_cast<uint32_t*>(&attl[(size_t)(rg + 8) * OW + col]) = lp;
    }
}

// ---------------- launch ----------------
extern "C" void kernel_launch(void* const* d_in, const int* in_sizes, int n_in,
                              void* d_out, int out_size)
{
    (void)in_sizes; (void)n_in; (void)out_size;
    const float* hidden = (const float*)d_in[0];
    const float* w_qa   = (const float*)d_in[1];
    const float* g_qa   = (const float*)d_in[2];
    const float* w_qb   = (const float*)d_in[3];
    const float* w_kva  = (const float*)d_in[4];
    const float* g_kva  = (const float*)d_in[5];
    const float* w_kvb  = (const float*)d_in[6];
    const float* w_o    = (const float*)d_in[7];
    float* out = (float*)d_out;

    float *qa, *q, *ckv;
    cudaGetSymbolAddress((void**)&qa,   d_qa);
    cudaGetSymbolAddress((void**)&q,    d_q);
    cudaGetSymbolAddress((void**)&ckv,  d_ckv);

    __nv_bfloat16 *hidh,*hidl,*wqah,*wqal,*wkvah,*wkval,*wqbh,*wqbl,*wkvbh,*wkvbl,*woh,*wol;
    __nv_bfloat16 *qanh,*qanl,*ckvnh,*ckvnl,*kvh,*kvl,*kpeh,*kpel,*atth,*attl;
    cudaGetSymbolAddress((void**)&hidh, d_hidh);   cudaGetSymbolAddress((void**)&hidl, d_hidl);
    cudaGetSymbolAddress((void**)&wqah, d_wqah);   cudaGetSymbolAddress((void**)&wqal, d_wqal);
    cudaGetSymbolAddress((void**)&wkvah, d_wkvah); cudaGetSymbolAddress((void**)&wkval, d_wkval);
    cudaGetSymbolAddress((void**)&wqbh, d_wqbh);   cudaGetSymbolAddress((void**)&wqbl, d_wqbl);
    cudaGetSymbolAddress((void**)&wkvbh, d_wkvbh); cudaGetSymbolAddress((void**)&wkvbl, d_wkvbl);
    cudaGetSymbolAddress((void**)&woh, d_woh);     cudaGetSymbolAddress((void**)&wol, d_wol);
    cudaGetSymbolAddress((void**)&qanh, d_qanh);   cudaGetSymbolAddress((void**)&qanl, d_qanl);
    cudaGetSymbolAddress((void**)&ckvnh, d_ckvnh); cudaGetSymbolAddress((void**)&ckvnl, d_ckvnl);
    cudaGetSymbolAddress((void**)&kvh, d_kvh);     cudaGetSymbolAddress((void**)&kvl, d_kvl);
    cudaGetSymbolAddress((void**)&kpeh, d_kpeh);   cudaGetSymbolAddress((void**)&kpel, d_kpel);
    cudaGetSymbolAddress((void**)&atth, d_atth);   cudaGetSymbolAddress((void**)&attl, d_attl);

    cudaFuncSetAttribute(gemm_bf, cudaFuncAttributeMaxDynamicSharedMemorySize, GEMM_SMEM);
    cudaFuncSetAttribute(flash_tc, cudaFuncAttributeMaxDynamicSharedMemorySize, FLASH_SMEM);

    const dim3 blk(256);

    // split inputs (weights + hidden)
    split_kernel<<<MTOT, 256>>>(hidden, HDIM, HDIM, hidh, hidl);
    split_kernel<<<QLORA, 256>>>(w_qa, HDIM, HDIM, wqah, wqal);
    split_kernel<<<CKVW, 256>>>(w_kva, HDIM, HDIM, wkvah, wkval);
    split_kernel<<<QW, 256>>>(w_qb, QLORA, QLORA, wqbh, wqbl);
    split_kernel<<<KVW, 256>>>(w_kvb, KVLORA, KVLORA, wkvbh, wkvbl);
    split_kernel<<<HDIM, 256>>>(w_o, OW, OW, woh, wol);

    // q_a = hidden @ w_qa^T   [4096,1536] (fp32 out)
    gemm_bf<<<dim3(QLORA/128, MTOT/128), blk, GEMM_SMEM>>>(hidh, hidl, wqah, wqal, qa, nullptr, nullptr, MTOT, QLORA, HDIM);
    // ckv = hidden @ w_kva^T  [4096,576] (fp32 out)
    gemm_bf<<<dim3((CKVW+127)/128, MTOT/128), blk, GEMM_SMEM>>>(hidh, hidl, wkvah, wkval, ckv, nullptr, nullptr, MTOT, CKVW, HDIM);
    // fused rmsnorm + split
    rmsnorm_split<<<MTOT, 256>>>(qa, g_qa, QLORA, QLORA, qanh, qanl);
    rmsnorm_split<<<MTOT, 256>>>(ckv, g_kva, KVLORA, CKVW, ckvnh, ckvnl);
    // q = rms(q_a) @ w_qb^T   [4096,3072] (fp32 out, rope follows)
    gemm_bf<<<dim3(QW/128, MTOT/128), blk, GEMM_SMEM>>>(qanh, qanl, wqbh, wqbl, q, nullptr, nullptr, MTOT, QW, QLORA);
    // kv = rms(ckv) @ w_kvb^T [4096,4096] (bf16 hi/lo out)
    gemm_bf<<<dim3(KVW/128, MTOT/128), blk, GEMM_SMEM>>>(ckvnh, ckvnl, wkvbh, wkvbl, nullptr, kvh, kvl, MTOT, KVW, KVLORA);
    // rope
    rope_q_kernel<<<MTOT * NH, 32>>>(q);
    rope_k_split<<<MTOT, 32>>>(ckv, kpeh, kpel);
    // flash attention (writes bf16 hi/lo attn)
    flash_tc<<<dim3(SS/128, NH, BB), 256, FLASH_SMEM>>>(q, kvh, kvl, kpeh, kpel, atth, attl);
    // out = attn @ w_o^T      [4096,2048]
    gemm_bf<<<dim3(HDIM/128, MTOT/128), blk, GEMM_SMEM>>>(atth, attl, woh, wol, out, nullptr, nullptr, MTOT, HDIM, OW);
}

// round 8
// speedup vs baseline: 4.2028x; 1.0047x over previous
#include <cuda_runtime.h>
#include <cuda_bf16.h>
#include <math.h>
#include <stdint.h>

// ---------------- problem constants ----------------
#define HDIM   2048
#define NH     16
#define QLORA  1536
#define KVLORA 512
#define DN     128
#define DR     64
#define DV     128
#define QD     192
#define BB     2
#define SS     2048
#define MTOT   (BB*SS)      // 4096
#define CKVW   (KVLORA+DR)  // 576
#define KVW    (NH*(DN+DV)) // 4096
#define QW     (NH*QD)      // 3072
#define OW     (NH*DV)      // 2048

// ---------------- fp32 scratch ----------------
__device__ float d_qa  [(size_t)MTOT*QLORA];
__device__ float d_q   [(size_t)MTOT*QW];
__device__ float d_ckv [(size_t)MTOT*CKVW];

// ---------------- bf16 hi/lo scratch ----------------
__device__ __nv_bfloat16 d_hidh [(size_t)MTOT*HDIM],   d_hidl [(size_t)MTOT*HDIM];
__device__ __nv_bfloat16 d_wqah [(size_t)QLORA*HDIM],  d_wqal [(size_t)QLORA*HDIM];
__device__ __nv_bfloat16 d_wkvah[(size_t)CKVW*HDIM],   d_wkval[(size_t)CKVW*HDIM];
__device__ __nv_bfloat16 d_wqbh [(size_t)QW*QLORA],    d_wqbl [(size_t)QW*QLORA];
__device__ __nv_bfloat16 d_wkvbh[(size_t)KVW*KVLORA],  d_wkvbl[(size_t)KVW*KVLORA];
__device__ __nv_bfloat16 d_woh  [(size_t)HDIM*OW],     d_wol  [(size_t)HDIM*OW];
__device__ __nv_bfloat16 d_qanh [(size_t)MTOT*QLORA],  d_qanl [(size_t)MTOT*QLORA];
__device__ __nv_bfloat16 d_ckvnh[(size_t)MTOT*KVLORA], d_ckvnl[(size_t)MTOT*KVLORA];
__device__ __nv_bfloat16 d_kvh  [(size_t)MTOT*KVW],    d_kvl  [(size_t)MTOT*KVW];
__device__ __nv_bfloat16 d_kpeh [(size_t)MTOT*DR],     d_kpel [(size_t)MTOT*DR];
__device__ __nv_bfloat16 d_atth [(size_t)MTOT*OW],     d_attl [(size_t)MTOT*OW];

// ---------------- helpers ----------------
__device__ __forceinline__ uint32_t smem_u32(const void* p) {
    uint32_t a;
    asm("{ .reg .u64 t; cvta.to.shared.u64 t, %1; cvt.u32.u64 %0, t; }" : "=r"(a) : "l"(p));
    return a;
}

__device__ __forceinline__ void ldsm4(uint32_t r[4], uint32_t addr) {
    asm volatile("ldmatrix.sync.aligned.m8n8.x4.shared.b16 {%0,%1,%2,%3}, [%4];"
                 : "=r"(r[0]), "=r"(r[1]), "=r"(r[2]), "=r"(r[3]) : "r"(addr));
}

__device__ __forceinline__ void ldsm4t(uint32_t r[4], uint32_t addr) {
    asm volatile("ldmatrix.sync.aligned.m8n8.x4.trans.shared.b16 {%0,%1,%2,%3}, [%4];"
                 : "=r"(r[0]), "=r"(r[1]), "=r"(r[2]), "=r"(r[3]) : "r"(addr));
}

__device__ __forceinline__ void mma_bf16(float c[4], const uint32_t a[4],
                                         uint32_t b0, uint32_t b1) {
    asm volatile(
        "mma.sync.aligned.m16n8k16.row.col.f32.bf16.bf16.f32 "
        "{%0,%1,%2,%3}, {%4,%5,%6,%7}, {%8,%9}, {%0,%1,%2,%3};"
        : "+f"(c[0]), "+f"(c[1]), "+f"(c[2]), "+f"(c[3])
        : "r"(a[0]), "r"(a[1]), "r"(a[2]), "r"(a[3]), "r"(b0), "r"(b1));
}

__device__ __forceinline__ void split2(float x, float y, uint32_t& hp, uint32_t& lp) {
    __nv_bfloat16 hx = __float2bfloat16(x), hy = __float2bfloat16(y);
    __nv_bfloat16 lx = __float2bfloat16(x - __bfloat162float(hx));
    __nv_bfloat16 ly = __float2bfloat16(y - __bfloat162float(hy));
    hp = ((uint32_t)__bfloat16_as_ushort(hy) << 16) | __bfloat16_as_ushort(hx);
    lp = ((uint32_t)__bfloat16_as_ushort(ly) << 16) | __bfloat16_as_ushort(lx);
}

__device__ __forceinline__ uint32_t sw64(uint32_t o)   { return o ^ ((o >> 3) & 0x30); }
__device__ __forceinline__ uint32_t swz256(uint32_t o) { return o ^ (((o >> 8) & 7) << 4); }

__device__ __forceinline__ void cpa16(uint32_t dst, const void* src) {
    asm volatile("cp.async.cg.shared.global [%0], [%1], 16;" :: "r"(dst), "l"(src));
}
__device__ __forceinline__ void cpa16p(uint32_t dst, const void* src, bool valid) {
    int sz = valid ? 16 : 0;
    asm volatile("cp.async.cg.shared.global [%0], [%1], 16, %2;" :: "r"(dst), "l"(src), "r"(sz));
}
#define CPA_COMMIT() asm volatile("cp.async.commit_group;" ::: "memory")
#define CPA_WAIT1()  asm volatile("cp.async.wait_group 1;" ::: "memory")
#define CPA_WAIT0()  asm volatile("cp.async.wait_group 0;" ::: "memory")

// ---------------- fp32 -> bf16 hi/lo split ----------------
__global__ void split_kernel(const float* __restrict__ src, int lda, int cols,
                             __nv_bfloat16* __restrict__ h, __nv_bfloat16* __restrict__ l)
{
    const int row = blockIdx.x;
    const float* p = src + (size_t)row * lda;
    uint32_t* hp = reinterpret_cast<uint32_t*>(h + (size_t)row * cols);
    uint32_t* lp = reinterpret_cast<uint32_t*>(l + (size_t)row * cols);
    for (int i = threadIdx.x * 4; i < cols; i += blockDim.x * 4) {
        float4 v = *reinterpret_cast<const float4*>(p + i);
        uint32_t h0, l0, h1, l1;
        split2(v.x, v.y, h0, l0);
        split2(v.z, v.w, h1, l1);
        hp[i/2] = h0; hp[i/2+1] = h1;
        lp[i/2] = l0; lp[i/2+1] = l1;
    }
}

// ---------------- fused RMSNorm + split ----------------
__global__ void rmsnorm_split(const float* __restrict__ x, const float* __restrict__ g,
                              int D, int lda,
                              __nv_bfloat16* __restrict__ h, __nv_bfloat16* __restrict__ l)
{
    const int row = blockIdx.x;
    const float* p = x + (size_t)row * lda;
    float ss = 0.f;
    for (int i = threadIdx.x; i < D; i += blockDim.x) { float v = p[i]; ss += v * v; }
    #pragma unroll
    for (int o = 16; o > 0; o >>= 1) ss += __shfl_xor_sync(0xffffffffu, ss, o);
    __shared__ float sred[8];
    if ((threadIdx.x & 31) == 0) sred[threadIdx.x >> 5] = ss;
    __syncthreads();
    if (threadIdx.x < 8) {
        float v = sred[threadIdx.x];
        #pragma unroll
        for (int o = 4; o > 0; o >>= 1) v += __shfl_xor_sync(0xffu, v, o);
        if (threadIdx.x == 0) sred[0] = v;
    }
    __syncthreads();
    const float inv = rsqrtf(sred[0] / (float)D + 1e-6f);
    uint32_t* hp = reinterpret_cast<uint32_t*>(h + (size_t)row * D);
    uint32_t* lp = reinterpret_cast<uint32_t*>(l + (size_t)row * D);
    for (int i = threadIdx.x * 4; i < D; i += blockDim.x * 4) {
        float4 v = *reinterpret_cast<const float4*>(p + i);
        v.x *= inv * g[i]; v.y *= inv * g[i+1]; v.z *= inv * g[i+2]; v.w *= inv * g[i+3];
        uint32_t h0, l0, h1, l1;
        split2(v.x, v.y, h0, l0);
        split2(v.z, v.w, h1, l1);
        hp[i/2] = h0; hp[i/2+1] = h1;
        lp[i/2] = l0; lp[i/2+1] = l1;
    }
}

// ---------------- bf16x3 GEMM, 3-stage cp.async pipeline ----------------
#define GS_AH 0
#define GS_AL 8192
#define GS_BH 16384
#define GS_BL 24576
#define GS_STAGE 32768
#define GEMM_SMEM (3*GS_STAGE)

__global__ __launch_bounds__(256) void gemm_bf(
    const __nv_bfloat16* __restrict__ Ah, const __nv_bfloat16* __restrict__ Al,
    const __nv_bfloat16* __restrict__ Bh, const __nv_bfloat16* __restrict__ Bl,
    float* __restrict__ C, __nv_bfloat16* __restrict__ Ch, __nv_bfloat16* __restrict__ Cl,
    int M, int N, int K)
{
    extern __shared__ char sm[];
    const uint32_t sb = smem_u32(sm);

    const int tid = threadIdx.x;
    const int bm = blockIdx.y * 128;
    const int bn = blockIdx.x * 128;
    const int NC = K >> 5;

    const int w = tid >> 5, lane = tid & 31;
    const int wm = (w & 1) * 64;
    const int wn = (w >> 1) * 32;
    const int mi  = lane >> 3;
    const int aro = (lane & 7) + (mi & 1) * 8;
    const int aks = (mi >> 1) * 8;
    const int bro = (lane & 7) + ((mi >> 1) & 1) * 8;
    const int bks = (mi & 1) * 8;

    float acc[4][4][4] = {};

    const int lr0 = tid >> 2;
    const int lc0 = tid & 3;
    const int lr1 = (256 + tid) >> 2;
    const int lc1 = (256 + tid) & 3;
    const uint32_t do0 = sw64((uint32_t)(lr0 * 64 + lc0 * 16));
    const uint32_t do1 = sw64((uint32_t)(lr1 * 64 + lc1 * 16));
    const bool bok0 = (bn + lr0) < N;
    const bool bok1 = (bn + lr1) < N;

    auto issue = [&](int c) {
        const int k0 = c << 5;
        const uint32_t st = sb + (uint32_t)(c % 3) * GS_STAGE;
        {
            const size_t go = (size_t)(bm + lr0) * K + k0 + lc0 * 8;
            cpa16(st + GS_AH + do0, Ah + go);
            cpa16(st + GS_AL + do0, Al + go);
            const size_t gb = (size_t)(bn + lr0) * K + k0 + lc0 * 8;
            cpa16p(st + GS_BH + do0, Bh + gb, bok0);
            cpa16p(st + GS_BL + do0, Bl + gb, bok0);
        }
        {
            const size_t go = (size_t)(bm + lr1) * K + k0 + lc1 * 8;
            cpa16(st + GS_AH + do1, Ah + go);
            cpa16(st + GS_AL + do1, Al + go);
            const size_t gb = (size_t)(bn + lr1) * K + k0 + lc1 * 8;
            cpa16p(st + GS_BH + do1, Bh + gb, bok1);
            cpa16p(st + GS_BL + do1, Bl + gb, bok1);
        }
        CPA_COMMIT();
    };

    auto compute = [&](int c) {
        const uint32_t st = sb + (uint32_t)(c % 3) * GS_STAGE;
        #pragma unroll
        for (int k16 = 0; k16 < 32; k16 += 16) {
            uint32_t A_h[4][4], B_h[2][4];
            #pragma unroll
            for (int f = 0; f < 4; f++) {
                const uint32_t x = (uint32_t)((wm + f * 16 + aro) * 64 + (k16 + aks) * 2);
                ldsm4(A_h[f], st + GS_AH + sw64(x));
            }
            #pragma unroll
            for (int g2 = 0; g2 < 2; g2++) {
                const uint32_t x = (uint32_t)((wn + g2 * 16 + bro) * 64 + (k16 + bks) * 2);
                ldsm4(B_h[g2], st + GS_BH + sw64(x));
            }
            #pragma unroll
            for (int f = 0; f < 4; f++)
                #pragma unroll
                for (int ni = 0; ni < 4; ni++)
                    mma_bf16(acc[f][ni], A_h[f], B_h[ni >> 1][(ni & 1) * 2],
                             B_h[ni >> 1][(ni & 1) * 2 + 1]);
            {
                uint32_t B_l[2][4];
                #pragma unroll
                for (int g2 = 0; g2 < 2; g2++) {
                    const uint32_t x = (uint32_t)((wn + g2 * 16 + bro) * 64 + (k16 + bks) * 2);
                    ldsm4(B_l[g2], st + GS_BL + sw64(x));
                }
                #pragma unroll
                for (int f = 0; f < 4; f++)
                    #pragma unroll
                    for (int ni = 0; ni < 4; ni++)
                        mma_bf16(acc[f][ni], A_h[f], B_l[ni >> 1][(ni & 1) * 2],
                                 B_l[ni >> 1][(ni & 1) * 2 + 1]);
            }
            {
                uint32_t A_l[4][4];
                #pragma unroll
                for (int f = 0; f < 4; f++) {
                    const uint32_t x = (uint32_t)((wm + f * 16 + aro) * 64 + (k16 + aks) * 2);
                    ldsm4(A_l[f], st + GS_AL + sw64(x));
                }
                #pragma unroll
                for (int f = 0; f < 4; f++)
                    #pragma unroll
                    for (int ni = 0; ni < 4; ni++)
                        mma_bf16(acc[f][ni], A_l[f], B_h[ni >> 1][(ni & 1) * 2],
                                 B_h[ni >> 1][(ni & 1) * 2 + 1]);
            }
        }
    };

    // 3-stage pipeline: 2 groups in flight, one barrier per chunk
    issue(0);
    issue(1);
    for (int c = 0; c < NC; c++) {
        if (c + 1 < NC) CPA_WAIT1(); else CPA_WAIT0();
        __syncthreads();
        if (c + 2 < NC) issue(c + 2);
        compute(c);
        __syncthreads();
    }

    const int gq = lane >> 2, t4 = lane & 3;
    if (C) {
        #pragma unroll
        for (int f = 0; f < 4; f++)
            #pragma unroll
            for (int ni = 0; ni < 4; ni++) {
                const int col = bn + wn + ni * 8 + t4 * 2;
                if (col < N) {
                    const int r = bm + wm + f * 16 + gq;
                    *reinterpret_cast<float2*>(&C[(size_t)r * N + col]) =
                        make_float2(acc[f][ni][0], acc[f][ni][1]);
                    *reinterpret_cast<float2*>(&C[(size_t)(r + 8) * N + col]) =
                        make_float2(acc[f][ni][2], acc[f][ni][3]);
                }
            }
    } else {
        #pragma unroll
        for (int f = 0; f < 4; f++)
            #pragma unroll
            for (int ni = 0; ni < 4; ni++) {
                const int col = bn + wn + ni * 8 + t4 * 2;
                if (col < N) {
                    const int r = bm + wm + f * 16 + gq;
                    uint32_t hp, lp;
                    split2(acc[f][ni][0], acc[f][ni][1], hp, lp);
                    *reinterpret_cast<uint32_t*>(&Ch[(size_t)r * N + col]) = hp;
                    *reinterpret_cast<uint32_t*>(&Cl[(size_t)r * N + col]) = lp;
                    split2(acc[f][ni][2], acc[f][ni][3], hp, lp);
                    *reinterpret_cast<uint32_t*>(&Ch[(size_t)(r + 8) * N + col]) = hp;
                    *reinterpret_cast<uint32_t*>(&Cl[(size_t)(r + 8) * N + col]) = lp;
                }
            }
    }
}

// ---------------- RoPE ----------------
__global__ void rope_q_kernel(float* __restrict__ q)
{
    const int idx = blockIdx.x;
    const int row = idx / NH, h = idx % NH;
    const int t = row % SS;
    const int j = threadIdx.x;
    const double inv = exp(-log(10000.0) * (2.0 * j) / (double)DR);
    const double ang = (double)t * inv;
    const float c = (float)cos(ang), s = (float)sin(ang);
    float* p = q + (size_t)row * QW + h * QD + DN;
    const float x0 = p[j], x1 = p[j + 32];
    p[j]      = x0 * c - x1 * s;
    p[j + 32] = x1 * c + x0 * s;
}

__global__ void rope_k_split(const float* __restrict__ ckv,
                             __nv_bfloat16* __restrict__ kpeh, __nv_bfloat16* __restrict__ kpel)
{
    const int row = blockIdx.x;
    const int t = row % SS;
    const int j = threadIdx.x;
    const double inv = exp(-log(10000.0) * (2.0 * j) / (double)DR);
    const double ang = (double)t * inv;
    const float c = (float)cos(ang), s = (float)sin(ang);
    const float* p = ckv + (size_t)row * CKVW + KVLORA;
    const float x0 = p[j], x1 = p[j + 32];
    const float y0 = x0 * c - x1 * s;
    const float y1 = x1 * c + x0 * s;
    __nv_bfloat16 h0 = __float2bfloat16(y0);
    __nv_bfloat16 h1 = __float2bfloat16(y1);
    kpeh[(size_t)row * DR + j]      = h0;
    kpeh[(size_t)row * DR + j + 32] = h1;
    kpel[(size_t)row * DR + j]      = __float2bfloat16(y0 - __bfloat162float(h0));
    kpel[(size_t)row * DR + j + 32] = __float2bfloat16(y1 - __bfloat162float(h1));
}

// ---------------- tensor-core causal flash attention ----------------
#define FQH 0                 // 6*8192 = 49152
#define FQL 49152
#define FKB 98304             // stage s at FKB + s*49152; KH +0, KL +24576
#define FVB 196608            // VH +0, VL +16384
#define FLASH_SMEM 229376

__global__ __launch_bounds__(256) void flash_tc(
    const float* __restrict__ q,
    const __nv_bfloat16* __restrict__ kvh, const __nv_bfloat16* __restrict__ kvl,
    const __nv_bfloat16* __restrict__ kpeh, const __nv_bfloat16* __restrict__ kpel,
    __nv_bfloat16* __restrict__ atth, __nv_bfloat16* __restrict__ attl)
{
    extern __shared__ char sm[];
    const uint32_t sb = smem_u32(sm);

    const int qb = blockIdx.x, h = blockIdx.y, b = blockIdx.z;
    const int tid = threadIdx.x;
    const int w = tid >> 5, lane = tid & 31;
    const int g = lane >> 2, t4 = lane & 3;
    const int mi  = lane >> 3;
    const int aro = (lane & 7) + (mi & 1) * 8;
    const int aks = (mi >> 1) * 8;
    const int bro = (lane & 7) + ((mi >> 1) & 1) * 8;
    const int bks = (mi & 1) * 8;
    const int hoff = h * (DN + DV);

    const int q0 = qb * 128;
    const int row0 = b * SS + q0;
    const int brow = b * SS;
    const float scale = rsqrtf((float)QD);
    const int n_tiles = 2 * qb + 2;

    auto issueK = [&](int kt) {
        const uint32_t base = sb + FKB + (kt & 1) * 49152;
        const int krow = brow + kt * 64;
        #pragma unroll
        for (int t = 0; t < 12; t++) {
            const int idx = t * 256 + tid;
            const int half = idx >= 1536;
            const int cidx = half ? idx - 1536 : idx;
            const int key = cidx / 24;
            const int c = cidx % 24;
            const int d = (c < 16) ? c * 8 : 128 + (c - 16) * 8;
            const uint32_t dst = base + (half ? 24576u : 0u) + (uint32_t)(d >> 5) * 4096
                               + sw64((uint32_t)(key * 64 + (d & 31) * 2));
            const __nv_bfloat16* src;
            if (c < 16) src = (half ? kvl : kvh) + (size_t)(krow + key) * KVW + hoff + d;
            else        src = (half ? kpel : kpeh) + (size_t)(krow + key) * DR + (d - 128);
            cpa16(dst, src);
        }
    };
    auto issueV = [&](int kt) {
        const int krow = brow + kt * 64;
        #pragma unroll
        for (int t = 0; t < 8; t++) {
            const int idx = t * 256 + tid;
            const int half = idx >= 1024;
            const int cidx = idx & 1023;
            const int key = cidx >> 4;
            const int d = (cidx & 15) * 8;
            const uint32_t dst = sb + FVB + (half ? 16384u : 0u)
                               + swz256((uint32_t)(key * 256 + d * 2));
            const __nv_bfloat16* src = (half ? kvl : kvh) + (size_t)(krow + key) * KVW + hoff + DN + d;
            cpa16(dst, src);
        }
    };

    #pragma unroll
    for (int t = 0; t < 24; t++) {
        const int idx = t * 256 + tid;
        const int r = idx / 48;
        const int c4 = (idx % 48) * 4;
        float4 v = *reinterpret_cast<const float4*>(&q[(size_t)(row0 + r) * QW + h * QD + c4]);
        v.x *= scale; v.y *= scale; v.z *= scale; v.w *= scale;
        const uint32_t off = (uint32_t)(c4 >> 5) * 8192 + sw64((uint32_t)(r * 64 + (c4 & 31) * 2));
        uint32_t h0, l0, h1, l1;
        split2(v.x, v.y, h0, l0);
        split2(v.z, v.w, h1, l1);
        *reinterpret_cast<uint2*>(sm + FQH + off) = make_uint2(h0, h1);
        *reinterpret_cast<uint2*>(sm + FQL + off) = make_uint2(l0, l1);
    }

    issueK(0);
    issueV(0);
    CPA_COMMIT();

    float of[16][4] = {};
    float m0 = -INFINITY, m1 = -INFINITY, l0 = 0.f, l1 = 0.f;

    for (int kt = 0; kt < n_tiles; kt++) {
        if (kt + 1 < n_tiles) { issueK(kt + 1); CPA_COMMIT(); CPA_WAIT1(); }
        else                  { CPA_WAIT0(); }
        __syncthreads();

        const int k0 = kt * 64;
        const uint32_t kbase = sb + FKB + (kt & 1) * 49152;

        float sf[8][4] = {};
        const uint32_t qax = (uint32_t)((w * 16 + aro) * 64 + aks * 2);
        #pragma unroll
        for (int s = 0; s < 12; s++) {
            uint32_t ah[4], al[4];
            const uint32_t qoff = (uint32_t)(s >> 1) * 8192 + sw64(qax + (s & 1) * 32);
            ldsm4(ah, sb + FQH + qoff);
            ldsm4(al, sb + FQL + qoff);
            #pragma unroll
            for (int g2 = 0; g2 < 4; g2++) {
                const uint32_t kx = (uint32_t)((g2 * 16 + bro) * 64 + bks * 2);
                const uint32_t koff = (uint32_t)(s >> 1) * 4096 + sw64(kx + (s & 1) * 32);
                uint32_t bh[4], bl[4];
                ldsm4(bh, kbase + koff);
                ldsm4(bl, kbase + 24576 + koff);
                #pragma unroll
                for (int sub = 0; sub < 2; sub++) {
                    const int ni = g2 * 2 + sub;
                    mma_bf16(sf[ni], ah, bh[sub * 2], bh[sub * 2 + 1]);
                    mma_bf16(sf[ni], ah, bl[sub * 2], bl[sub * 2 + 1]);
                    mma_bf16(sf[ni], al, bh[sub * 2], bh[sub * 2 + 1]);
                }
            }
        }

        if (kt >= 2 * qb) {
            const int qr0 = q0 + w * 16 + g;
            const int qr8 = qr0 + 8;
            #pragma unroll
            for (int ni = 0; ni < 8; ni++) {
                const int kp0 = k0 + ni * 8 + 2 * t4;
                const int kp1 = kp0 + 1;
                if (kp0 > qr0) sf[ni][0] = -1e30f;
                if (kp1 > qr0) sf[ni][1] = -1e30f;
                if (kp0 > qr8) sf[ni][2] = -1e30f;
                if (kp1 > qr8) sf[ni][3] = -1e30f;
            }
        }

        float tm0 = -INFINITY, tm1 = -INFINITY;
        #pragma unroll
        for (int ni = 0; ni < 8; ni++) {
            tm0 = fmaxf(tm0, fmaxf(sf[ni][0], sf[ni][1]));
            tm1 = fmaxf(tm1, fmaxf(sf[ni][2], sf[ni][3]));
        }
        #pragma unroll
        for (int o = 1; o < 4; o <<= 1) {
            tm0 = fmaxf(tm0, __shfl_xor_sync(0xffffffffu, tm0, o));
            tm1 = fmaxf(tm1, __shfl_xor_sync(0xffffffffu, tm1, o));
        }
        const float mn0 = fmaxf(m0, tm0), mn1 = fmaxf(m1, tm1);
        const float a0 = __expf(m0 - mn0), a1 = __expf(m1 - mn1);
        float ls0 = 0.f, ls1 = 0.f;
        #pragma unroll
        for (int ni = 0; ni < 8; ni++) {
            sf[ni][0] = __expf(sf[ni][0] - mn0); ls0 += sf[ni][0];
            sf[ni][1] = __expf(sf[ni][1] - mn0); ls0 += sf[ni][1];
            sf[ni][2] = __expf(sf[ni][2] - mn1); ls1 += sf[ni][2];
            sf[ni][3] = __expf(sf[ni][3] - mn1); ls1 += sf[ni][3];
        }
        #pragma unroll
        for (int o = 1; o < 4; o <<= 1) {
            ls0 += __shfl_xor_sync(0xffffffffu, ls0, o);
            ls1 += __shfl_xor_sync(0xffffffffu, ls1, o);
        }
        l0 = l0 * a0 + ls0; l1 = l1 * a1 + ls1;
        m0 = mn0; m1 = mn1;
        #pragma unroll
        for (int ni = 0; ni < 16; ni++) {
            of[ni][0] *= a0; of[ni][1] *= a0;
            of[ni][2] *= a1; of[ni][3] *= a1;
        }

        #pragma unroll
        for (int ks = 0; ks < 4; ks++) {
            uint32_t ph[4], pl[4];
            split2(sf[2*ks][0],   sf[2*ks][1],   ph[0], pl[0]);
            split2(sf[2*ks][2],   sf[2*ks][3],   ph[1], pl[1]);
            split2(sf[2*ks+1][0], sf[2*ks+1][1], ph[2], pl[2]);
            split2(sf[2*ks+1][2], sf[2*ks+1][3], ph[3], pl[3]);
            const int vkey = ks * 16 + (mi & 1) * 8 + (lane & 7);
            const int vdvo = (mi >> 1) * 8;
            #pragma unroll
            for (int g2 = 0; g2 < 8; g2++) {
                const uint32_t vo = swz256((uint32_t)(vkey * 256 + (g2 * 16 + vdvo) * 2));
                uint32_t vh[4], vl[4];
                ldsm4t(vh, sb + FVB + vo);
                ldsm4t(vl, sb + FVB + 16384 + vo);
                #pragma unroll
                for (int sub = 0; sub < 2; sub++) {
                    const int ni = g2 * 2 + sub;
                    mma_bf16(of[ni], ph, vh[sub * 2], vh[sub * 2 + 1]);
                    mma_bf16(of[ni], ph, vl[sub * 2], vl[sub * 2 + 1]);
                    mma_bf16(of[ni], pl, vh[sub * 2], vh[sub * 2 + 1]);
                }
            }
        }
        __syncthreads();
        if (kt + 1 < n_tiles) { issueV(kt + 1); CPA_COMMIT(); }
    }

    const float il0 = 1.f / l0, il1 = 1.f / l1;
    const int rg = row0 + w * 16 + g;
    #pragma unroll
    for (int ni = 0; ni < 16; ni++) {
        const int col = h * DV + ni * 8 + t4 * 2;
        uint32_t hp, lp;
        split2(of[ni][0] * il0, of[ni][1] * il0, hp, lp);
        *reinterpret_cast<uint32_t*>(&atth[(size_t)rg * OW + col]) = hp;
        *reinterpret_cast<uint32_t*>(&attl[(size_t)rg * OW + col]) = lp;
        split2(of[ni][2] * il1, of[ni][3] * il1, hp, lp);
        *reinterpret_cast<uint32_t*>(&atth[(size_t)(rg + 8) * OW + col]) = hp;
        *reinterpret_cast<uint32_t*>(&attl[(size_t)(rg + 8) * OW + col]) = lp;
    }
}

// ---------------- launch ----------------
extern "C" void kernel_launch(void* const* d_in, const int* in_sizes, int n_in,
                              void* d_out, int out_size)
{
    (void)in_sizes; (void)n_in; (void)out_size;
    const float* hidden = (const float*)d_in[0];
    const float* w_qa   = (const float*)d_in[1];
    const float* g_qa   = (const float*)d_in[2];
    const float* w_qb   = (const float*)d_in[3];
    const float* w_kva  = (const float*)d_in[4];
    const float* g_kva  = (const float*)d_in[5];
    const float* w_kvb  = (const float*)d_in[6];
    const float* w_o    = (const float*)d_in[7];
    float* out = (float*)d_out;

    float *qa, *q, *ckv;
    cudaGetSymbolAddress((void**)&qa,   d_qa);
    cudaGetSymbolAddress((void**)&q,    d_q);
    cudaGetSymbolAddress((void**)&ckv,  d_ckv);

    __nv_bfloat16 *hidh,*hidl,*wqah,*wqal,*wkvah,*wkval,*wqbh,*wqbl,*wkvbh,*wkvbl,*woh,*wol;
    __nv_bfloat16 *qanh,*qanl,*ckvnh,*ckvnl,*kvh,*kvl,*kpeh,*kpel,*atth,*attl;
    cudaGetSymbolAddress((void**)&hidh, d_hidh);   cudaGetSymbolAddress((void**)&hidl, d_hidl);
    cudaGetSymbolAddress((void**)&wqah, d_wqah);   cudaGetSymbolAddress((void**)&wqal, d_wqal);
    cudaGetSymbolAddress((void**)&wkvah, d_wkvah); cudaGetSymbolAddress((void**)&wkval, d_wkval);
    cudaGetSymbolAddress((void**)&wqbh, d_wqbh);   cudaGetSymbolAddress((void**)&wqbl, d_wqbl);
    cudaGetSymbolAddress((void**)&wkvbh, d_wkvbh); cudaGetSymbolAddress((void**)&wkvbl, d_wkvbl);
    cudaGetSymbolAddress((void**)&woh, d_woh);     cudaGetSymbolAddress((void**)&wol, d_wol);
    cudaGetSymbolAddress((void**)&qanh, d_qanh);   cudaGetSymbolAddress((void**)&qanl, d_qanl);
    cudaGetSymbolAddress((void**)&ckvnh, d_ckvnh); cudaGetSymbolAddress((void**)&ckvnl, d_ckvnl);
    cudaGetSymbolAddress((void**)&kvh, d_kvh);     cudaGetSymbolAddress((void**)&kvl, d_kvl);
    cudaGetSymbolAddress((void**)&kpeh, d_kpeh);   cudaGetSymbolAddress((void**)&kpel, d_kpel);
    cudaGetSymbolAddress((void**)&atth, d_atth);   cudaGetSymbolAddress((void**)&attl, d_attl);

    cudaFuncSetAttribute(gemm_bf, cudaFuncAttributeMaxDynamicSharedMemorySize, GEMM_SMEM);
    cudaFuncSetAttribute(flash_tc, cudaFuncAttributeMaxDynamicSharedMemorySize, FLASH_SMEM);

    const dim3 blk(256);

    // launches 1-3: splits needed by the qa GEMM
    split_kernel<<<MTOT, 256>>>(hidden, HDIM, HDIM, hidh, hidl);          // 1
    split_kernel<<<QLORA, 256>>>(w_qa, HDIM, HDIM, wqah, wqal);           // 2
    split_kernel<<<CKVW, 256>>>(w_kva, HDIM, HDIM, wkvah, wkval);         // 3
    // launch 4 (ncu captures this one): the big qa GEMM
    gemm_bf<<<dim3(QLORA/128, MTOT/128), blk, GEMM_SMEM>>>(hidh, hidl, wqah, wqal, qa, nullptr, nullptr, MTOT, QLORA, HDIM);
    // ckv = hidden @ w_kva^T  [4096,576]
    gemm_bf<<<dim3((CKVW+127)/128, MTOT/128), blk, GEMM_SMEM>>>(hidh, hidl, wkvah, wkval, ckv, nullptr, nullptr, MTOT, CKVW, HDIM);
    // remaining weight splits
    split_kernel<<<QW, 256>>>(w_qb, QLORA, QLORA, wqbh, wqbl);
    split_kernel<<<KVW, 256>>>(w_kvb, KVLORA, KVLORA, wkvbh, wkvbl);
    // fused rmsnorm + split
    rmsnorm_split<<<MTOT, 256>>>(qa, g_qa, QLORA, QLORA, qanh, qanl);
    rmsnorm_split<<<MTOT, 256>>>(ckv, g_kva, KVLORA, CKVW, ckvnh, ckvnl);
    // q = rms(q_a) @ w_qb^T   [4096,3072]
    gemm_bf<<<dim3(QW/128, MTOT/128), blk, GEMM_SMEM>>>(qanh, qanl, wqbh, wqbl, q, nullptr, nullptr, MTOT, QW, QLORA);
    // kv = rms(ckv) @ w_kvb^T [4096,4096] (bf16 hi/lo out)
    gemm_bf<<<dim3(KVW/128, MTOT/128), blk, GEMM_SMEM>>>(ckvnh, ckvnl, wkvbh, wkvbl, nullptr, kvh, kvl, MTOT, KVW, KVLORA);
    // rope
    rope_q_kernel<<<MTOT * NH, 32>>>(q);
    rope_k_split<<<MTOT, 32>>>(ckv, kpeh, kpel);
    // flash attention
    flash_tc<<<dim3(SS/128, NH, BB), 256, FLASH_SMEM>>>(q, kvh, kvl, kpeh, kpel, atth, attl);
    // out = attn @ w_o^T      [4096,2048]
    split_kernel<<<HDIM, 256>>>(w_o, OW, OW, woh, wol);
    gemm_bf<<<dim3(HDIM/128, MTOT/128), blk, GEMM_SMEM>>>(atth, attl, woh, wol, out, nullptr, nullptr, MTOT, HDIM, OW);
}

// round 9
// speedup vs baseline: 4.4962x; 1.0698x over previous
#include <cuda_runtime.h>
#include <cuda_bf16.h>
#include <math.h>
#include <stdint.h>

// ---------------- problem constants ----------------
#define HDIM   2048
#define NH     16
#define QLORA  1536
#define KVLORA 512
#define DN     128
#define DR     64
#define DV     128
#define QD     192
#define BB     2
#define SS     2048
#define MTOT   (BB*SS)      // 4096
#define CKVW   (KVLORA+DR)  // 576
#define KVW    (NH*(DN+DV)) // 4096
#define QW     (NH*QD)      // 3072
#define OW     (NH*DV)      // 2048

// ---------------- fp32 scratch ----------------
__device__ float d_qa  [(size_t)MTOT*QLORA];
__device__ float d_q   [(size_t)MTOT*QW];
__device__ float d_ckv [(size_t)MTOT*CKVW];

// ---------------- bf16 hi/lo scratch ----------------
__device__ __nv_bfloat16 d_hidh [(size_t)MTOT*HDIM],   d_hidl [(size_t)MTOT*HDIM];
__device__ __nv_bfloat16 d_wqah [(size_t)QLORA*HDIM],  d_wqal [(size_t)QLORA*HDIM];
__device__ __nv_bfloat16 d_wkvah[(size_t)CKVW*HDIM],   d_wkval[(size_t)CKVW*HDIM];
__device__ __nv_bfloat16 d_wqbh [(size_t)QW*QLORA],    d_wqbl [(size_t)QW*QLORA];
__device__ __nv_bfloat16 d_wkvbh[(size_t)KVW*KVLORA],  d_wkvbl[(size_t)KVW*KVLORA];
__device__ __nv_bfloat16 d_woh  [(size_t)HDIM*OW],     d_wol  [(size_t)HDIM*OW];
__device__ __nv_bfloat16 d_qanh [(size_t)MTOT*QLORA],  d_qanl [(size_t)MTOT*QLORA];
__device__ __nv_bfloat16 d_ckvnh[(size_t)MTOT*KVLORA], d_ckvnl[(size_t)MTOT*KVLORA];
__device__ __nv_bfloat16 d_kvh  [(size_t)MTOT*KVW],    d_kvl  [(size_t)MTOT*KVW];
__device__ __nv_bfloat16 d_kpeh [(size_t)MTOT*DR],     d_kpel [(size_t)MTOT*DR];
__device__ __nv_bfloat16 d_atth [(size_t)MTOT*OW],     d_attl [(size_t)MTOT*OW];

// ---------------- helpers ----------------
__device__ __forceinline__ uint32_t smem_u32(const void* p) {
    uint32_t a;
    asm("{ .reg .u64 t; cvta.to.shared.u64 t, %1; cvt.u32.u64 %0, t; }" : "=r"(a) : "l"(p));
    return a;
}

__device__ __forceinline__ void ldsm4(uint32_t r[4], uint32_t addr) {
    asm volatile("ldmatrix.sync.aligned.m8n8.x4.shared.b16 {%0,%1,%2,%3}, [%4];"
                 : "=r"(r[0]), "=r"(r[1]), "=r"(r[2]), "=r"(r[3]) : "r"(addr));
}

__device__ __forceinline__ void ldsm4t(uint32_t r[4], uint32_t addr) {
    asm volatile("ldmatrix.sync.aligned.m8n8.x4.trans.shared.b16 {%0,%1,%2,%3}, [%4];"
                 : "=r"(r[0]), "=r"(r[1]), "=r"(r[2]), "=r"(r[3]) : "r"(addr));
}

__device__ __forceinline__ void mma_bf16(float c[4], const uint32_t a[4],
                                         uint32_t b0, uint32_t b1) {
    asm volatile(
        "mma.sync.aligned.m16n8k16.row.col.f32.bf16.bf16.f32 "
        "{%0,%1,%2,%3}, {%4,%5,%6,%7}, {%8,%9}, {%0,%1,%2,%3};"
        : "+f"(c[0]), "+f"(c[1]), "+f"(c[2]), "+f"(c[3])
        : "r"(a[0]), "r"(a[1]), "r"(a[2]), "r"(a[3]), "r"(b0), "r"(b1));
}

__device__ __forceinline__ void split2(float x, float y, uint32_t& hp, uint32_t& lp) {
    __nv_bfloat16 hx = __float2bfloat16(x), hy = __float2bfloat16(y);
    __nv_bfloat16 lx = __float2bfloat16(x - __bfloat162float(hx));
    __nv_bfloat16 ly = __float2bfloat16(y - __bfloat162float(hy));
    hp = ((uint32_t)__bfloat16_as_ushort(hy) << 16) | __bfloat16_as_ushort(hx);
    lp = ((uint32_t)__bfloat16_as_ushort(ly) << 16) | __bfloat16_as_ushort(lx);
}

__device__ __forceinline__ uint32_t sw64(uint32_t o)   { return o ^ ((o >> 3) & 0x30); }
__device__ __forceinline__ uint32_t swz256(uint32_t o) { return o ^ (((o >> 8) & 7) << 4); }

__device__ __forceinline__ void cpa16(uint32_t dst, const void* src) {
    asm volatile("cp.async.cg.shared.global [%0], [%1], 16;" :: "r"(dst), "l"(src));
}
__device__ __forceinline__ void cpa16p(uint32_t dst, const void* src, bool valid) {
    int sz = valid ? 16 : 0;
    asm volatile("cp.async.cg.shared.global [%0], [%1], 16, %2;" :: "r"(dst), "l"(src), "r"(sz));
}
#define CPA_COMMIT() asm volatile("cp.async.commit_group;" ::: "memory")
#define CPA_WAIT1()  asm volatile("cp.async.wait_group 1;" ::: "memory")
#define CPA_WAIT0()  asm volatile("cp.async.wait_group 0;" ::: "memory")

// ---------------- fp32 -> bf16 hi/lo split ----------------
__global__ void split_kernel(const float* __restrict__ src, int lda, int cols,
                             __nv_bfloat16* __restrict__ h, __nv_bfloat16* __restrict__ l)
{
    const int row = blockIdx.x;
    const float* p = src + (size_t)row * lda;
    uint32_t* hp = reinterpret_cast<uint32_t*>(h + (size_t)row * cols);
    uint32_t* lp = reinterpret_cast<uint32_t*>(l + (size_t)row * cols);
    for (int i = threadIdx.x * 4; i < cols; i += blockDim.x * 4) {
        float4 v = *reinterpret_cast<const float4*>(p + i);
        uint32_t h0, l0, h1, l1;
        split2(v.x, v.y, h0, l0);
        split2(v.z, v.w, h1, l1);
        hp[i/2] = h0; hp[i/2+1] = h1;
        lp[i/2] = l0; lp[i/2+1] = l1;
    }
}

// ---------------- fused RMSNorm + split ----------------
__global__ void rmsnorm_split(const float* __restrict__ x, const float* __restrict__ g,
                              int D, int lda,
                              __nv_bfloat16* __restrict__ h, __nv_bfloat16* __restrict__ l)
{
    const int row = blockIdx.x;
    const float* p = x + (size_t)row * lda;
    float ss = 0.f;
    for (int i = threadIdx.x; i < D; i += blockDim.x) { float v = p[i]; ss += v * v; }
    #pragma unroll
    for (int o = 16; o > 0; o >>= 1) ss += __shfl_xor_sync(0xffffffffu, ss, o);
    __shared__ float sred[8];
    if ((threadIdx.x & 31) == 0) sred[threadIdx.x >> 5] = ss;
    __syncthreads();
    if (threadIdx.x < 8) {
        float v = sred[threadIdx.x];
        #pragma unroll
        for (int o = 4; o > 0; o >>= 1) v += __shfl_xor_sync(0xffu, v, o);
        if (threadIdx.x == 0) sred[0] = v;
    }
    __syncthreads();
    const float inv = rsqrtf(sred[0] / (float)D + 1e-6f);
    uint32_t* hp = reinterpret_cast<uint32_t*>(h + (size_t)row * D);
    uint32_t* lp = reinterpret_cast<uint32_t*>(l + (size_t)row * D);
    for (int i = threadIdx.x * 4; i < D; i += blockDim.x * 4) {
        float4 v = *reinterpret_cast<const float4*>(p + i);
        v.x *= inv * g[i]; v.y *= inv * g[i+1]; v.z *= inv * g[i+2]; v.w *= inv * g[i+3];
        uint32_t h0, l0, h1, l1;
        split2(v.x, v.y, h0, l0);
        split2(v.z, v.w, h1, l1);
        hp[i/2] = h0; hp[i/2+1] = h1;
        lp[i/2] = l0; lp[i/2+1] = l1;
    }
}

// ---------------- bf16x3 GEMM, 3-stage cp.async pipeline, 2 CTAs/SM ----------------
#define GS_AH 0
#define GS_AL 8192
#define GS_BH 16384
#define GS_BL 24576
#define GS_STAGE 32768
#define GEMM_SMEM (3*GS_STAGE)

__global__ __launch_bounds__(256, 2) void gemm_bf(
    const __nv_bfloat16* __restrict__ Ah, const __nv_bfloat16* __restrict__ Al,
    const __nv_bfloat16* __restrict__ Bh, const __nv_bfloat16* __restrict__ Bl,
    float* __restrict__ C, __nv_bfloat16* __restrict__ Ch, __nv_bfloat16* __restrict__ Cl,
    int M, int N, int K)
{
    extern __shared__ char sm[];
    const uint32_t sb = smem_u32(sm);

    const int tid = threadIdx.x;
    const int bm = blockIdx.y * 128;
    const int bn = blockIdx.x * 128;
    const int NC = K >> 5;

    const int w = tid >> 5, lane = tid & 31;
    const int wm = (w & 1) * 64;
    const int wn = (w >> 1) * 32;
    const int mi  = lane >> 3;
    const int aro = (lane & 7) + (mi & 1) * 8;
    const int aks = (mi >> 1) * 8;
    const int bro = (lane & 7) + ((mi >> 1) & 1) * 8;
    const int bks = (mi & 1) * 8;

    float acc[4][4][4] = {};

    const int lr0 = tid >> 2;
    const int lc0 = tid & 3;
    const int lr1 = (256 + tid) >> 2;
    const int lc1 = (256 + tid) & 3;
    const uint32_t do0 = sw64((uint32_t)(lr0 * 64 + lc0 * 16));
    const uint32_t do1 = sw64((uint32_t)(lr1 * 64 + lc1 * 16));
    const bool bok0 = (bn + lr0) < N;
    const bool bok1 = (bn + lr1) < N;

    auto issue = [&](int c) {
        const int k0 = c << 5;
        const uint32_t st = sb + (uint32_t)(c % 3) * GS_STAGE;
        {
            const size_t go = (size_t)(bm + lr0) * K + k0 + lc0 * 8;
            cpa16(st + GS_AH + do0, Ah + go);
            cpa16(st + GS_AL + do0, Al + go);
            const size_t gb = (size_t)(bn + lr0) * K + k0 + lc0 * 8;
            cpa16p(st + GS_BH + do0, Bh + gb, bok0);
            cpa16p(st + GS_BL + do0, Bl + gb, bok0);
        }
        {
            const size_t go = (size_t)(bm + lr1) * K + k0 + lc1 * 8;
            cpa16(st + GS_AH + do1, Ah + go);
            cpa16(st + GS_AL + do1, Al + go);
            const size_t gb = (size_t)(bn + lr1) * K + k0 + lc1 * 8;
            cpa16p(st + GS_BH + do1, Bh + gb, bok1);
            cpa16p(st + GS_BL + do1, Bl + gb, bok1);
        }
        CPA_COMMIT();
    };

    auto compute = [&](int c) {
        const uint32_t st = sb + (uint32_t)(c % 3) * GS_STAGE;
        #pragma unroll
        for (int k16 = 0; k16 < 32; k16 += 16) {
            uint32_t A_h[4][4], B_h[2][4];
            #pragma unroll
            for (int f = 0; f < 4; f++) {
                const uint32_t x = (uint32_t)((wm + f * 16 + aro) * 64 + (k16 + aks) * 2);
                ldsm4(A_h[f], st + GS_AH + sw64(x));
            }
            #pragma unroll
            for (int g2 = 0; g2 < 2; g2++) {
                const uint32_t x = (uint32_t)((wn + g2 * 16 + bro) * 64 + (k16 + bks) * 2);
                ldsm4(B_h[g2], st + GS_BH + sw64(x));
            }
            #pragma unroll
            for (int f = 0; f < 4; f++)
                #pragma unroll
                for (int ni = 0; ni < 4; ni++)
                    mma_bf16(acc[f][ni], A_h[f], B_h[ni >> 1][(ni & 1) * 2],
                             B_h[ni >> 1][(ni & 1) * 2 + 1]);
            {
                uint32_t B_l[2][4];
                #pragma unroll
                for (int g2 = 0; g2 < 2; g2++) {
                    const uint32_t x = (uint32_t)((wn + g2 * 16 + bro) * 64 + (k16 + bks) * 2);
                    ldsm4(B_l[g2], st + GS_BL + sw64(x));
                }
                #pragma unroll
                for (int f = 0; f < 4; f++)
                    #pragma unroll
                    for (int ni = 0; ni < 4; ni++)
                        mma_bf16(acc[f][ni], A_h[f], B_l[ni >> 1][(ni & 1) * 2],
                                 B_l[ni >> 1][(ni & 1) * 2 + 1]);
            }
            {
                uint32_t A_l[4][4];
                #pragma unroll
                for (int f = 0; f < 4; f++) {
                    const uint32_t x = (uint32_t)((wm + f * 16 + aro) * 64 + (k16 + aks) * 2);
                    ldsm4(A_l[f], st + GS_AL + sw64(x));
                }
                #pragma unroll
                for (int f = 0; f < 4; f++)
                    #pragma unroll
                    for (int ni = 0; ni < 4; ni++)
                        mma_bf16(acc[f][ni], A_l[f], B_h[ni >> 1][(ni & 1) * 2],
                                 B_h[ni >> 1][(ni & 1) * 2 + 1]);
            }
        }
    };

    // 3-stage pipeline: 2 groups in flight, one barrier per chunk
    issue(0);
    issue(1);
    for (int c = 0; c < NC; c++) {
        if (c + 1 < NC) CPA_WAIT1(); else CPA_WAIT0();
        __syncthreads();
        if (c + 2 < NC) issue(c + 2);
        compute(c);
        __syncthreads();
    }

    const int gq = lane >> 2, t4 = lane & 3;
    if (C) {
        #pragma unroll
        for (int f = 0; f < 4; f++)
            #pragma unroll
            for (int ni = 0; ni < 4; ni++) {
                const int col = bn + wn + ni * 8 + t4 * 2;
                if (col < N) {
                    const int r = bm + wm + f * 16 + gq;
                    *reinterpret_cast<float2*>(&C[(size_t)r * N + col]) =
                        make_float2(acc[f][ni][0], acc[f][ni][1]);
                    *reinterpret_cast<float2*>(&C[(size_t)(r + 8) * N + col]) =
                        make_float2(acc[f][ni][2], acc[f][ni][3]);
                }
            }
    } else {
        #pragma unroll
        for (int f = 0; f < 4; f++)
            #pragma unroll
            for (int ni = 0; ni < 4; ni++) {
                const int col = bn + wn + ni * 8 + t4 * 2;
                if (col < N) {
                    const int r = bm + wm + f * 16 + gq;
                    uint32_t hp, lp;
                    split2(acc[f][ni][0], acc[f][ni][1], hp, lp);
                    *reinterpret_cast<uint32_t*>(&Ch[(size_t)r * N + col]) = hp;
                    *reinterpret_cast<uint32_t*>(&Cl[(size_t)r * N + col]) = lp;
                    split2(acc[f][ni][2], acc[f][ni][3], hp, lp);
                    *reinterpret_cast<uint32_t*>(&Ch[(size_t)(r + 8) * N + col]) = hp;
                    *reinterpret_cast<uint32_t*>(&Cl[(size_t)(r + 8) * N + col]) = lp;
                }
            }
    }
}

// ---------------- RoPE ----------------
__global__ void rope_q_kernel(float* __restrict__ q)
{
    const int idx = blockIdx.x;
    const int row = idx / NH, h = idx % NH;
    const int t = row % SS;
    const int j = threadIdx.x;
    const double inv = exp(-log(10000.0) * (2.0 * j) / (double)DR);
    const double ang = (double)t * inv;
    const float c = (float)cos(ang), s = (float)sin(ang);
    float* p = q + (size_t)row * QW + h * QD + DN;
    const float x0 = p[j], x1 = p[j + 32];
    p[j]      = x0 * c - x1 * s;
    p[j + 32] = x1 * c + x0 * s;
}

__global__ void rope_k_split(const float* __restrict__ ckv,
                             __nv_bfloat16* __restrict__ kpeh, __nv_bfloat16* __restrict__ kpel)
{
    const int row = blockIdx.x;
    const int t = row % SS;
    const int j = threadIdx.x;
    const double inv = exp(-log(10000.0) * (2.0 * j) / (double)DR);
    const double ang = (double)t * inv;
    const float c = (float)cos(ang), s = (float)sin(ang);
    const float* p = ckv + (size_t)row * CKVW + KVLORA;
    const float x0 = p[j], x1 = p[j + 32];
    const float y0 = x0 * c - x1 * s;
    const float y1 = x1 * c + x0 * s;
    __nv_bfloat16 h0 = __float2bfloat16(y0);
    __nv_bfloat16 h1 = __float2bfloat16(y1);
    kpeh[(size_t)row * DR + j]      = h0;
    kpeh[(size_t)row * DR + j + 32] = h1;
    kpel[(size_t)row * DR + j]      = __float2bfloat16(y0 - __bfloat162float(h0));
    kpel[(size_t)row * DR + j + 32] = __float2bfloat16(y1 - __bfloat162float(h1));
}

// ---------------- tensor-core causal flash attention ----------------
#define FQH 0                 // 6*8192 = 49152
#define FQL 49152
#define FKB 98304             // stage s at FKB + s*49152; KH +0, KL +24576
#define FVB 196608            // VH +0, VL +16384
#define FLASH_SMEM 229376

__global__ __launch_bounds__(256) void flash_tc(
    const float* __restrict__ q,
    const __nv_bfloat16* __restrict__ kvh, const __nv_bfloat16* __restrict__ kvl,
    const __nv_bfloat16* __restrict__ kpeh, const __nv_bfloat16* __restrict__ kpel,
    __nv_bfloat16* __restrict__ atth, __nv_bfloat16* __restrict__ attl)
{
    extern __shared__ char sm[];
    const uint32_t sb = smem_u32(sm);

    const int qb = blockIdx.x, h = blockIdx.y, b = blockIdx.z;
    const int tid = threadIdx.x;
    const int w = tid >> 5, lane = tid & 31;
    const int g = lane >> 2, t4 = lane & 3;
    const int mi  = lane >> 3;
    const int aro = (lane & 7) + (mi & 1) * 8;
    const int aks = (mi >> 1) * 8;
    const int bro = (lane & 7) + ((mi >> 1) & 1) * 8;
    const int bks = (mi & 1) * 8;
    const int hoff = h * (DN + DV);

    const int q0 = qb * 128;
    const int row0 = b * SS + q0;
    const int brow = b * SS;
    const float scale = rsqrtf((float)QD);
    const int n_tiles = 2 * qb + 2;

    auto issueK = [&](int kt) {
        const uint32_t base = sb + FKB + (kt & 1) * 49152;
        const int krow = brow + kt * 64;
        #pragma unroll
        for (int t = 0; t < 12; t++) {
            const int idx = t * 256 + tid;
            const int half = idx >= 1536;
            const int cidx = half ? idx - 1536 : idx;
            const int key = cidx / 24;
            const int c = cidx % 24;
            const int d = (c < 16) ? c * 8 : 128 + (c - 16) * 8;
            const uint32_t dst = base + (half ? 24576u : 0u) + (uint32_t)(d >> 5) * 4096
                               + sw64((uint32_t)(key * 64 + (d & 31) * 2));
            const __nv_bfloat16* src;
            if (c < 16) src = (half ? kvl : kvh) + (size_t)(krow + key) * KVW + hoff + d;
            else        src = (half ? kpel : kpeh) + (size_t)(krow + key) * DR + (d - 128);
            cpa16(dst, src);
        }
    };
    auto issueV = [&](int kt) {
        const int krow = brow + kt * 64;
        #pragma unroll
        for (int t = 0; t < 8; t++) {
            const int idx = t * 256 + tid;
            const int half = idx >= 1024;
            const int cidx = idx & 1023;
            const int key = cidx >> 4;
            const int d = (cidx & 15) * 8;
            const uint32_t dst = sb + FVB + (half ? 16384u : 0u)
                               + swz256((uint32_t)(key * 256 + d * 2));
            const __nv_bfloat16* src = (half ? kvl : kvh) + (size_t)(krow + key) * KVW + hoff + DN + d;
            cpa16(dst, src);
        }
    };

    #pragma unroll
    for (int t = 0; t < 24; t++) {
        const int idx = t * 256 + tid;
        const int r = idx / 48;
        const int c4 = (idx % 48) * 4;
        float4 v = *reinterpret_cast<const float4*>(&q[(size_t)(row0 + r) * QW + h * QD + c4]);
        v.x *= scale; v.y *= scale; v.z *= scale; v.w *= scale;
        const uint32_t off = (uint32_t)(c4 >> 5) * 8192 + sw64((uint32_t)(r * 64 + (c4 & 31) * 2));
        uint32_t h0, l0, h1, l1;
        split2(v.x, v.y, h0, l0);
        split2(v.z, v.w, h1, l1);
        *reinterpret_cast<uint2*>(sm + FQH + off) = make_uint2(h0, h1);
        *reinterpret_cast<uint2*>(sm + FQL + off) = make_uint2(l0, l1);
    }

    issueK(0);
    issueV(0);
    CPA_COMMIT();

    float of[16][4] = {};
    float m0 = -INFINITY, m1 = -INFINITY, l0 = 0.f, l1 = 0.f;

    for (int kt = 0; kt < n_tiles; kt++) {
        if (kt + 1 < n_tiles) { issueK(kt + 1); CPA_COMMIT(); CPA_WAIT1(); }
        else                  { CPA_WAIT0(); }
        __syncthreads();

        const int k0 = kt * 64;
        const uint32_t kbase = sb + FKB + (kt & 1) * 49152;

        float sf[8][4] = {};
        const uint32_t qax = (uint32_t)((w * 16 + aro) * 64 + aks * 2);
        #pragma unroll
        for (int s = 0; s < 12; s++) {
            uint32_t ah[4], al[4];
            const uint32_t qoff = (uint32_t)(s >> 1) * 8192 + sw64(qax + (s & 1) * 32);
            ldsm4(ah, sb + FQH + qoff);
            ldsm4(al, sb + FQL + qoff);
            #pragma unroll
            for (int g2 = 0; g2 < 4; g2++) {
                const uint32_t kx = (uint32_t)((g2 * 16 + bro) * 64 + bks * 2);
                const uint32_t koff = (uint32_t)(s >> 1) * 4096 + sw64(kx + (s & 1) * 32);
                uint32_t bh[4], bl[4];
                ldsm4(bh, kbase + koff);
                ldsm4(bl, kbase + 24576 + koff);
                #pragma unroll
                for (int sub = 0; sub < 2; sub++) {
                    const int ni = g2 * 2 + sub;
                    mma_bf16(sf[ni], ah, bh[sub * 2], bh[sub * 2 + 1]);
                    mma_bf16(sf[ni], ah, bl[sub * 2], bl[sub * 2 + 1]);
                    mma_bf16(sf[ni], al, bh[sub * 2], bh[sub * 2 + 1]);
                }
            }
        }

        if (kt >= 2 * qb) {
            const int qr0 = q0 + w * 16 + g;
            const int qr8 = qr0 + 8;
            #pragma unroll
            for (int ni = 0; ni < 8; ni++) {
                const int kp0 = k0 + ni * 8 + 2 * t4;
                const int kp1 = kp0 + 1;
                if (kp0 > qr0) sf[ni][0] = -1e30f;
                if (kp1 > qr0) sf[ni][1] = -1e30f;
                if (kp0 > qr8) sf[ni][2] = -1e30f;
                if (kp1 > qr8) sf[ni][3] = -1e30f;
            }
        }

        float tm0 = -INFINITY, tm1 = -INFINITY;
        #pragma unroll
        for (int ni = 0; ni < 8; ni++) {
            tm0 = fmaxf(tm0, fmaxf(sf[ni][0], sf[ni][1]));
            tm1 = fmaxf(tm1, fmaxf(sf[ni][2], sf[ni][3]));
        }
        #pragma unroll
        for (int o = 1; o < 4; o <<= 1) {
            tm0 = fmaxf(tm0, __shfl_xor_sync(0xffffffffu, tm0, o));
            tm1 = fmaxf(tm1, __shfl_xor_sync(0xffffffffu, tm1, o));
        }
        const float mn0 = fmaxf(m0, tm0), mn1 = fmaxf(m1, tm1);
        const float a0 = __expf(m0 - mn0), a1 = __expf(m1 - mn1);
        float ls0 = 0.f, ls1 = 0.f;
        #pragma unroll
        for (int ni = 0; ni < 8; ni++) {
            sf[ni][0] = __expf(sf[ni][0] - mn0); ls0 += sf[ni][0];
            sf[ni][1] = __expf(sf[ni][1] - mn0); ls0 += sf[ni][1];
            sf[ni][2] = __expf(sf[ni][2] - mn1); ls1 += sf[ni][2];
            sf[ni][3] = __expf(sf[ni][3] - mn1); ls1 += sf[ni][3];
        }
        #pragma unroll
        for (int o = 1; o < 4; o <<= 1) {
            ls0 += __shfl_xor_sync(0xffffffffu, ls0, o);
            ls1 += __shfl_xor_sync(0xffffffffu, ls1, o);
        }
        l0 = l0 * a0 + ls0; l1 = l1 * a1 + ls1;
        m0 = mn0; m1 = mn1;
        #pragma unroll
        for (int ni = 0; ni < 16; ni++) {
            of[ni][0] *= a0; of[ni][1] *= a0;
            of[ni][2] *= a1; of[ni][3] *= a1;
        }

        #pragma unroll
        for (int ks = 0; ks < 4; ks++) {
            uint32_t ph[4], pl[4];
            split2(sf[2*ks][0],   sf[2*ks][1],   ph[0], pl[0]);
            split2(sf[2*ks][2],   sf[2*ks][3],   ph[1], pl[1]);
            split2(sf[2*ks+1][0], sf[2*ks+1][1], ph[2], pl[2]);
            split2(sf[2*ks+1][2], sf[2*ks+1][3], ph[3], pl[3]);
            const int vkey = ks * 16 + (mi & 1) * 8 + (lane & 7);
            const int vdvo = (mi >> 1) * 8;
            #pragma unroll
            for (int g2 = 0; g2 < 8; g2++) {
                const uint32_t vo = swz256((uint32_t)(vkey * 256 + (g2 * 16 + vdvo) * 2));
                uint32_t vh[4], vl[4];
                ldsm4t(vh, sb + FVB + vo);
                ldsm4t(vl, sb + FVB + 16384 + vo);
                #pragma unroll
                for (int sub = 0; sub < 2; sub++) {
                    const int ni = g2 * 2 + sub;
                    mma_bf16(of[ni], ph, vh[sub * 2], vh[sub * 2 + 1]);
                    mma_bf16(of[ni], ph, vl[sub * 2], vl[sub * 2 + 1]);
                    mma_bf16(of[ni], pl, vh[sub * 2], vh[sub * 2 + 1]);
                }
            }
        }
        __syncthreads();
        if (kt + 1 < n_tiles) { issueV(kt + 1); CPA_COMMIT(); }
    }

    const float il0 = 1.f / l0, il1 = 1.f / l1;
    const int rg = row0 + w * 16 + g;
    #pragma unroll
    for (int ni = 0; ni < 16; ni++) {
        const int col = h * DV + ni * 8 + t4 * 2;
        uint32_t hp, lp;
        split2(of[ni][0] * il0, of[ni][1] * il0, hp, lp);
        *reinterpret_cast<uint32_t*>(&atth[(size_t)rg * OW + col]) = hp;
        *reinterpret_cast<uint32_t*>(&attl[(size_t)rg * OW + col]) = lp;
        split2(of[ni][2] * il1, of[ni][3] * il1, hp, lp);
        *reinterpret_cast<uint32_t*>(&atth[(size_t)(rg + 8) * OW + col]) = hp;
        *reinterpret_cast<uint32_t*>(&attl[(size_t)(rg + 8) * OW + col]) = lp;
    }
}

// ---------------- launch ----------------
extern "C" void kernel_launch(void* const* d_in, const int* in_sizes, int n_in,
                              void* d_out, int out_size)
{
    (void)in_sizes; (void)n_in; (void)out_size;
    const float* hidden = (const float*)d_in[0];
    const float* w_qa   = (const float*)d_in[1];
    const float* g_qa   = (const float*)d_in[2];
    const float* w_qb   = (const float*)d_in[3];
    const float* w_kva  = (const float*)d_in[4];
    const float* g_kva  = (const float*)d_in[5];
    const float* w_kvb  = (const float*)d_in[6];
    const float* w_o    = (const float*)d_in[7];
    float* out = (float*)d_out;

    float *qa, *q, *ckv;
    cudaGetSymbolAddress((void**)&qa,   d_qa);
    cudaGetSymbolAddress((void**)&q,    d_q);
    cudaGetSymbolAddress((void**)&ckv,  d_ckv);

    __nv_bfloat16 *hidh,*hidl,*wqah,*wqal,*wkvah,*wkval,*wqbh,*wqbl,*wkvbh,*wkvbl,*woh,*wol;
    __nv_bfloat16 *qanh,*qanl,*ckvnh,*ckvnl,*kvh,*kvl,*kpeh,*kpel,*atth,*attl;
    cudaGetSymbolAddress((void**)&hidh, d_hidh);   cudaGetSymbolAddress((void**)&hidl, d_hidl);
    cudaGetSymbolAddress((void**)&wqah, d_wqah);   cudaGetSymbolAddress((void**)&wqal, d_wqal);
    cudaGetSymbolAddress((void**)&wkvah, d_wkvah); cudaGetSymbolAddress((void**)&wkval, d_wkval);
    cudaGetSymbolAddress((void**)&wqbh, d_wqbh);   cudaGetSymbolAddress((void**)&wqbl, d_wqbl);
    cudaGetSymbolAddress((void**)&wkvbh, d_wkvbh); cudaGetSymbolAddress((void**)&wkvbl, d_wkvbl);
    cudaGetSymbolAddress((void**)&woh, d_woh);     cudaGetSymbolAddress((void**)&wol, d_wol);
    cudaGetSymbolAddress((void**)&qanh, d_qanh);   cudaGetSymbolAddress((void**)&qanl, d_qanl);
    cudaGetSymbolAddress((void**)&ckvnh, d_ckvnh); cudaGetSymbolAddress((void**)&ckvnl, d_ckvnl);
    cudaGetSymbolAddress((void**)&kvh, d_kvh);     cudaGetSymbolAddress((void**)&kvl, d_kvl);
    cudaGetSymbolAddress((void**)&kpeh, d_kpeh);   cudaGetSymbolAddress((void**)&kpel, d_kpel);
    cudaGetSymbolAddress((void**)&atth, d_atth);   cudaGetSymbolAddress((void**)&attl, d_attl);

    cudaFuncSetAttribute(gemm_bf, cudaFuncAttributeMaxDynamicSharedMemorySize, GEMM_SMEM);
    cudaFuncSetAttribute(flash_tc, cudaFuncAttributeMaxDynamicSharedMemorySize, FLASH_SMEM);

    const dim3 blk(256);

    // launches 1-3: splits needed by the qa GEMM
    split_kernel<<<MTOT, 256>>>(hidden, HDIM, HDIM, hidh, hidl);          // 1
    split_kernel<<<QLORA, 256>>>(w_qa, HDIM, HDIM, wqah, wqal);           // 2
    split_kernel<<<CKVW, 256>>>(w_kva, HDIM, HDIM, wkvah, wkval);         // 3
    // launch 4 (ncu captures this one): the big qa GEMM
    gemm_bf<<<dim3(QLORA/128, MTOT/128), blk, GEMM_SMEM>>>(hidh, hidl, wqah, wqal, qa, nullptr, nullptr, MTOT, QLORA, HDIM);
    // ckv = hidden @ w_kva^T  [4096,576]
    gemm_bf<<<dim3((CKVW+127)/128, MTOT/128), blk, GEMM_SMEM>>>(hidh, hidl, wkvah, wkval, ckv, nullptr, nullptr, MTOT, CKVW, HDIM);
    // remaining weight splits
    split_kernel<<<QW, 256>>>(w_qb, QLORA, QLORA, wqbh, wqbl);
    split_kernel<<<KVW, 256>>>(w_kvb, KVLORA, KVLORA, wkvbh, wkvbl);
    // fused rmsnorm + split
    rmsnorm_split<<<MTOT, 256>>>(qa, g_qa, QLORA, QLORA, qanh, qanl);
    rmsnorm_split<<<MTOT, 256>>>(ckv, g_kva, KVLORA, CKVW, ckvnh, ckvnl);
    // q = rms(q_a) @ w_qb^T   [4096,3072]
    gemm_bf<<<dim3(QW/128, MTOT/128), blk, GEMM_SMEM>>>(qanh, qanl, wqbh, wqbl, q, nullptr, nullptr, MTOT, QW, QLORA);
    // kv = rms(ckv) @ w_kvb^T [4096,4096] (bf16 hi/lo out)
    gemm_bf<<<dim3(KVW/128, MTOT/128), blk, GEMM_SMEM>>>(ckvnh, ckvnl, wkvbh, wkvbl, nullptr, kvh, kvl, MTOT, KVW, KVLORA);
    // rope
    rope_q_kernel<<<MTOT * NH, 32>>>(q);
    rope_k_split<<<MTOT, 32>>>(ckv, kpeh, kpel);
    // flash attention
    flash_tc<<<dim3(SS/128, NH, BB), 256, FLASH_SMEM>>>(q, kvh, kvl, kpeh, kpel, atth, attl);
    // out = attn @ w_o^T      [4096,2048]
    split_kernel<<<HDIM, 256>>>(w_o, OW, OW, woh, wol);
    gemm_bf<<<dim3(HDIM/128, MTOT/128), blk, GEMM_SMEM>>>(atth, attl, woh, wol, out, nullptr, nullptr, MTOT, HDIM, OW);
}

// round 10
// speedup vs baseline: 4.7143x; 1.0485x over previous
#include <cuda_runtime.h>
#include <cuda_bf16.h>
#include <math.h>
#include <stdint.h>

// ---------------- problem constants ----------------
#define HDIM   2048
#define NH     16
#define QLORA  1536
#define KVLORA 512
#define DN     128
#define DR     64
#define DV     128
#define QD     192
#define BB     2
#define SS     2048
#define MTOT   (BB*SS)      // 4096
#define CKVW   (KVLORA+DR)  // 576
#define KVW    (NH*(DN+DV)) // 4096
#define QW     (NH*QD)      // 3072
#define OW     (NH*DV)      // 2048

// ---------------- fp32 scratch ----------------
__device__ float d_qa  [(size_t)MTOT*QLORA];
__device__ float d_q   [(size_t)MTOT*QW];
__device__ float d_ckv [(size_t)MTOT*CKVW];

// ---------------- bf16 hi/lo scratch ----------------
__device__ __nv_bfloat16 d_hidh [(size_t)MTOT*HDIM],   d_hidl [(size_t)MTOT*HDIM];
__device__ __nv_bfloat16 d_wqah [(size_t)QLORA*HDIM],  d_wqal [(size_t)QLORA*HDIM];
__device__ __nv_bfloat16 d_wkvah[(size_t)CKVW*HDIM],   d_wkval[(size_t)CKVW*HDIM];
__device__ __nv_bfloat16 d_wqbh [(size_t)QW*QLORA],    d_wqbl [(size_t)QW*QLORA];
__device__ __nv_bfloat16 d_wkvbh[(size_t)KVW*KVLORA],  d_wkvbl[(size_t)KVW*KVLORA];
__device__ __nv_bfloat16 d_woh  [(size_t)HDIM*OW],     d_wol  [(size_t)HDIM*OW];
__device__ __nv_bfloat16 d_qanh [(size_t)MTOT*QLORA],  d_qanl [(size_t)MTOT*QLORA];
__device__ __nv_bfloat16 d_ckvnh[(size_t)MTOT*KVLORA], d_ckvnl[(size_t)MTOT*KVLORA];
__device__ __nv_bfloat16 d_kvh  [(size_t)MTOT*KVW],    d_kvl  [(size_t)MTOT*KVW];
__device__ __nv_bfloat16 d_kpeh [(size_t)MTOT*DR],     d_kpel [(size_t)MTOT*DR];
__device__ __nv_bfloat16 d_atth [(size_t)MTOT*OW],     d_attl [(size_t)MTOT*OW];

// ---------------- helpers ----------------
__device__ __forceinline__ uint32_t smem_u32(const void* p) {
    uint32_t a;
    asm("{ .reg .u64 t; cvta.to.shared.u64 t, %1; cvt.u32.u64 %0, t; }" : "=r"(a) : "l"(p));
    return a;
}

__device__ __forceinline__ void ldsm4(uint32_t r[4], uint32_t addr) {
    asm volatile("ldmatrix.sync.aligned.m8n8.x4.shared.b16 {%0,%1,%2,%3}, [%4];"
                 : "=r"(r[0]), "=r"(r[1]), "=r"(r[2]), "=r"(r[3]) : "r"(addr));
}

__device__ __forceinline__ void ldsm4t(uint32_t r[4], uint32_t addr) {
    asm volatile("ldmatrix.sync.aligned.m8n8.x4.trans.shared.b16 {%0,%1,%2,%3}, [%4];"
                 : "=r"(r[0]), "=r"(r[1]), "=r"(r[2]), "=r"(r[3]) : "r"(addr));
}

__device__ __forceinline__ void mma_bf16(float c[4], const uint32_t a[4],
                                         uint32_t b0, uint32_t b1) {
    asm volatile(
        "mma.sync.aligned.m16n8k16.row.col.f32.bf16.bf16.f32 "
        "{%0,%1,%2,%3}, {%4,%5,%6,%7}, {%8,%9}, {%0,%1,%2,%3};"
        : "+f"(c[0]), "+f"(c[1]), "+f"(c[2]), "+f"(c[3])
        : "r"(a[0]), "r"(a[1]), "r"(a[2]), "r"(a[3]), "r"(b0), "r"(b1));
}

__device__ __forceinline__ void split2(float x, float y, uint32_t& hp, uint32_t& lp) {
    __nv_bfloat16 hx = __float2bfloat16(x), hy = __float2bfloat16(y);
    __nv_bfloat16 lx = __float2bfloat16(x - __bfloat162float(hx));
    __nv_bfloat16 ly = __float2bfloat16(y - __bfloat162float(hy));
    hp = ((uint32_t)__bfloat16_as_ushort(hy) << 16) | __bfloat16_as_ushort(hx);
    lp = ((uint32_t)__bfloat16_as_ushort(ly) << 16) | __bfloat16_as_ushort(lx);
}

__device__ __forceinline__ uint32_t sw64(uint32_t o)   { return o ^ ((o >> 3) & 0x30); }
__device__ __forceinline__ uint32_t swz256(uint32_t o) { return o ^ (((o >> 8) & 7) << 4); }

__device__ __forceinline__ void cpa16(uint32_t dst, const void* src) {
    asm volatile("cp.async.cg.shared.global [%0], [%1], 16;" :: "r"(dst), "l"(src));
}
__device__ __forceinline__ void cpa16p(uint32_t dst, const void* src, bool valid) {
    int sz = valid ? 16 : 0;
    asm volatile("cp.async.cg.shared.global [%0], [%1], 16, %2;" :: "r"(dst), "l"(src), "r"(sz));
}
#define CPA_COMMIT() asm volatile("cp.async.commit_group;" ::: "memory")
#define CPA_WAIT1()  asm volatile("cp.async.wait_group 1;" ::: "memory")
#define CPA_WAIT0()  asm volatile("cp.async.wait_group 0;" ::: "memory")

// ---------------- fp32 -> bf16 hi/lo split ----------------
__global__ void split_kernel(const float* __restrict__ src, int lda, int cols,
                             __nv_bfloat16* __restrict__ h, __nv_bfloat16* __restrict__ l)
{
    const int row = blockIdx.x;
    const float* p = src + (size_t)row * lda;
    uint32_t* hp = reinterpret_cast<uint32_t*>(h + (size_t)row * cols);
    uint32_t* lp = reinterpret_cast<uint32_t*>(l + (size_t)row * cols);
    for (int i = threadIdx.x * 4; i < cols; i += blockDim.x * 4) {
        float4 v = *reinterpret_cast<const float4*>(p + i);
        uint32_t h0, l0, h1, l1;
        split2(v.x, v.y, h0, l0);
        split2(v.z, v.w, h1, l1);
        hp[i/2] = h0; hp[i/2+1] = h1;
        lp[i/2] = l0; lp[i/2+1] = l1;
    }
}

// ---------------- fused RMSNorm + split ----------------
__global__ void rmsnorm_split(const float* __restrict__ x, const float* __restrict__ g,
                              int D, int lda,
                              __nv_bfloat16* __restrict__ h, __nv_bfloat16* __restrict__ l)
{
    const int row = blockIdx.x;
    const float* p = x + (size_t)row * lda;
    float ss = 0.f;
    for (int i = threadIdx.x; i < D; i += blockDim.x) { float v = p[i]; ss += v * v; }
    #pragma unroll
    for (int o = 16; o > 0; o >>= 1) ss += __shfl_xor_sync(0xffffffffu, ss, o);
    __shared__ float sred[8];
    if ((threadIdx.x & 31) == 0) sred[threadIdx.x >> 5] = ss;
    __syncthreads();
    if (threadIdx.x < 8) {
        float v = sred[threadIdx.x];
        #pragma unroll
        for (int o = 4; o > 0; o >>= 1) v += __shfl_xor_sync(0xffu, v, o);
        if (threadIdx.x == 0) sred[0] = v;
    }
    __syncthreads();
    const float inv = rsqrtf(sred[0] / (float)D + 1e-6f);
    uint32_t* hp = reinterpret_cast<uint32_t*>(h + (size_t)row * D);
    uint32_t* lp = reinterpret_cast<uint32_t*>(l + (size_t)row * D);
    for (int i = threadIdx.x * 4; i < D; i += blockDim.x * 4) {
        float4 v = *reinterpret_cast<const float4*>(p + i);
        v.x *= inv * g[i]; v.y *= inv * g[i+1]; v.z *= inv * g[i+2]; v.w *= inv * g[i+3];
        uint32_t h0, l0, h1, l1;
        split2(v.x, v.y, h0, l0);
        split2(v.z, v.w, h1, l1);
        hp[i/2] = h0; hp[i/2+1] = h1;
        lp[i/2] = l0; lp[i/2+1] = l1;
    }
}

// ---------------- bf16x3 GEMM core, 3-stage cp.async pipeline ----------------
#define GS_AH 0
#define GS_AL 8192
#define GS_BH 16384
#define GS_BL 24576
#define GS_STAGE 32768
#define GEMM_SMEM (3*GS_STAGE)

__device__ __forceinline__ void gemm_core(
    const __nv_bfloat16* __restrict__ Ah, const __nv_bfloat16* __restrict__ Al,
    const __nv_bfloat16* __restrict__ Bh, const __nv_bfloat16* __restrict__ Bl,
    float* __restrict__ C, __nv_bfloat16* __restrict__ Ch, __nv_bfloat16* __restrict__ Cl,
    int N, int K, int bm, int bn, char* sm)
{
    const uint32_t sb = smem_u32(sm);
    const int tid = threadIdx.x;
    const int NC = K >> 5;

    const int w = tid >> 5, lane = tid & 31;
    const int wm = (w & 1) * 64;
    const int wn = (w >> 1) * 32;
    const int mi  = lane >> 3;
    const int aro = (lane & 7) + (mi & 1) * 8;
    const int aks = (mi >> 1) * 8;
    const int bro = (lane & 7) + ((mi >> 1) & 1) * 8;
    const int bks = (mi & 1) * 8;

    float acc[4][4][4] = {};

    const int lr0 = tid >> 2;
    const int lc0 = tid & 3;
    const int lr1 = (256 + tid) >> 2;
    const int lc1 = (256 + tid) & 3;
    const uint32_t do0 = sw64((uint32_t)(lr0 * 64 + lc0 * 16));
    const uint32_t do1 = sw64((uint32_t)(lr1 * 64 + lc1 * 16));
    const bool bok0 = (bn + lr0) < N;
    const bool bok1 = (bn + lr1) < N;

    auto issue = [&](int c) {
        const int k0 = c << 5;
        const uint32_t st = sb + (uint32_t)(c % 3) * GS_STAGE;
        {
            const size_t go = (size_t)(bm + lr0) * K + k0 + lc0 * 8;
            cpa16(st + GS_AH + do0, Ah + go);
            cpa16(st + GS_AL + do0, Al + go);
            const size_t gb = (size_t)(bn + lr0) * K + k0 + lc0 * 8;
            cpa16p(st + GS_BH + do0, Bh + gb, bok0);
            cpa16p(st + GS_BL + do0, Bl + gb, bok0);
        }
        {
            const size_t go = (size_t)(bm + lr1) * K + k0 + lc1 * 8;
            cpa16(st + GS_AH + do1, Ah + go);
            cpa16(st + GS_AL + do1, Al + go);
            const size_t gb = (size_t)(bn + lr1) * K + k0 + lc1 * 8;
            cpa16p(st + GS_BH + do1, Bh + gb, bok1);
            cpa16p(st + GS_BL + do1, Bl + gb, bok1);
        }
        CPA_COMMIT();
    };

    auto compute = [&](int c) {
        const uint32_t st = sb + (uint32_t)(c % 3) * GS_STAGE;
        #pragma unroll
        for (int k16 = 0; k16 < 32; k16 += 16) {
            uint32_t A_h[4][4], B_h[2][4];
            #pragma unroll
            for (int f = 0; f < 4; f++) {
                const uint32_t x = (uint32_t)((wm + f * 16 + aro) * 64 + (k16 + aks) * 2);
                ldsm4(A_h[f], st + GS_AH + sw64(x));
            }
            #pragma unroll
            for (int g2 = 0; g2 < 2; g2++) {
                const uint32_t x = (uint32_t)((wn + g2 * 16 + bro) * 64 + (k16 + bks) * 2);
                ldsm4(B_h[g2], st + GS_BH + sw64(x));
            }
            #pragma unroll
            for (int f = 0; f < 4; f++)
                #pragma unroll
                for (int ni = 0; ni < 4; ni++)
                    mma_bf16(acc[f][ni], A_h[f], B_h[ni >> 1][(ni & 1) * 2],
                             B_h[ni >> 1][(ni & 1) * 2 + 1]);
            {
                uint32_t B_l[2][4];
                #pragma unroll
                for (int g2 = 0; g2 < 2; g2++) {
                    const uint32_t x = (uint32_t)((wn + g2 * 16 + bro) * 64 + (k16 + bks) * 2);
                    ldsm4(B_l[g2], st + GS_BL + sw64(x));
                }
                #pragma unroll
                for (int f = 0; f < 4; f++)
                    #pragma unroll
                    for (int ni = 0; ni < 4; ni++)
                        mma_bf16(acc[f][ni], A_h[f], B_l[ni >> 1][(ni & 1) * 2],
                                 B_l[ni >> 1][(ni & 1) * 2 + 1]);
            }
            {
                uint32_t A_l[4][4];
                #pragma unroll
                for (int f = 0; f < 4; f++) {
                    const uint32_t x = (uint32_t)((wm + f * 16 + aro) * 64 + (k16 + aks) * 2);
                    ldsm4(A_l[f], st + GS_AL + sw64(x));
                }
                #pragma unroll
                for (int f = 0; f < 4; f++)
                    #pragma unroll
                    for (int ni = 0; ni < 4; ni++)
                        mma_bf16(acc[f][ni], A_l[f], B_h[ni >> 1][(ni & 1) * 2],
                                 B_h[ni >> 1][(ni & 1) * 2 + 1]);
            }
        }
    };

    issue(0);
    issue(1);
    for (int c = 0; c < NC; c++) {
        if (c + 1 < NC) CPA_WAIT1(); else CPA_WAIT0();
        __syncthreads();
        if (c + 2 < NC) issue(c + 2);
        compute(c);
        __syncthreads();
    }

    const int gq = lane >> 2, t4 = lane & 3;
    if (C) {
        #pragma unroll
        for (int f = 0; f < 4; f++)
            #pragma unroll
            for (int ni = 0; ni < 4; ni++) {
                const int col = bn + wn + ni * 8 + t4 * 2;
                if (col < N) {
                    const int r = bm + wm + f * 16 + gq;
                    *reinterpret_cast<float2*>(&C[(size_t)r * N + col]) =
                        make_float2(acc[f][ni][0], acc[f][ni][1]);
                    *reinterpret_cast<float2*>(&C[(size_t)(r + 8) * N + col]) =
                        make_float2(acc[f][ni][2], acc[f][ni][3]);
                }
            }
    } else {
        #pragma unroll
        for (int f = 0; f < 4; f++)
            #pragma unroll
            for (int ni = 0; ni < 4; ni++) {
                const int col = bn + wn + ni * 8 + t4 * 2;
                if (col < N) {
                    const int r = bm + wm + f * 16 + gq;
                    uint32_t hp, lp;
                    split2(acc[f][ni][0], acc[f][ni][1], hp, lp);
                    *reinterpret_cast<uint32_t*>(&Ch[(size_t)r * N + col]) = hp;
                    *reinterpret_cast<uint32_t*>(&Cl[(size_t)r * N + col]) = lp;
                    split2(acc[f][ni][2], acc[f][ni][3], hp, lp);
                    *reinterpret_cast<uint32_t*>(&Ch[(size_t)(r + 8) * N + col]) = hp;
                    *reinterpret_cast<uint32_t*>(&Cl[(size_t)(r + 8) * N + col]) = lp;
                }
            }
    }
}

__global__ __launch_bounds__(256, 2) void gemm_bf(
    const __nv_bfloat16* __restrict__ Ah, const __nv_bfloat16* __restrict__ Al,
    const __nv_bfloat16* __restrict__ Bh, const __nv_bfloat16* __restrict__ Bl,
    float* __restrict__ C, __nv_bfloat16* __restrict__ Ch, __nv_bfloat16* __restrict__ Cl,
    int N, int K)
{
    extern __shared__ char sm[];
    gemm_core(Ah, Al, Bh, Bl, C, Ch, Cl, N, K, blockIdx.y * 128, blockIdx.x * 128, sm);
}

// merged qa+ckv GEMM: same A, same K; grid.x = 12 (qa) + 5 (ckv) = 17
__global__ __launch_bounds__(256, 2) void gemm_dual(
    const __nv_bfloat16* __restrict__ Ah, const __nv_bfloat16* __restrict__ Al,
    const __nv_bfloat16* __restrict__ B1h, const __nv_bfloat16* __restrict__ B1l,
    float* __restrict__ C1, int N1, int split,
    const __nv_bfloat16* __restrict__ B2h, const __nv_bfloat16* __restrict__ B2l,
    float* __restrict__ C2, int N2, int K)
{
    extern __shared__ char sm[];
    const int bx = blockIdx.x;
    if (bx < split)
        gemm_core(Ah, Al, B1h, B1l, C1, nullptr, nullptr, N1, K,
                  blockIdx.y * 128, bx * 128, sm);
    else
        gemm_core(Ah, Al, B2h, B2l, C2, nullptr, nullptr, N2, K,
                  blockIdx.y * 128, (bx - split) * 128, sm);
}

// ---------------- RoPE ----------------
__global__ void rope_q_kernel(float* __restrict__ q)
{
    const int idx = blockIdx.x;
    const int row = idx / NH, h = idx % NH;
    const int t = row % SS;
    const int j = threadIdx.x;
    const double inv = exp(-log(10000.0) * (2.0 * j) / (double)DR);
    const double ang = (double)t * inv;
    const float c = (float)cos(ang), s = (float)sin(ang);
    float* p = q + (size_t)row * QW + h * QD + DN;
    const float x0 = p[j], x1 = p[j + 32];
    p[j]      = x0 * c - x1 * s;
    p[j + 32] = x1 * c + x0 * s;
}

__global__ void rope_k_split(const float* __restrict__ ckv,
                             __nv_bfloat16* __restrict__ kpeh, __nv_bfloat16* __restrict__ kpel)
{
    const int row = blockIdx.x;
    const int t = row % SS;
    const int j = threadIdx.x;
    const double inv = exp(-log(10000.0) * (2.0 * j) / (double)DR);
    const double ang = (double)t * inv;
    const float c = (float)cos(ang), s = (float)sin(ang);
    const float* p = ckv + (size_t)row * CKVW + KVLORA;
    const float x0 = p[j], x1 = p[j + 32];
    const float y0 = x0 * c - x1 * s;
    const float y1 = x1 * c + x0 * s;
    __nv_bfloat16 h0 = __float2bfloat16(y0);
    __nv_bfloat16 h1 = __float2bfloat16(y1);
    kpeh[(size_t)row * DR + j]      = h0;
    kpeh[(size_t)row * DR + j + 32] = h1;
    kpel[(size_t)row * DR + j]      = __float2bfloat16(y0 - __bfloat162float(h0));
    kpel[(size_t)row * DR + j + 32] = __float2bfloat16(y1 - __bfloat162float(h1));
}

// ---------------- tensor-core causal flash attention ----------------
#define FQH 0                 // 6*8192 = 49152
#define FQL 49152
#define FKB 98304             // stage s at FKB + s*49152; KH +0, KL +24576
#define FVB 196608            // VH +0, VL +16384
#define FLASH_SMEM 229376

__global__ __launch_bounds__(256) void flash_tc(
    const float* __restrict__ q,
    const __nv_bfloat16* __restrict__ kvh, const __nv_bfloat16* __restrict__ kvl,
    const __nv_bfloat16* __restrict__ kpeh, const __nv_bfloat16* __restrict__ kpel,
    __nv_bfloat16* __restrict__ atth, __nv_bfloat16* __restrict__ attl)
{
    extern __shared__ char sm[];
    const uint32_t sb = smem_u32(sm);

    // longest-first: big causal tiles (high qb) launch first
    const int qb = (int)gridDim.x - 1 - (int)blockIdx.x;
    const int h = blockIdx.y, b = blockIdx.z;
    const int tid = threadIdx.x;
    const int w = tid >> 5, lane = tid & 31;
    const int g = lane >> 2, t4 = lane & 3;
    const int mi  = lane >> 3;
    const int aro = (lane & 7) + (mi & 1) * 8;
    const int aks = (mi >> 1) * 8;
    const int bro = (lane & 7) + ((mi >> 1) & 1) * 8;
    const int bks = (mi & 1) * 8;
    const int hoff = h * (DN + DV);

    const int q0 = qb * 128;
    const int row0 = b * SS + q0;
    const int brow = b * SS;
    const float scale = rsqrtf((float)QD);
    const int n_tiles = 2 * qb + 2;

    auto issueK = [&](int kt) {
        const uint32_t base = sb + FKB + (kt & 1) * 49152;
        const int krow = brow + kt * 64;
        #pragma unroll
        for (int t = 0; t < 12; t++) {
            const int idx = t * 256 + tid;
            const int half = idx >= 1536;
            const int cidx = half ? idx - 1536 : idx;
            const int key = cidx / 24;
            const int c = cidx % 24;
            const int d = (c < 16) ? c * 8 : 128 + (c - 16) * 8;
            const uint32_t dst = base + (half ? 24576u : 0u) + (uint32_t)(d >> 5) * 4096
                               + sw64((uint32_t)(key * 64 + (d & 31) * 2));
            const __nv_bfloat16* src;
            if (c < 16) src = (half ? kvl : kvh) + (size_t)(krow + key) * KVW + hoff + d;
            else        src = (half ? kpel : kpeh) + (size_t)(krow + key) * DR + (d - 128);
            cpa16(dst, src);
        }
    };
    auto issueV = [&](int kt) {
        const int krow = brow + kt * 64;
        #pragma unroll
        for (int t = 0; t < 8; t++) {
            const int idx = t * 256 + tid;
            const int half = idx >= 1024;
            const int cidx = idx & 1023;
            const int key = cidx >> 4;
            const int d = (cidx & 15) * 8;
            const uint32_t dst = sb + FVB + (half ? 16384u : 0u)
                               + swz256((uint32_t)(key * 256 + d * 2));
            const __nv_bfloat16* src = (half ? kvl : kvh) + (size_t)(krow + key) * KVW + hoff + DN + d;
            cpa16(dst, src);
        }
    };

    #pragma unroll
    for (int t = 0; t < 24; t++) {
        const int idx = t * 256 + tid;
        const int r = idx / 48;
        const int c4 = (idx % 48) * 4;
        float4 v = *reinterpret_cast<const float4*>(&q[(size_t)(row0 + r) * QW + h * QD + c4]);
        v.x *= scale; v.y *= scale; v.z *= scale; v.w *= scale;
        const uint32_t off = (uint32_t)(c4 >> 5) * 8192 + sw64((uint32_t)(r * 64 + (c4 & 31) * 2));
        uint32_t h0, l0, h1, l1;
        split2(v.x, v.y, h0, l0);
        split2(v.z, v.w, h1, l1);
        *reinterpret_cast<uint2*>(sm + FQH + off) = make_uint2(h0, h1);
        *reinterpret_cast<uint2*>(sm + FQL + off) = make_uint2(l0, l1);
    }

    issueK(0);
    issueV(0);
    CPA_COMMIT();

    float of[16][4] = {};
    float m0 = -INFINITY, m1 = -INFINITY, l0 = 0.f, l1 = 0.f;

    for (int kt = 0; kt < n_tiles; kt++) {
        if (kt + 1 < n_tiles) { issueK(kt + 1); CPA_COMMIT(); CPA_WAIT1(); }
        else                  { CPA_WAIT0(); }
        __syncthreads();

        const int k0 = kt * 64;
        const uint32_t kbase = sb + FKB + (kt & 1) * 49152;

        float sf[8][4] = {};
        const uint32_t qax = (uint32_t)((w * 16 + aro) * 64 + aks * 2);
        #pragma unroll
        for (int s = 0; s < 12; s++) {
            uint32_t ah[4], al[4];
            const uint32_t qoff = (uint32_t)(s >> 1) * 8192 + sw64(qax + (s & 1) * 32);
            ldsm4(ah, sb + FQH + qoff);
            ldsm4(al, sb + FQL + qoff);
            #pragma unroll
            for (int g2 = 0; g2 < 4; g2++) {
                const uint32_t kx = (uint32_t)((g2 * 16 + bro) * 64 + bks * 2);
                const uint32_t koff = (uint32_t)(s >> 1) * 4096 + sw64(kx + (s & 1) * 32);
                uint32_t bh[4], bl[4];
                ldsm4(bh, kbase + koff);
                ldsm4(bl, kbase + 24576 + koff);
                #pragma unroll
                for (int sub = 0; sub < 2; sub++) {
                    const int ni = g2 * 2 + sub;
                    mma_bf16(sf[ni], ah, bh[sub * 2], bh[sub * 2 + 1]);
                    mma_bf16(sf[ni], ah, bl[sub * 2], bl[sub * 2 + 1]);
                    mma_bf16(sf[ni], al, bh[sub * 2], bh[sub * 2 + 1]);
                }
            }
        }

        if (kt >= 2 * qb) {
            const int qr0 = q0 + w * 16 + g;
            const int qr8 = qr0 + 8;
            #pragma unroll
            for (int ni = 0; ni < 8; ni++) {
                const int kp0 = k0 + ni * 8 + 2 * t4;
                const int kp1 = kp0 + 1;
                if (kp0 > qr0) sf[ni][0] = -1e30f;
                if (kp1 > qr0) sf[ni][1] = -1e30f;
                if (kp0 > qr8) sf[ni][2] = -1e30f;
                if (kp1 > qr8) sf[ni][3] = -1e30f;
            }
        }

        float tm0 = -INFINITY, tm1 = -INFINITY;
        #pragma unroll
        for (int ni = 0; ni < 8; ni++) {
            tm0 = fmaxf(tm0, fmaxf(sf[ni][0], sf[ni][1]));
            tm1 = fmaxf(tm1, fmaxf(sf[ni][2], sf[ni][3]));
        }
        #pragma unroll
        for (int o = 1; o < 4; o <<= 1) {
            tm0 = fmaxf(tm0, __shfl_xor_sync(0xffffffffu, tm0, o));
            tm1 = fmaxf(tm1, __shfl_xor_sync(0xffffffffu, tm1, o));
        }
        const float mn0 = fmaxf(m0, tm0), mn1 = fmaxf(m1, tm1);
        const float a0 = __expf(m0 - mn0), a1 = __expf(m1 - mn1);
        float ls0 = 0.f, ls1 = 0.f;
        #pragma unroll
        for (int ni = 0; ni < 8; ni++) {
            sf[ni][0] = __expf(sf[ni][0] - mn0); ls0 += sf[ni][0];
            sf[ni][1] = __expf(sf[ni][1] - mn0); ls0 += sf[ni][1];
            sf[ni][2] = __expf(sf[ni][2] - mn1); ls1 += sf[ni][2];
            sf[ni][3] = __expf(sf[ni][3] - mn1); ls1 += sf[ni][3];
        }
        #pragma unroll
        for (int o = 1; o < 4; o <<= 1) {
            ls0 += __shfl_xor_sync(0xffffffffu, ls0, o);
            ls1 += __shfl_xor_sync(0xffffffffu, ls1, o);
        }
        l0 = l0 * a0 + ls0; l1 = l1 * a1 + ls1;
        m0 = mn0; m1 = mn1;
        #pragma unroll
        for (int ni = 0; ni < 16; ni++) {
            of[ni][0] *= a0; of[ni][1] *= a0;
            of[ni][2] *= a1; of[ni][3] *= a1;
        }

        #pragma unroll
        for (int ks = 0; ks < 4; ks++) {
            uint32_t ph[4], pl[4];
            split2(sf[2*ks][0],   sf[2*ks][1],   ph[0], pl[0]);
            split2(sf[2*ks][2],   sf[2*ks][3],   ph[1], pl[1]);
            split2(sf[2*ks+1][0], sf[2*ks+1][1], ph[2], pl[2]);
            split2(sf[2*ks+1][2], sf[2*ks+1][3], ph[3], pl[3]);
            const int vkey = ks * 16 + (mi & 1) * 8 + (lane & 7);
            const int vdvo = (mi >> 1) * 8;
            #pragma unroll
            for (int g2 = 0; g2 < 8; g2++) {
                const uint32_t vo = swz256((uint32_t)(vkey * 256 + (g2 * 16 + vdvo) * 2));
                uint32_t vh[4], vl[4];
                ldsm4t(vh, sb + FVB + vo);
                ldsm4t(vl, sb + FVB + 16384 + vo);
                #pragma unroll
                for (int sub = 0; sub < 2; sub++) {
                    const int ni = g2 * 2 + sub;
                    mma_bf16(of[ni], ph, vh[sub * 2], vh[sub * 2 + 1]);
                    mma_bf16(of[ni], ph, vl[sub * 2], vl[sub * 2 + 1]);
                    mma_bf16(of[ni], pl, vh[sub * 2], vh[sub * 2 + 1]);
                }
            }
        }
        __syncthreads();
        if (kt + 1 < n_tiles) { issueV(kt + 1); CPA_COMMIT(); }
    }

    const float il0 = 1.f / l0, il1 = 1.f / l1;
    const int rg = row0 + w * 16 + g;
    #pragma unroll
    for (int ni = 0; ni < 16; ni++) {
        const int col = h * DV + ni * 8 + t4 * 2;
        uint32_t hp, lp;
        split2(of[ni][0] * il0, of[ni][1] * il0, hp, lp);
        *reinterpret_cast<uint32_t*>(&atth[(size_t)rg * OW + col]) = hp;
        *reinterpret_cast<uint32_t*>(&attl[(size_t)rg * OW + col]) = lp;
        split2(of[ni][2] * il1, of[ni][3] * il1, hp, lp);
        *reinterpret_cast<uint32_t*>(&atth[(size_t)(rg + 8) * OW + col]) = hp;
        *reinterpret_cast<uint32_t*>(&attl[(size_t)(rg + 8) * OW + col]) = lp;
    }
}

// ---------------- launch ----------------
extern "C" void kernel_launch(void* const* d_in, const int* in_sizes, int n_in,
                              void* d_out, int out_size)
{
    (void)in_sizes; (void)n_in; (void)out_size;
    const float* hidden = (const float*)d_in[0];
    const float* w_qa   = (const float*)d_in[1];
    const float* g_qa   = (const float*)d_in[2];
    const float* w_qb   = (const float*)d_in[3];
    const float* w_kva  = (const float*)d_in[4];
    const float* g_kva  = (const float*)d_in[5];
    const float* w_kvb  = (const float*)d_in[6];
    const float* w_o    = (const float*)d_in[7];
    float* out = (float*)d_out;

    float *qa, *q, *ckv;
    cudaGetSymbolAddress((void**)&qa,   d_qa);
    cudaGetSymbolAddress((void**)&q,    d_q);
    cudaGetSymbolAddress((void**)&ckv,  d_ckv);

    __nv_bfloat16 *hidh,*hidl,*wqah,*wqal,*wkvah,*wkval,*wqbh,*wqbl,*wkvbh,*wkvbl,*woh,*wol;
    __nv_bfloat16 *qanh,*qanl,*ckvnh,*ckvnl,*kvh,*kvl,*kpeh,*kpel,*atth,*attl;
    cudaGetSymbolAddress((void**)&hidh, d_hidh);   cudaGetSymbolAddress((void**)&hidl, d_hidl);
    cudaGetSymbolAddress((void**)&wqah, d_wqah);   cudaGetSymbolAddress((void**)&wqal, d_wqal);
    cudaGetSymbolAddress((void**)&wkvah, d_wkvah); cudaGetSymbolAddress((void**)&wkval, d_wkval);
    cudaGetSymbolAddress((void**)&wqbh, d_wqbh);   cudaGetSymbolAddress((void**)&wqbl, d_wqbl);
    cudaGetSymbolAddress((void**)&wkvbh, d_wkvbh); cudaGetSymbolAddress((void**)&wkvbl, d_wkvbl);
    cudaGetSymbolAddress((void**)&woh, d_woh);     cudaGetSymbolAddress((void**)&wol, d_wol);
    cudaGetSymbolAddress((void**)&qanh, d_qanh);   cudaGetSymbolAddress((void**)&qanl, d_qanl);
    cudaGetSymbolAddress((void**)&ckvnh, d_ckvnh); cudaGetSymbolAddress((void**)&ckvnl, d_ckvnl);
    cudaGetSymbolAddress((void**)&kvh, d_kvh);     cudaGetSymbolAddress((void**)&kvl, d_kvl);
    cudaGetSymbolAddress((void**)&kpeh, d_kpeh);   cudaGetSymbolAddress((void**)&kpel, d_kpel);
    cudaGetSymbolAddress((void**)&atth, d_atth);   cudaGetSymbolAddress((void**)&attl, d_attl);

    cudaFuncSetAttribute(gemm_bf, cudaFuncAttributeMaxDynamicSharedMemorySize, GEMM_SMEM);
    cudaFuncSetAttribute(gemm_dual, cudaFuncAttributeMaxDynamicSharedMemorySize, GEMM_SMEM);
    cudaFuncSetAttribute(flash_tc, cudaFuncAttributeMaxDynamicSharedMemorySize, FLASH_SMEM);

    const dim3 blk(256);

    // launches 1-3: splits needed by the first GEMM
    split_kernel<<<MTOT, 256>>>(hidden, HDIM, HDIM, hidh, hidl);          // 1
    split_kernel<<<QLORA, 256>>>(w_qa, HDIM, HDIM, wqah, wqal);           // 2
    split_kernel<<<CKVW, 256>>>(w_kva, HDIM, HDIM, wkvah, wkval);         // 3
    // launch 4 (profiled): merged qa + ckv GEMM (shared A, K=2048)
    gemm_dual<<<dim3(QLORA/128 + (CKVW+127)/128, MTOT/128), blk, GEMM_SMEM>>>(
        hidh, hidl,
        wqah, wqal, qa, QLORA, QLORA/128,
        wkvah, wkval, ckv, CKVW, HDIM);
    // remaining weight splits
    split_kernel<<<QW, 256>>>(w_qb, QLORA, QLORA, wqbh, wqbl);
    split_kernel<<<KVW, 256>>>(w_kvb, KVLORA, KVLORA, wkvbh, wkvbl);
    // fused rmsnorm + split
    rmsnorm_split<<<MTOT, 256>>>(qa, g_qa, QLORA, QLORA, qanh, qanl);
    rmsnorm_split<<<MTOT, 256>>>(ckv, g_kva, KVLORA, CKVW, ckvnh, ckvnl);
    // q = rms(q_a) @ w_qb^T   [4096,3072]
    gemm_bf<<<dim3(QW/128, MTOT/128), blk, GEMM_SMEM>>>(qanh, qanl, wqbh, wqbl, q, nullptr, nullptr, QW, QLORA);
    // kv = rms(ckv) @ w_kvb^T [4096,4096] (bf16 hi/lo out)
    gemm_bf<<<dim3(KVW/128, MTOT/128), blk, GEMM_SMEM>>>(ckvnh, ckvnl, wkvbh, wkvbl, nullptr, kvh, kvl, KVW, KVLORA);
    // rope
    rope_q_kernel<<<MTOT * NH, 32>>>(q);
    rope_k_split<<<MTOT, 32>>>(ckv, kpeh, kpel);
    // flash attention (longest-first qb order)
    flash_tc<<<dim3(SS/128, NH, BB), 256, FLASH_SMEM>>>(q, kvh, kvl, kpeh, kpel, atth, attl);
    // out = attn @ w_o^T      [4096,2048]
    split_kernel<<<HDIM, 256>>>(w_o, OW, OW, woh, wol);
    gemm_bf<<<dim3(HDIM/128, MTOT/128), blk, GEMM_SMEM>>>(atth, attl, woh, wol, out, nullptr, nullptr, HDIM, OW);
}

// round 11
// speedup vs baseline: 4.7350x; 1.0044x over previous
#include <cuda_runtime.h>
#include <cuda_bf16.h>
#include <math.h>
#include <stdint.h>

// ---------------- problem constants ----------------
#define HDIM   2048
#define NH     16
#define QLORA  1536
#define KVLORA 512
#define DN     128
#define DR     64
#define DV     128
#define QD     192
#define BB     2
#define SS     2048
#define MTOT   (BB*SS)      // 4096
#define CKVW   (KVLORA+DR)  // 576
#define KVW    (NH*(DN+DV)) // 4096
#define QW     (NH*QD)      // 3072
#define OW     (NH*DV)      // 2048

// ---------------- fp32 scratch ----------------
__device__ float d_qa  [(size_t)MTOT*QLORA];
__device__ float d_q   [(size_t)MTOT*QW];
__device__ float d_ckv [(size_t)MTOT*CKVW];

// ---------------- bf16 hi/lo scratch ----------------
__device__ __nv_bfloat16 d_hidh [(size_t)MTOT*HDIM],   d_hidl [(size_t)MTOT*HDIM];
__device__ __nv_bfloat16 d_wqah [(size_t)QLORA*HDIM],  d_wqal [(size_t)QLORA*HDIM];
__device__ __nv_bfloat16 d_wkvah[(size_t)CKVW*HDIM],   d_wkval[(size_t)CKVW*HDIM];
__device__ __nv_bfloat16 d_wqbh [(size_t)QW*QLORA],    d_wqbl [(size_t)QW*QLORA];
__device__ __nv_bfloat16 d_wkvbh[(size_t)KVW*KVLORA],  d_wkvbl[(size_t)KVW*KVLORA];
__device__ __nv_bfloat16 d_woh  [(size_t)HDIM*OW],     d_wol  [(size_t)HDIM*OW];
__device__ __nv_bfloat16 d_qanh [(size_t)MTOT*QLORA],  d_qanl [(size_t)MTOT*QLORA];
__device__ __nv_bfloat16 d_ckvnh[(size_t)MTOT*KVLORA], d_ckvnl[(size_t)MTOT*KVLORA];
__device__ __nv_bfloat16 d_kvh  [(size_t)MTOT*KVW],    d_kvl  [(size_t)MTOT*KVW];
__device__ __nv_bfloat16 d_kpeh [(size_t)MTOT*DR],     d_kpel [(size_t)MTOT*DR];
__device__ __nv_bfloat16 d_atth [(size_t)MTOT*OW],     d_attl [(size_t)MTOT*OW];

// ---------------- helpers ----------------
__device__ __forceinline__ uint32_t smem_u32(const void* p) {
    uint32_t a;
    asm("{ .reg .u64 t; cvta.to.shared.u64 t, %1; cvt.u32.u64 %0, t; }" : "=r"(a) : "l"(p));
    return a;
}

__device__ __forceinline__ void ldsm4(uint32_t r[4], uint32_t addr) {
    asm volatile("ldmatrix.sync.aligned.m8n8.x4.shared.b16 {%0,%1,%2,%3}, [%4];"
                 : "=r"(r[0]), "=r"(r[1]), "=r"(r[2]), "=r"(r[3]) : "r"(addr));
}

__device__ __forceinline__ void ldsm4t(uint32_t r[4], uint32_t addr) {
    asm volatile("ldmatrix.sync.aligned.m8n8.x4.trans.shared.b16 {%0,%1,%2,%3}, [%4];"
                 : "=r"(r[0]), "=r"(r[1]), "=r"(r[2]), "=r"(r[3]) : "r"(addr));
}

__device__ __forceinline__ void mma_bf16(float c[4], const uint32_t a[4],
                                         uint32_t b0, uint32_t b1) {
    asm volatile(
        "mma.sync.aligned.m16n8k16.row.col.f32.bf16.bf16.f32 "
        "{%0,%1,%2,%3}, {%4,%5,%6,%7}, {%8,%9}, {%0,%1,%2,%3};"
        : "+f"(c[0]), "+f"(c[1]), "+f"(c[2]), "+f"(c[3])
        : "r"(a[0]), "r"(a[1]), "r"(a[2]), "r"(a[3]), "r"(b0), "r"(b1));
}

__device__ __forceinline__ void split2(float x, float y, uint32_t& hp, uint32_t& lp) {
    __nv_bfloat16 hx = __float2bfloat16(x), hy = __float2bfloat16(y);
    __nv_bfloat16 lx = __float2bfloat16(x - __bfloat162float(hx));
    __nv_bfloat16 ly = __float2bfloat16(y - __bfloat162float(hy));
    hp = ((uint32_t)__bfloat16_as_ushort(hy) << 16) | __bfloat16_as_ushort(hx);
    lp = ((uint32_t)__bfloat16_as_ushort(ly) << 16) | __bfloat16_as_ushort(lx);
}

__device__ __forceinline__ uint32_t sw64(uint32_t o)   { return o ^ ((o >> 3) & 0x30); }
__device__ __forceinline__ uint32_t swz256(uint32_t o) { return o ^ (((o >> 8) & 7) << 4); }

__device__ __forceinline__ void cpa16(uint32_t dst, const void* src) {
    asm volatile("cp.async.cg.shared.global [%0], [%1], 16;" :: "r"(dst), "l"(src));
}
__device__ __forceinline__ void cpa16p(uint32_t dst, const void* src, bool valid) {
    int sz = valid ? 16 : 0;
    asm volatile("cp.async.cg.shared.global [%0], [%1], 16, %2;" :: "r"(dst), "l"(src), "r"(sz));
}
#define CPA_COMMIT() asm volatile("cp.async.commit_group;" ::: "memory")
#define CPA_WAIT1()  asm volatile("cp.async.wait_group 1;" ::: "memory")
#define CPA_WAIT0()  asm volatile("cp.async.wait_group 0;" ::: "memory")

// ---------------- segmented fp32 -> bf16 hi/lo splits ----------------
__device__ __forceinline__ void split_row(const float* __restrict__ p, int cols,
                                          __nv_bfloat16* __restrict__ h,
                                          __nv_bfloat16* __restrict__ l)
{
    uint32_t* hp = reinterpret_cast<uint32_t*>(h);
    uint32_t* lp = reinterpret_cast<uint32_t*>(l);
    for (int i = threadIdx.x * 4; i < cols; i += blockDim.x * 4) {
        float4 v = *reinterpret_cast<const float4*>(p + i);
        uint32_t h0, l0, h1, l1;
        split2(v.x, v.y, h0, l0);
        split2(v.z, v.w, h1, l1);
        hp[i/2] = h0; hp[i/2+1] = h1;
        lp[i/2] = l0; lp[i/2+1] = l1;
    }
}

// segments: hidden [4096,2048], w_qa [1536,2048], w_kva [576,2048]
__global__ void splitA_kernel(
    const float* __restrict__ hid, __nv_bfloat16* __restrict__ hidh, __nv_bfloat16* __restrict__ hidl,
    const float* __restrict__ wqa, __nv_bfloat16* __restrict__ wqah, __nv_bfloat16* __restrict__ wqal,
    const float* __restrict__ wkva, __nv_bfloat16* __restrict__ wkvah, __nv_bfloat16* __restrict__ wkval)
{
    int r = blockIdx.x;
    if (r < MTOT) {
        split_row(hid + (size_t)r * HDIM, HDIM, hidh + (size_t)r * HDIM, hidl + (size_t)r * HDIM);
    } else if (r < MTOT + QLORA) {
        r -= MTOT;
        split_row(wqa + (size_t)r * HDIM, HDIM, wqah + (size_t)r * HDIM, wqal + (size_t)r * HDIM);
    } else {
        r -= MTOT + QLORA;
        split_row(wkva + (size_t)r * HDIM, HDIM, wkvah + (size_t)r * HDIM, wkval + (size_t)r * HDIM);
    }
}
#define SPLITA_ROWS (MTOT + QLORA + CKVW)

// segments: w_qb [3072,1536], w_kvb [4096,512], w_o [2048,2048]
__global__ void splitB_kernel(
    const float* __restrict__ wqb, __nv_bfloat16* __restrict__ wqbh, __nv_bfloat16* __restrict__ wqbl,
    const float* __restrict__ wkvb, __nv_bfloat16* __restrict__ wkvbh, __nv_bfloat16* __restrict__ wkvbl,
    const float* __restrict__ wo, __nv_bfloat16* __restrict__ woh, __nv_bfloat16* __restrict__ wol)
{
    int r = blockIdx.x;
    if (r < QW) {
        split_row(wqb + (size_t)r * QLORA, QLORA, wqbh + (size_t)r * QLORA, wqbl + (size_t)r * QLORA);
    } else if (r < QW + KVW) {
        r -= QW;
        split_row(wkvb + (size_t)r * KVLORA, KVLORA, wkvbh + (size_t)r * KVLORA, wkvbl + (size_t)r * KVLORA);
    } else {
        r -= QW + KVW;
        split_row(wo + (size_t)r * OW, OW, woh + (size_t)r * OW, wol + (size_t)r * OW);
    }
}
#define SPLITB_ROWS (QW + KVW + HDIM)

// ---------------- fused RMSNorm + split ----------------
__global__ void rmsnorm_split(const float* __restrict__ x, const float* __restrict__ g,
                              int D, int lda,
                              __nv_bfloat16* __restrict__ h, __nv_bfloat16* __restrict__ l)
{
    const int row = blockIdx.x;
    const float* p = x + (size_t)row * lda;
    float ss = 0.f;
    for (int i = threadIdx.x; i < D; i += blockDim.x) { float v = p[i]; ss += v * v; }
    #pragma unroll
    for (int o = 16; o > 0; o >>= 1) ss += __shfl_xor_sync(0xffffffffu, ss, o);
    __shared__ float sred[8];
    if ((threadIdx.x & 31) == 0) sred[threadIdx.x >> 5] = ss;
    __syncthreads();
    if (threadIdx.x < 8) {
        float v = sred[threadIdx.x];
        #pragma unroll
        for (int o = 4; o > 0; o >>= 1) v += __shfl_xor_sync(0xffu, v, o);
        if (threadIdx.x == 0) sred[0] = v;
    }
    __syncthreads();
    const float inv = rsqrtf(sred[0] / (float)D + 1e-6f);
    uint32_t* hp = reinterpret_cast<uint32_t*>(h + (size_t)row * D);
    uint32_t* lp = reinterpret_cast<uint32_t*>(l + (size_t)row * D);
    for (int i = threadIdx.x * 4; i < D; i += blockDim.x * 4) {
        float4 v = *reinterpret_cast<const float4*>(p + i);
        v.x *= inv * g[i]; v.y *= inv * g[i+1]; v.z *= inv * g[i+2]; v.w *= inv * g[i+3];
        uint32_t h0, l0, h1, l1;
        split2(v.x, v.y, h0, l0);
        split2(v.z, v.w, h1, l1);
        hp[i/2] = h0; hp[i/2+1] = h1;
        lp[i/2] = l0; lp[i/2+1] = l1;
    }
}

// ---------------- bf16x3 GEMM core, 3-stage cp.async pipeline ----------------
#define GS_AH 0
#define GS_AL 8192
#define GS_BH 16384
#define GS_BL 24576
#define GS_STAGE 32768
#define GEMM_SMEM (3*GS_STAGE)

__device__ __forceinline__ void gemm_core(
    const __nv_bfloat16* __restrict__ Ah, const __nv_bfloat16* __restrict__ Al,
    const __nv_bfloat16* __restrict__ Bh, const __nv_bfloat16* __restrict__ Bl,
    float* __restrict__ C, __nv_bfloat16* __restrict__ Ch, __nv_bfloat16* __restrict__ Cl,
    int N, int K, int bm, int bn, char* sm)
{
    const uint32_t sb = smem_u32(sm);
    const int tid = threadIdx.x;
    const int NC = K >> 5;

    const int w = tid >> 5, lane = tid & 31;
    const int wm = (w & 1) * 64;
    const int wn = (w >> 1) * 32;
    const int mi  = lane >> 3;
    const int aro = (lane & 7) + (mi & 1) * 8;
    const int aks = (mi >> 1) * 8;
    const int bro = (lane & 7) + ((mi >> 1) & 1) * 8;
    const int bks = (mi & 1) * 8;

    float acc[4][4][4] = {};

    const int lr0 = tid >> 2;
    const int lc0 = tid & 3;
    const int lr1 = (256 + tid) >> 2;
    const int lc1 = (256 + tid) & 3;
    const uint32_t do0 = sw64((uint32_t)(lr0 * 64 + lc0 * 16));
    const uint32_t do1 = sw64((uint32_t)(lr1 * 64 + lc1 * 16));
    const bool bok0 = (bn + lr0) < N;
    const bool bok1 = (bn + lr1) < N;

    auto issue = [&](int c) {
        const int k0 = c << 5;
        const uint32_t st = sb + (uint32_t)(c % 3) * GS_STAGE;
        {
            const size_t go = (size_t)(bm + lr0) * K + k0 + lc0 * 8;
            cpa16(st + GS_AH + do0, Ah + go);
            cpa16(st + GS_AL + do0, Al + go);
            const size_t gb = (size_t)(bn + lr0) * K + k0 + lc0 * 8;
            cpa16p(st + GS_BH + do0, Bh + gb, bok0);
            cpa16p(st + GS_BL + do0, Bl + gb, bok0);
        }
        {
            const size_t go = (size_t)(bm + lr1) * K + k0 + lc1 * 8;
            cpa16(st + GS_AH + do1, Ah + go);
            cpa16(st + GS_AL + do1, Al + go);
            const size_t gb = (size_t)(bn + lr1) * K + k0 + lc1 * 8;
            cpa16p(st + GS_BH + do1, Bh + gb, bok1);
            cpa16p(st + GS_BL + do1, Bl + gb, bok1);
        }
        CPA_COMMIT();
    };

    auto compute = [&](int c) {
        const uint32_t st = sb + (uint32_t)(c % 3) * GS_STAGE;
        #pragma unroll
        for (int k16 = 0; k16 < 32; k16 += 16) {
            uint32_t A_h[4][4], B_h[2][4];
            #pragma unroll
            for (int f = 0; f < 4; f++) {
                const uint32_t x = (uint32_t)((wm + f * 16 + aro) * 64 + (k16 + aks) * 2);
                ldsm4(A_h[f], st + GS_AH + sw64(x));
            }
            #pragma unroll
            for (int g2 = 0; g2 < 2; g2++) {
                const uint32_t x = (uint32_t)((wn + g2 * 16 + bro) * 64 + (k16 + bks) * 2);
                ldsm4(B_h[g2], st + GS_BH + sw64(x));
            }
            #pragma unroll
            for (int f = 0; f < 4; f++)
                #pragma unroll
                for (int ni = 0; ni < 4; ni++)
                    mma_bf16(acc[f][ni], A_h[f], B_h[ni >> 1][(ni & 1) * 2],
                             B_h[ni >> 1][(ni & 1) * 2 + 1]);
            {
                uint32_t B_l[2][4];
                #pragma unroll
                for (int g2 = 0; g2 < 2; g2++) {
                    const uint32_t x = (uint32_t)((wn + g2 * 16 + bro) * 64 + (k16 + bks) * 2);
                    ldsm4(B_l[g2], st + GS_BL + sw64(x));
                }
                #pragma unroll
                for (int f = 0; f < 4; f++)
                    #pragma unroll
                    for (int ni = 0; ni < 4; ni++)
                        mma_bf16(acc[f][ni], A_h[f], B_l[ni >> 1][(ni & 1) * 2],
                                 B_l[ni >> 1][(ni & 1) * 2 + 1]);
            }
            {
                uint32_t A_l[4][4];
                #pragma unroll
                for (int f = 0; f < 4; f++) {
                    const uint32_t x = (uint32_t)((wm + f * 16 + aro) * 64 + (k16 + aks) * 2);
                    ldsm4(A_l[f], st + GS_AL + sw64(x));
                }
                #pragma unroll
                for (int f = 0; f < 4; f++)
                    #pragma unroll
                    for (int ni = 0; ni < 4; ni++)
                        mma_bf16(acc[f][ni], A_l[f], B_h[ni >> 1][(ni & 1) * 2],
                                 B_h[ni >> 1][(ni & 1) * 2 + 1]);
            }
        }
    };

    issue(0);
    issue(1);
    for (int c = 0; c < NC; c++) {
        if (c + 1 < NC) CPA_WAIT1(); else CPA_WAIT0();
        __syncthreads();
        if (c + 2 < NC) issue(c + 2);
        compute(c);
        __syncthreads();
    }

    const int gq = lane >> 2, t4 = lane & 3;
    if (C) {
        #pragma unroll
        for (int f = 0; f < 4; f++)
            #pragma unroll
            for (int ni = 0; ni < 4; ni++) {
                const int col = bn + wn + ni * 8 + t4 * 2;
                if (col < N) {
                    const int r = bm + wm + f * 16 + gq;
                    *reinterpret_cast<float2*>(&C[(size_t)r * N + col]) =
                        make_float2(acc[f][ni][0], acc[f][ni][1]);
                    *reinterpret_cast<float2*>(&C[(size_t)(r + 8) * N + col]) =
                        make_float2(acc[f][ni][2], acc[f][ni][3]);
                }
            }
    } else {
        #pragma unroll
        for (int f = 0; f < 4; f++)
            #pragma unroll
            for (int ni = 0; ni < 4; ni++) {
                const int col = bn + wn + ni * 8 + t4 * 2;
                if (col < N) {
                    const int r = bm + wm + f * 16 + gq;
                    uint32_t hp, lp;
                    split2(acc[f][ni][0], acc[f][ni][1], hp, lp);
                    *reinterpret_cast<uint32_t*>(&Ch[(size_t)r * N + col]) = hp;
                    *reinterpret_cast<uint32_t*>(&Cl[(size_t)r * N + col]) = lp;
                    split2(acc[f][ni][2], acc[f][ni][3], hp, lp);
                    *reinterpret_cast<uint32_t*>(&Ch[(size_t)(r + 8) * N + col]) = hp;
                    *reinterpret_cast<uint32_t*>(&Cl[(size_t)(r + 8) * N + col]) = lp;
                }
            }
    }
}

__global__ __launch_bounds__(256, 2) void gemm_bf(
    const __nv_bfloat16* __restrict__ Ah, const __nv_bfloat16* __restrict__ Al,
    const __nv_bfloat16* __restrict__ Bh, const __nv_bfloat16* __restrict__ Bl,
    float* __restrict__ C, __nv_bfloat16* __restrict__ Ch, __nv_bfloat16* __restrict__ Cl,
    int N, int K)
{
    extern __shared__ char sm[];
    gemm_core(Ah, Al, Bh, Bl, C, Ch, Cl, N, K, blockIdx.y * 128, blockIdx.x * 128, sm);
}

// merged qa+ckv GEMM: same A, same K
__global__ __launch_bounds__(256, 2) void gemm_dual(
    const __nv_bfloat16* __restrict__ Ah, const __nv_bfloat16* __restrict__ Al,
    const __nv_bfloat16* __restrict__ B1h, const __nv_bfloat16* __restrict__ B1l,
    float* __restrict__ C1, int N1, int split,
    const __nv_bfloat16* __restrict__ B2h, const __nv_bfloat16* __restrict__ B2l,
    float* __restrict__ C2, int N2, int K)
{
    extern __shared__ char sm[];
    const int bx = blockIdx.x;
    if (bx < split)
        gemm_core(Ah, Al, B1h, B1l, C1, nullptr, nullptr, N1, K,
                  blockIdx.y * 128, bx * 128, sm);
    else
        gemm_core(Ah, Al, B2h, B2l, C2, nullptr, nullptr, N2, K,
                  blockIdx.y * 128, (bx - split) * 128, sm);
}

// merged q+kv GEMM: different A, K, and output kind per segment
__global__ __launch_bounds__(256, 2) void gemm_dual2(
    const __nv_bfloat16* __restrict__ A1h, const __nv_bfloat16* __restrict__ A1l,
    const __nv_bfloat16* __restrict__ B1h, const __nv_bfloat16* __restrict__ B1l,
    float* __restrict__ C1, int N1, int K1, int split,
    const __nv_bfloat16* __restrict__ A2h, const __nv_bfloat16* __restrict__ A2l,
    const __nv_bfloat16* __restrict__ B2h, const __nv_bfloat16* __restrict__ B2l,
    __nv_bfloat16* __restrict__ C2h, __nv_bfloat16* __restrict__ C2l, int N2, int K2)
{
    extern __shared__ char sm[];
    const int bx = blockIdx.x;
    if (bx < split)
        gemm_core(A1h, A1l, B1h, B1l, C1, nullptr, nullptr, N1, K1,
                  blockIdx.y * 128, bx * 128, sm);
    else
        gemm_core(A2h, A2l, B2h, B2l, nullptr, C2h, C2l, N2, K2,
                  blockIdx.y * 128, (bx - split) * 128, sm);
}

// ---------------- RoPE ----------------
__global__ void rope_q_kernel(float* __restrict__ q)
{
    const int idx = blockIdx.x;
    const int row = idx / NH, h = idx % NH;
    const int t = row % SS;
    const int j = threadIdx.x;
    const double inv = exp(-log(10000.0) * (2.0 * j) / (double)DR);
    const double ang = (double)t * inv;
    const float c = (float)cos(ang), s = (float)sin(ang);
    float* p = q + (size_t)row * QW + h * QD + DN;
    const float x0 = p[j], x1 = p[j + 32];
    p[j]      = x0 * c - x1 * s;
    p[j + 32] = x1 * c + x0 * s;
}

__global__ void rope_k_split(const float* __restrict__ ckv,
                             __nv_bfloat16* __restrict__ kpeh, __nv_bfloat16* __restrict__ kpel)
{
    const int row = blockIdx.x;
    const int t = row % SS;
    const int j = threadIdx.x;
    const double inv = exp(-log(10000.0) * (2.0 * j) / (double)DR);
    const double ang = (double)t * inv;
    const float c = (float)cos(ang), s = (float)sin(ang);
    const float* p = ckv + (size_t)row * CKVW + KVLORA;
    const float x0 = p[j], x1 = p[j + 32];
    const float y0 = x0 * c - x1 * s;
    const float y1 = x1 * c + x0 * s;
    __nv_bfloat16 h0 = __float2bfloat16(y0);
    __nv_bfloat16 h1 = __float2bfloat16(y1);
    kpeh[(size_t)row * DR + j]      = h0;
    kpeh[(size_t)row * DR + j + 32] = h1;
    kpel[(size_t)row * DR + j]      = __float2bfloat16(y0 - __bfloat162float(h0));
    kpel[(size_t)row * DR + j + 32] = __float2bfloat16(y1 - __bfloat162float(h1));
}

// ---------------- tensor-core causal flash attention ----------------
#define FQH 0                 // 6*8192 = 49152
#define FQL 49152
#define FKB 98304             // stage s at FKB + s*49152; KH +0, KL +24576
#define FVB 196608            // VH +0, VL +16384
#define FLASH_SMEM 229376

__global__ __launch_bounds__(256) void flash_tc(
    const float* __restrict__ q,
    const __nv_bfloat16* __restrict__ kvh, const __nv_bfloat16* __restrict__ kvl,
    const __nv_bfloat16* __restrict__ kpeh, const __nv_bfloat16* __restrict__ kpel,
    __nv_bfloat16* __restrict__ atth, __nv_bfloat16* __restrict__ attl)
{
    extern __shared__ char sm[];
    const uint32_t sb = smem_u32(sm);

    // longest-first: big causal tiles (high qb) launch first
    const int qb = (int)gridDim.x - 1 - (int)blockIdx.x;
    const int h = blockIdx.y, b = blockIdx.z;
    const int tid = threadIdx.x;
    const int w = tid >> 5, lane = tid & 31;
    const int g = lane >> 2, t4 = lane & 3;
    const int mi  = lane >> 3;
    const int aro = (lane & 7) + (mi & 1) * 8;
    const int aks = (mi >> 1) * 8;
    const int bro = (lane & 7) + ((mi >> 1) & 1) * 8;
    const int bks = (mi & 1) * 8;
    const int hoff = h * (DN + DV);

    const int q0 = qb * 128;
    const int row0 = b * SS + q0;
    const int brow = b * SS;
    const float scale = rsqrtf((float)QD);
    const int n_tiles = 2 * qb + 2;

    auto issueK = [&](int kt) {
        const uint32_t base = sb + FKB + (kt & 1) * 49152;
        const int krow = brow + kt * 64;
        #pragma unroll
        for (int t = 0; t < 12; t++) {
            const int idx = t * 256 + tid;
            const int half = idx >= 1536;
            const int cidx = half ? idx - 1536 : idx;
            const int key = cidx / 24;
            const int c = cidx % 24;
            const int d = (c < 16) ? c * 8 : 128 + (c - 16) * 8;
            const uint32_t dst = base + (half ? 24576u : 0u) + (uint32_t)(d >> 5) * 4096
                               + sw64((uint32_t)(key * 64 + (d & 31) * 2));
            const __nv_bfloat16* src;
            if (c < 16) src = (half ? kvl : kvh) + (size_t)(krow + key) * KVW + hoff + d;
            else        src = (half ? kpel : kpeh) + (size_t)(krow + key) * DR + (d - 128);
            cpa16(dst, src);
        }
    };
    auto issueV = [&](int kt) {
        const int krow = brow + kt * 64;
        #pragma unroll
        for (int t = 0; t < 8; t++) {
            const int idx = t * 256 + tid;
            const int half = idx >= 1024;
            const int cidx = idx & 1023;
            const int key = cidx >> 4;
            const int d = (cidx & 15) * 8;
            const uint32_t dst = sb + FVB + (half ? 16384u : 0u)
                               + swz256((uint32_t)(key * 256 + d * 2));
            const __nv_bfloat16* src = (half ? kvl : kvh) + (size_t)(krow + key) * KVW + hoff + DN + d;
            cpa16(dst, src);
        }
    };

    #pragma unroll
    for (int t = 0; t < 24; t++) {
        const int idx = t * 256 + tid;
        const int r = idx / 48;
        const int c4 = (idx % 48) * 4;
        float4 v = *reinterpret_cast<const float4*>(&q[(size_t)(row0 + r) * QW + h * QD + c4]);
        v.x *= scale; v.y *= scale; v.z *= scale; v.w *= scale;
        const uint32_t off = (uint32_t)(c4 >> 5) * 8192 + sw64((uint32_t)(r * 64 + (c4 & 31) * 2));
        uint32_t h0, l0, h1, l1;
        split2(v.x, v.y, h0, l0);
        split2(v.z, v.w, h1, l1);
        *reinterpret_cast<uint2*>(sm + FQH + off) = make_uint2(h0, h1);
        *reinterpret_cast<uint2*>(sm + FQL + off) = make_uint2(l0, l1);
    }

    issueK(0);
    issueV(0);
    CPA_COMMIT();

    float of[16][4] = {};
    float m0 = -INFINITY, m1 = -INFINITY, l0 = 0.f, l1 = 0.f;

    for (int kt = 0; kt < n_tiles; kt++) {
        if (kt + 1 < n_tiles) { issueK(kt + 1); CPA_COMMIT(); CPA_WAIT1(); }
        else                  { CPA_WAIT0(); }
        __syncthreads();

        const int k0 = kt * 64;
        const uint32_t kbase = sb + FKB + (kt & 1) * 49152;

        float sf[8][4] = {};
        const uint32_t qax = (uint32_t)((w * 16 + aro) * 64 + aks * 2);
        #pragma unroll
        for (int s = 0; s < 12; s++) {
            uint32_t ah[4], al[4];
            const uint32_t qoff = (uint32_t)(s >> 1) * 8192 + sw64(qax + (s & 1) * 32);
            ldsm4(ah, sb + FQH + qoff);
            ldsm4(al, sb + FQL + qoff);
            #pragma unroll
            for (int g2 = 0; g2 < 4; g2++) {
                const uint32_t kx = (uint32_t)((g2 * 16 + bro) * 64 + bks * 2);
                const uint32_t koff = (uint32_t)(s >> 1) * 4096 + sw64(kx + (s & 1) * 32);
                uint32_t bh[4], bl[4];
                ldsm4(bh, kbase + koff);
                ldsm4(bl, kbase + 24576 + koff);
                #pragma unroll
                for (int sub = 0; sub < 2; sub++) {
                    const int ni = g2 * 2 + sub;
                    mma_bf16(sf[ni], ah, bh[sub * 2], bh[sub * 2 + 1]);
                    mma_bf16(sf[ni], ah, bl[sub * 2], bl[sub * 2 + 1]);
                    mma_bf16(sf[ni], al, bh[sub * 2], bh[sub * 2 + 1]);
                }
            }
        }

        if (kt >= 2 * qb) {
            const int qr0 = q0 + w * 16 + g;
            const int qr8 = qr0 + 8;
            #pragma unroll
            for (int ni = 0; ni < 8; ni++) {
                const int kp0 = k0 + ni * 8 + 2 * t4;
                const int kp1 = kp0 + 1;
                if (kp0 > qr0) sf[ni][0] = -1e30f;
                if (kp1 > qr0) sf[ni][1] = -1e30f;
                if (kp0 > qr8) sf[ni][2] = -1e30f;
                if (kp1 > qr8) sf[ni][3] = -1e30f;
            }
        }

        float tm0 = -INFINITY, tm1 = -INFINITY;
        #pragma unroll
        for (int ni = 0; ni < 8; ni++) {
            tm0 = fmaxf(tm0, fmaxf(sf[ni][0], sf[ni][1]));
            tm1 = fmaxf(tm1, fmaxf(sf[ni][2], sf[ni][3]));
        }
        #pragma unroll
        for (int o = 1; o < 4; o <<= 1) {
            tm0 = fmaxf(tm0, __shfl_xor_sync(0xffffffffu, tm0, o));
            tm1 = fmaxf(tm1, __shfl_xor_sync(0xffffffffu, tm1, o));
        }
        const float mn0 = fmaxf(m0, tm0), mn1 = fmaxf(m1, tm1);
        const float a0 = __expf(m0 - mn0), a1 = __expf(m1 - mn1);
        float ls0 = 0.f, ls1 = 0.f;
        #pragma unroll
        for (int ni = 0; ni < 8; ni++) {
            sf[ni][0] = __expf(sf[ni][0] - mn0); ls0 += sf[ni][0];
            sf[ni][1] = __expf(sf[ni][1] - mn0); ls0 += sf[ni][1];
            sf[ni][2] = __expf(sf[ni][2] - mn1); ls1 += sf[ni][2];
            sf[ni][3] = __expf(sf[ni][3] - mn1); ls1 += sf[ni][3];
        }
        #pragma unroll
        for (int o = 1; o < 4; o <<= 1) {
            ls0 += __shfl_xor_sync(0xffffffffu, ls0, o);
            ls1 += __shfl_xor_sync(0xffffffffu, ls1, o);
        }
        l0 = l0 * a0 + ls0; l1 = l1 * a1 + ls1;
        m0 = mn0; m1 = mn1;
        #pragma unroll
        for (int ni = 0; ni < 16; ni++) {
            of[ni][0] *= a0; of[ni][1] *= a0;
            of[ni][2] *= a1; of[ni][3] *= a1;
        }

        #pragma unroll
        for (int ks = 0; ks < 4; ks++) {
            uint32_t ph[4], pl[4];
            split2(sf[2*ks][0],   sf[2*ks][1],   ph[0], pl[0]);
            split2(sf[2*ks][2],   sf[2*ks][3],   ph[1], pl[1]);
            split2(sf[2*ks+1][0], sf[2*ks+1][1], ph[2], pl[2]);
            split2(sf[2*ks+1][2], sf[2*ks+1][3], ph[3], pl[3]);
            const int vkey = ks * 16 + (mi & 1) * 8 + (lane & 7);
            const int vdvo = (mi >> 1) * 8;
            #pragma unroll
            for (int g2 = 0; g2 < 8; g2++) {
                const uint32_t vo = swz256((uint32_t)(vkey * 256 + (g2 * 16 + vdvo) * 2));
                uint32_t vh[4], vl[4];
                ldsm4t(vh, sb + FVB + vo);
                ldsm4t(vl, sb + FVB + 16384 + vo);
                #pragma unroll
                for (int sub = 0; sub < 2; sub++) {
                    const int ni = g2 * 2 + sub;
                    mma_bf16(of[ni], ph, vh[sub * 2], vh[sub * 2 + 1]);
                    mma_bf16(of[ni], ph, vl[sub * 2], vl[sub * 2 + 1]);
                    mma_bf16(of[ni], pl, vh[sub * 2], vh[sub * 2 + 1]);
                }
            }
        }
        __syncthreads();
        if (kt + 1 < n_tiles) { issueV(kt + 1); CPA_COMMIT(); }
    }

    const float il0 = 1.f / l0, il1 = 1.f / l1;
    const int rg = row0 + w * 16 + g;
    #pragma unroll
    for (int ni = 0; ni < 16; ni++) {
        const int col = h * DV + ni * 8 + t4 * 2;
        uint32_t hp, lp;
        split2(of[ni][0] * il0, of[ni][1] * il0, hp, lp);
        *reinterpret_cast<uint32_t*>(&atth[(size_t)rg * OW + col]) = hp;
        *reinterpret_cast<uint32_t*>(&attl[(size_t)rg * OW + col]) = lp;
        split2(of[ni][2] * il1, of[ni][3] * il1, hp, lp);
        *reinterpret_cast<uint32_t*>(&atth[(size_t)(rg + 8) * OW + col]) = hp;
        *reinterpret_cast<uint32_t*>(&attl[(size_t)(rg + 8) * OW + col]) = lp;
    }
}

// ---------------- launch ----------------
extern "C" void kernel_launch(void* const* d_in, const int* in_sizes, int n_in,
                              void* d_out, int out_size)
{
    (void)in_sizes; (void)n_in; (void)out_size;
    const float* hidden = (const float*)d_in[0];
    const float* w_qa   = (const float*)d_in[1];
    const float* g_qa   = (const float*)d_in[2];
    const float* w_qb   = (const float*)d_in[3];
    const float* w_kva  = (const float*)d_in[4];
    const float* g_kva  = (const float*)d_in[5];
    const float* w_kvb  = (const float*)d_in[6];
    const float* w_o    = (const float*)d_in[7];
    float* out = (float*)d_out;

    float *qa, *q, *ckv;
    cudaGetSymbolAddress((void**)&qa,   d_qa);
    cudaGetSymbolAddress((void**)&q,    d_q);
    cudaGetSymbolAddress((void**)&ckv,  d_ckv);

    __nv_bfloat16 *hidh,*hidl,*wqah,*wqal,*wkvah,*wkval,*wqbh,*wqbl,*wkvbh,*wkvbl,*woh,*wol;
    __nv_bfloat16 *qanh,*qanl,*ckvnh,*ckvnl,*kvh,*kvl,*kpeh,*kpel,*atth,*attl;
    cudaGetSymbolAddress((void**)&hidh, d_hidh);   cudaGetSymbolAddress((void**)&hidl, d_hidl);
    cudaGetSymbolAddress((void**)&wqah, d_wqah);   cudaGetSymbolAddress((void**)&wqal, d_wqal);
    cudaGetSymbolAddress((void**)&wkvah, d_wkvah); cudaGetSymbolAddress((void**)&wkval, d_wkval);
    cudaGetSymbolAddress((void**)&wqbh, d_wqbh);   cudaGetSymbolAddress((void**)&wqbl, d_wqbl);
    cudaGetSymbolAddress((void**)&wkvbh, d_wkvbh); cudaGetSymbolAddress((void**)&wkvbl, d_wkvbl);
    cudaGetSymbolAddress((void**)&woh, d_woh);     cudaGetSymbolAddress((void**)&wol, d_wol);
    cudaGetSymbolAddress((void**)&qanh, d_qanh);   cudaGetSymbolAddress((void**)&qanl, d_qanl);
    cudaGetSymbolAddress((void**)&ckvnh, d_ckvnh); cudaGetSymbolAddress((void**)&ckvnl, d_ckvnl);
    cudaGetSymbolAddress((void**)&kvh, d_kvh);     cudaGetSymbolAddress((void**)&kvl, d_kvl);
    cudaGetSymbolAddress((void**)&kpeh, d_kpeh);   cudaGetSymbolAddress((void**)&kpel, d_kpel);
    cudaGetSymbolAddress((void**)&atth, d_atth);   cudaGetSymbolAddress((void**)&attl, d_attl);

    cudaFuncSetAttribute(gemm_bf, cudaFuncAttributeMaxDynamicSharedMemorySize, GEMM_SMEM);
    cudaFuncSetAttribute(gemm_dual, cudaFuncAttributeMaxDynamicSharedMemorySize, GEMM_SMEM);
    cudaFuncSetAttribute(gemm_dual2, cudaFuncAttributeMaxDynamicSharedMemorySize, GEMM_SMEM);
    cudaFuncSetAttribute(flash_tc, cudaFuncAttributeMaxDynamicSharedMemorySize, FLASH_SMEM);

    const dim3 blk(256);

    // 1: splits needed by the first GEMM (hidden, w_qa, w_kva)
    splitA_kernel<<<SPLITA_ROWS, 256>>>(hidden, hidh, hidl, w_qa, wqah, wqal, w_kva, wkvah, wkval);
    // 2: merged qa + ckv GEMM (shared A, K=2048)
    gemm_dual<<<dim3(QLORA/128 + (CKVW+127)/128, MTOT/128), blk, GEMM_SMEM>>>(
        hidh, hidl,
        wqah, wqal, qa, QLORA, QLORA/128,
        wkvah, wkval, ckv, CKVW, HDIM);
    // 3: remaining weight splits (w_qb, w_kvb, w_o) — off critical path
    splitB_kernel<<<SPLITB_ROWS, 256>>>(w_qb, wqbh, wqbl, w_kvb, wkvbh, wkvbl, w_o, woh, wol);
    // 4-5: fused rmsnorm + split
    rmsnorm_split<<<MTOT, 256>>>(qa, g_qa, QLORA, QLORA, qanh, qanl);
    rmsnorm_split<<<MTOT, 256>>>(ckv, g_kva, KVLORA, CKVW, ckvnh, ckvnl);
    // 6: merged q + kv GEMM (different A/K/output per segment)
    gemm_dual2<<<dim3(QW/128 + KVW/128, MTOT/128), blk, GEMM_SMEM>>>(
        qanh, qanl, wqbh, wqbl, q, QW, QLORA, QW/128,
        ckvnh, ckvnl, wkvbh, wkvbl, kvh, kvl, KVW, KVLORA);
    // 7-8: rope
    rope_q_kernel<<<MTOT * NH, 32>>>(q);
    rope_k_split<<<MTOT, 32>>>(ckv, kpeh, kpel);
    // 9: flash attention (longest-first qb order)
    flash_tc<<<dim3(SS/128, NH, BB), 256, FLASH_SMEM>>>(q, kvh, kvl, kpeh, kpel, atth, attl);
    // 10: out = attn @ w_o^T  [4096,2048]
    gemm_bf<<<dim3(HDIM/128, MTOT/128), blk, GEMM_SMEM>>>(atth, attl, woh, wol, out, nullptr, nullptr, HDIM, OW);
}

// round 12
// speedup vs baseline: 4.7822x; 1.0100x over previous
#include <cuda_runtime.h>
#include <cuda_bf16.h>
#include <math.h>
#include <stdint.h>

// ---------------- problem constants ----------------
#define HDIM   2048
#define NH     16
#define QLORA  1536
#define KVLORA 512
#define DN     128
#define DR     64
#define DV     128
#define QD     192
#define BB     2
#define SS     2048
#define MTOT   (BB*SS)      // 4096
#define CKVW   (KVLORA+DR)  // 576
#define KVW    (NH*(DN+DV)) // 4096
#define QW     (NH*QD)      // 3072
#define OW     (NH*DV)      // 2048

// ---------------- fp32 scratch ----------------
__device__ float d_qa  [(size_t)MTOT*QLORA];
__device__ float d_q   [(size_t)MTOT*QW];
__device__ float d_ckv [(size_t)MTOT*CKVW];

// ---------------- bf16 hi/lo scratch ----------------
__device__ __nv_bfloat16 d_hidh [(size_t)MTOT*HDIM],   d_hidl [(size_t)MTOT*HDIM];
__device__ __nv_bfloat16 d_wqah [(size_t)QLORA*HDIM],  d_wqal [(size_t)QLORA*HDIM];
__device__ __nv_bfloat16 d_wkvah[(size_t)CKVW*HDIM],   d_wkval[(size_t)CKVW*HDIM];
__device__ __nv_bfloat16 d_wqbh [(size_t)QW*QLORA],    d_wqbl [(size_t)QW*QLORA];
__device__ __nv_bfloat16 d_wkvbh[(size_t)KVW*KVLORA],  d_wkvbl[(size_t)KVW*KVLORA];
__device__ __nv_bfloat16 d_woh  [(size_t)HDIM*OW],     d_wol  [(size_t)HDIM*OW];
__device__ __nv_bfloat16 d_qanh [(size_t)MTOT*QLORA],  d_qanl [(size_t)MTOT*QLORA];
__device__ __nv_bfloat16 d_ckvnh[(size_t)MTOT*KVLORA], d_ckvnl[(size_t)MTOT*KVLORA];
__device__ __nv_bfloat16 d_kvh  [(size_t)MTOT*KVW],    d_kvl  [(size_t)MTOT*KVW];
__device__ __nv_bfloat16 d_kpeh [(size_t)MTOT*DR],     d_kpel [(size_t)MTOT*DR];
__device__ __nv_bfloat16 d_atth [(size_t)MTOT*OW],     d_attl [(size_t)MTOT*OW];

// ---------------- helpers ----------------
__device__ __forceinline__ uint32_t smem_u32(const void* p) {
    uint32_t a;
    asm("{ .reg .u64 t; cvta.to.shared.u64 t, %1; cvt.u32.u64 %0, t; }" : "=r"(a) : "l"(p));
    return a;
}

__device__ __forceinline__ void ldsm4(uint32_t r[4], uint32_t addr) {
    asm volatile("ldmatrix.sync.aligned.m8n8.x4.shared.b16 {%0,%1,%2,%3}, [%4];"
                 : "=r"(r[0]), "=r"(r[1]), "=r"(r[2]), "=r"(r[3]) : "r"(addr));
}

__device__ __forceinline__ void ldsm4t(uint32_t r[4], uint32_t addr) {
    asm volatile("ldmatrix.sync.aligned.m8n8.x4.trans.shared.b16 {%0,%1,%2,%3}, [%4];"
                 : "=r"(r[0]), "=r"(r[1]), "=r"(r[2]), "=r"(r[3]) : "r"(addr));
}

__device__ __forceinline__ void mma_bf16(float c[4], const uint32_t a[4],
                                         uint32_t b0, uint32_t b1) {
    asm volatile(
        "mma.sync.aligned.m16n8k16.row.col.f32.bf16.bf16.f32 "
        "{%0,%1,%2,%3}, {%4,%5,%6,%7}, {%8,%9}, {%0,%1,%2,%3};"
        : "+f"(c[0]), "+f"(c[1]), "+f"(c[2]), "+f"(c[3])
        : "r"(a[0]), "r"(a[1]), "r"(a[2]), "r"(a[3]), "r"(b0), "r"(b1));
}

__device__ __forceinline__ void split2(float x, float y, uint32_t& hp, uint32_t& lp) {
    __nv_bfloat16 hx = __float2bfloat16(x), hy = __float2bfloat16(y);
    __nv_bfloat16 lx = __float2bfloat16(x - __bfloat162float(hx));
    __nv_bfloat16 ly = __float2bfloat16(y - __bfloat162float(hy));
    hp = ((uint32_t)__bfloat16_as_ushort(hy) << 16) | __bfloat16_as_ushort(hx);
    lp = ((uint32_t)__bfloat16_as_ushort(ly) << 16) | __bfloat16_as_ushort(lx);
}

__device__ __forceinline__ uint32_t sw64(uint32_t o)   { return o ^ ((o >> 3) & 0x30); }
__device__ __forceinline__ uint32_t swz256(uint32_t o) { return o ^ (((o >> 8) & 7) << 4); }

__device__ __forceinline__ void cpa16(uint32_t dst, const void* src) {
    asm volatile("cp.async.cg.shared.global [%0], [%1], 16;" :: "r"(dst), "l"(src));
}
__device__ __forceinline__ void cpa16p(uint32_t dst, const void* src, bool valid) {
    int sz = valid ? 16 : 0;
    asm volatile("cp.async.cg.shared.global [%0], [%1], 16, %2;" :: "r"(dst), "l"(src), "r"(sz));
}
#define CPA_COMMIT() asm volatile("cp.async.commit_group;" ::: "memory")
#define CPA_WAIT1()  asm volatile("cp.async.wait_group 1;" ::: "memory")
#define CPA_WAIT0()  asm volatile("cp.async.wait_group 0;" ::: "memory")

// ---------------- merged fp32 -> bf16 hi/lo split (all 6 tensors) ----------------
__device__ __forceinline__ void split_row(const float* __restrict__ p, int cols,
                                          __nv_bfloat16* __restrict__ h,
                                          __nv_bfloat16* __restrict__ l)
{
    uint32_t* hp = reinterpret_cast<uint32_t*>(h);
    uint32_t* lp = reinterpret_cast<uint32_t*>(l);
    for (int i = threadIdx.x * 4; i < cols; i += blockDim.x * 4) {
        float4 v = *reinterpret_cast<const float4*>(p + i);
        uint32_t h0, l0, h1, l1;
        split2(v.x, v.y, h0, l0);
        split2(v.z, v.w, h1, l1);
        hp[i/2] = h0; hp[i/2+1] = h1;
        lp[i/2] = l0; lp[i/2+1] = l1;
    }
}

__global__ void splitAll_kernel(
    const float* __restrict__ hid, __nv_bfloat16* __restrict__ hidh, __nv_bfloat16* __restrict__ hidl,
    const float* __restrict__ wqa, __nv_bfloat16* __restrict__ wqah, __nv_bfloat16* __restrict__ wqal,
    const float* __restrict__ wkva, __nv_bfloat16* __restrict__ wkvah, __nv_bfloat16* __restrict__ wkval,
    const float* __restrict__ wqb, __nv_bfloat16* __restrict__ wqbh, __nv_bfloat16* __restrict__ wqbl,
    const float* __restrict__ wkvb, __nv_bfloat16* __restrict__ wkvbh, __nv_bfloat16* __restrict__ wkvbl,
    const float* __restrict__ wo, __nv_bfloat16* __restrict__ woh, __nv_bfloat16* __restrict__ wol)
{
    int r = blockIdx.x;
    if (r < MTOT) {
        split_row(hid + (size_t)r * HDIM, HDIM, hidh + (size_t)r * HDIM, hidl + (size_t)r * HDIM);
        return;
    }
    r -= MTOT;
    if (r < QLORA) {
        split_row(wqa + (size_t)r * HDIM, HDIM, wqah + (size_t)r * HDIM, wqal + (size_t)r * HDIM);
        return;
    }
    r -= QLORA;
    if (r < CKVW) {
        split_row(wkva + (size_t)r * HDIM, HDIM, wkvah + (size_t)r * HDIM, wkval + (size_t)r * HDIM);
        return;
    }
    r -= CKVW;
    if (r < QW) {
        split_row(wqb + (size_t)r * QLORA, QLORA, wqbh + (size_t)r * QLORA, wqbl + (size_t)r * QLORA);
        return;
    }
    r -= QW;
    if (r < KVW) {
        split_row(wkvb + (size_t)r * KVLORA, KVLORA, wkvbh + (size_t)r * KVLORA, wkvbl + (size_t)r * KVLORA);
        return;
    }
    r -= KVW;
    split_row(wo + (size_t)r * OW, OW, woh + (size_t)r * OW, wol + (size_t)r * OW);
}
#define SPLITALL_ROWS (MTOT + QLORA + CKVW + QW + KVW + HDIM)

// ---------------- fused RMSNorm + split (both norms, segmented) ----------------
__device__ __forceinline__ void rms_row(const float* __restrict__ p, const float* __restrict__ g,
                                        int D, __nv_bfloat16* __restrict__ h,
                                        __nv_bfloat16* __restrict__ l, float* sred)
{
    float ss = 0.f;
    for (int i = threadIdx.x; i < D; i += blockDim.x) { float v = p[i]; ss += v * v; }
    #pragma unroll
    for (int o = 16; o > 0; o >>= 1) ss += __shfl_xor_sync(0xffffffffu, ss, o);
    if ((threadIdx.x & 31) == 0) sred[threadIdx.x >> 5] = ss;
    __syncthreads();
    if (threadIdx.x < 8) {
        float v = sred[threadIdx.x];
        #pragma unroll
        for (int o = 4; o > 0; o >>= 1) v += __shfl_xor_sync(0xffu, v, o);
        if (threadIdx.x == 0) sred[0] = v;
    }
    __syncthreads();
    const float inv = rsqrtf(sred[0] / (float)D + 1e-6f);
    uint32_t* hp = reinterpret_cast<uint32_t*>(h);
    uint32_t* lp = reinterpret_cast<uint32_t*>(l);
    for (int i = threadIdx.x * 4; i < D; i += blockDim.x * 4) {
        float4 v = *reinterpret_cast<const float4*>(p + i);
        v.x *= inv * g[i]; v.y *= inv * g[i+1]; v.z *= inv * g[i+2]; v.w *= inv * g[i+3];
        uint32_t h0, l0, h1, l1;
        split2(v.x, v.y, h0, l0);
        split2(v.z, v.w, h1, l1);
        hp[i/2] = h0; hp[i/2+1] = h1;
        lp[i/2] = l0; lp[i/2+1] = l1;
    }
}

__global__ void rmsnorm2_kernel(
    const float* __restrict__ qa, const float* __restrict__ gqa,
    __nv_bfloat16* __restrict__ qanh, __nv_bfloat16* __restrict__ qanl,
    const float* __restrict__ ckv, const float* __restrict__ gkva,
    __nv_bfloat16* __restrict__ ckvnh, __nv_bfloat16* __restrict__ ckvnl)
{
    __shared__ float sred[8];
    int r = blockIdx.x;
    if (r < MTOT) {
        rms_row(qa + (size_t)r * QLORA, gqa, QLORA,
                qanh + (size_t)r * QLORA, qanl + (size_t)r * QLORA, sred);
    } else {
        r -= MTOT;
        rms_row(ckv + (size_t)r * CKVW, gkva, KVLORA,
                ckvnh + (size_t)r * KVLORA, ckvnl + (size_t)r * KVLORA, sred);
    }
}

// ---------------- bf16x3 GEMM core, 3-stage cp.async pipeline ----------------
#define GS_AH 0
#define GS_AL 8192
#define GS_BH 16384
#define GS_BL 24576
#define GS_STAGE 32768
#define GEMM_SMEM (3*GS_STAGE)

__device__ __forceinline__ void gemm_core(
    const __nv_bfloat16* __restrict__ Ah, const __nv_bfloat16* __restrict__ Al,
    const __nv_bfloat16* __restrict__ Bh, const __nv_bfloat16* __restrict__ Bl,
    float* __restrict__ C, __nv_bfloat16* __restrict__ Ch, __nv_bfloat16* __restrict__ Cl,
    int N, int K, int bm, int bn, char* sm)
{
    const uint32_t sb = smem_u32(sm);
    const int tid = threadIdx.x;
    const int NC = K >> 5;

    const int w = tid >> 5, lane = tid & 31;
    const int wm = (w & 1) * 64;
    const int wn = (w >> 1) * 32;
    const int mi  = lane >> 3;
    const int aro = (lane & 7) + (mi & 1) * 8;
    const int aks = (mi >> 1) * 8;
    const int bro = (lane & 7) + ((mi >> 1) & 1) * 8;
    const int bks = (mi & 1) * 8;

    float acc[4][4][4] = {};

    const int lr0 = tid >> 2;
    const int lc0 = tid & 3;
    const int lr1 = (256 + tid) >> 2;
    const int lc1 = (256 + tid) & 3;
    const uint32_t do0 = sw64((uint32_t)(lr0 * 64 + lc0 * 16));
    const uint32_t do1 = sw64((uint32_t)(lr1 * 64 + lc1 * 16));
    const bool bok0 = (bn + lr0) < N;
    const bool bok1 = (bn + lr1) < N;

    auto issue = [&](int c) {
        const int k0 = c << 5;
        const uint32_t st = sb + (uint32_t)(c % 3) * GS_STAGE;
        {
            const size_t go = (size_t)(bm + lr0) * K + k0 + lc0 * 8;
            cpa16(st + GS_AH + do0, Ah + go);
            cpa16(st + GS_AL + do0, Al + go);
            const size_t gb = (size_t)(bn + lr0) * K + k0 + lc0 * 8;
            cpa16p(st + GS_BH + do0, Bh + gb, bok0);
            cpa16p(st + GS_BL + do0, Bl + gb, bok0);
        }
        {
            const size_t go = (size_t)(bm + lr1) * K + k0 + lc1 * 8;
            cpa16(st + GS_AH + do1, Ah + go);
            cpa16(st + GS_AL + do1, Al + go);
            const size_t gb = (size_t)(bn + lr1) * K + k0 + lc1 * 8;
            cpa16p(st + GS_BH + do1, Bh + gb, bok1);
            cpa16p(st + GS_BL + do1, Bl + gb, bok1);
        }
        CPA_COMMIT();
    };

    auto compute = [&](int c) {
        const uint32_t st = sb + (uint32_t)(c % 3) * GS_STAGE;
        #pragma unroll
        for (int k16 = 0; k16 < 32; k16 += 16) {
            uint32_t A_h[4][4], B_h[2][4];
            #pragma unroll
            for (int f = 0; f < 4; f++) {
                const uint32_t x = (uint32_t)((wm + f * 16 + aro) * 64 + (k16 + aks) * 2);
                ldsm4(A_h[f], st + GS_AH + sw64(x));
            }
            #pragma unroll
            for (int g2 = 0; g2 < 2; g2++) {
                const uint32_t x = (uint32_t)((wn + g2 * 16 + bro) * 64 + (k16 + bks) * 2);
                ldsm4(B_h[g2], st + GS_BH + sw64(x));
            }
            #pragma unroll
            for (int f = 0; f < 4; f++)
                #pragma unroll
                for (int ni = 0; ni < 4; ni++)
                    mma_bf16(acc[f][ni], A_h[f], B_h[ni >> 1][(ni & 1) * 2],
                             B_h[ni >> 1][(ni & 1) * 2 + 1]);
            {
                uint32_t B_l[2][4];
                #pragma unroll
                for (int g2 = 0; g2 < 2; g2++) {
                    const uint32_t x = (uint32_t)((wn + g2 * 16 + bro) * 64 + (k16 + bks) * 2);
                    ldsm4(B_l[g2], st + GS_BL + sw64(x));
                }
                #pragma unroll
                for (int f = 0; f < 4; f++)
                    #pragma unroll
                    for (int ni = 0; ni < 4; ni++)
                        mma_bf16(acc[f][ni], A_h[f], B_l[ni >> 1][(ni & 1) * 2],
                                 B_l[ni >> 1][(ni & 1) * 2 + 1]);
            }
            {
                uint32_t A_l[4][4];
                #pragma unroll
                for (int f = 0; f < 4; f++) {
                    const uint32_t x = (uint32_t)((wm + f * 16 + aro) * 64 + (k16 + aks) * 2);
                    ldsm4(A_l[f], st + GS_AL + sw64(x));
                }
                #pragma unroll
                for (int f = 0; f < 4; f++)
                    #pragma unroll
                    for (int ni = 0; ni < 4; ni++)
                        mma_bf16(acc[f][ni], A_l[f], B_h[ni >> 1][(ni & 1) * 2],
                                 B_h[ni >> 1][(ni & 1) * 2 + 1]);
            }
        }
    };

    issue(0);
    issue(1);
    for (int c = 0; c < NC; c++) {
        if (c + 1 < NC) CPA_WAIT1(); else CPA_WAIT0();
        __syncthreads();
        if (c + 2 < NC) issue(c + 2);
        compute(c);
        __syncthreads();
    }

    const int gq = lane >> 2, t4 = lane & 3;
    if (C) {
        #pragma unroll
        for (int f = 0; f < 4; f++)
            #pragma unroll
            for (int ni = 0; ni < 4; ni++) {
                const int col = bn + wn + ni * 8 + t4 * 2;
                if (col < N) {
                    const int r = bm + wm + f * 16 + gq;
                    *reinterpret_cast<float2*>(&C[(size_t)r * N + col]) =
                        make_float2(acc[f][ni][0], acc[f][ni][1]);
                    *reinterpret_cast<float2*>(&C[(size_t)(r + 8) * N + col]) =
                        make_float2(acc[f][ni][2], acc[f][ni][3]);
                }
            }
    } else {
        #pragma unroll
        for (int f = 0; f < 4; f++)
            #pragma unroll
            for (int ni = 0; ni < 4; ni++) {
                const int col = bn + wn + ni * 8 + t4 * 2;
                if (col < N) {
                    const int r = bm + wm + f * 16 + gq;
                    uint32_t hp, lp;
                    split2(acc[f][ni][0], acc[f][ni][1], hp, lp);
                    *reinterpret_cast<uint32_t*>(&Ch[(size_t)r * N + col]) = hp;
                    *reinterpret_cast<uint32_t*>(&Cl[(size_t)r * N + col]) = lp;
                    split2(acc[f][ni][2], acc[f][ni][3], hp, lp);
                    *reinterpret_cast<uint32_t*>(&Ch[(size_t)(r + 8) * N + col]) = hp;
                    *reinterpret_cast<uint32_t*>(&Cl[(size_t)(r + 8) * N + col]) = lp;
                }
            }
    }
}

__global__ __launch_bounds__(256, 2) void gemm_bf(
    const __nv_bfloat16* __restrict__ Ah, const __nv_bfloat16* __restrict__ Al,
    const __nv_bfloat16* __restrict__ Bh, const __nv_bfloat16* __restrict__ Bl,
    float* __restrict__ C, __nv_bfloat16* __restrict__ Ch, __nv_bfloat16* __restrict__ Cl,
    int N, int K)
{
    extern __shared__ char sm[];
    gemm_core(Ah, Al, Bh, Bl, C, Ch, Cl, N, K, blockIdx.y * 128, blockIdx.x * 128, sm);
}

// merged qa+ckv GEMM: same A, same K
__global__ __launch_bounds__(256, 2) void gemm_dual(
    const __nv_bfloat16* __restrict__ Ah, const __nv_bfloat16* __restrict__ Al,
    const __nv_bfloat16* __restrict__ B1h, const __nv_bfloat16* __restrict__ B1l,
    float* __restrict__ C1, int N1, int split,
    const __nv_bfloat16* __restrict__ B2h, const __nv_bfloat16* __restrict__ B2l,
    float* __restrict__ C2, int N2, int K)
{
    extern __shared__ char sm[];
    const int bx = blockIdx.x;
    if (bx < split)
        gemm_core(Ah, Al, B1h, B1l, C1, nullptr, nullptr, N1, K,
                  blockIdx.y * 128, bx * 128, sm);
    else
        gemm_core(Ah, Al, B2h, B2l, C2, nullptr, nullptr, N2, K,
                  blockIdx.y * 128, (bx - split) * 128, sm);
}

// merged q+kv GEMM: different A, K, and output kind per segment
__global__ __launch_bounds__(256, 2) void gemm_dual2(
    const __nv_bfloat16* __restrict__ A1h, const __nv_bfloat16* __restrict__ A1l,
    const __nv_bfloat16* __restrict__ B1h, const __nv_bfloat16* __restrict__ B1l,
    float* __restrict__ C1, int N1, int K1, int split,
    const __nv_bfloat16* __restrict__ A2h, const __nv_bfloat16* __restrict__ A2l,
    const __nv_bfloat16* __restrict__ B2h, const __nv_bfloat16* __restrict__ B2l,
    __nv_bfloat16* __restrict__ C2h, __nv_bfloat16* __restrict__ C2l, int N2, int K2)
{
    extern __shared__ char sm[];
    const int bx = blockIdx.x;
    if (bx < split)
        gemm_core(A1h, A1l, B1h, B1l, C1, nullptr, nullptr, N1, K1,
                  blockIdx.y * 128, bx * 128, sm);
    else
        gemm_core(A2h, A2l, B2h, B2l, nullptr, C2h, C2l, N2, K2,
                  blockIdx.y * 128, (bx - split) * 128, sm);
}

// ---------------- RoPE ----------------
__global__ void rope_q_kernel(float* __restrict__ q)
{
    const int idx = blockIdx.x;
    const int row = idx / NH, h = idx % NH;
    const int t = row % SS;
    const int j = threadIdx.x;
    const double inv = exp(-log(10000.0) * (2.0 * j) / (double)DR);
    const double ang = (double)t * inv;
    const float c = (float)cos(ang), s = (float)sin(ang);
    float* p = q + (size_t)row * QW + h * QD + DN;
    const float x0 = p[j], x1 = p[j + 32];
    p[j]      = x0 * c - x1 * s;
    p[j + 32] = x1 * c + x0 * s;
}

__global__ void rope_k_split(const float* __restrict__ ckv,
                             __nv_bfloat16* __restrict__ kpeh, __nv_bfloat16* __restrict__ kpel)
{
    const int row = blockIdx.x;
    const int t = row % SS;
    const int j = threadIdx.x;
    const double inv = exp(-log(10000.0) * (2.0 * j) / (double)DR);
    const double ang = (double)t * inv;
    const float c = (float)cos(ang), s = (float)sin(ang);
    const float* p = ckv + (size_t)row * CKVW + KVLORA;
    const float x0 = p[j], x1 = p[j + 32];
    const float y0 = x0 * c - x1 * s;
    const float y1 = x1 * c + x0 * s;
    __nv_bfloat16 h0 = __float2bfloat16(y0);
    __nv_bfloat16 h1 = __float2bfloat16(y1);
    kpeh[(size_t)row * DR + j]      = h0;
    kpeh[(size_t)row * DR + j + 32] = h1;
    kpel[(size_t)row * DR + j]      = __float2bfloat16(y0 - __bfloat162float(h0));
    kpel[(size_t)row * DR + j + 32] = __float2bfloat16(y1 - __bfloat162float(h1));
}

// ---------------- tensor-core causal flash attention ----------------
// R12: MMA passes hoisted pass-major so consecutive MMAs hit different
// accumulators (same per-accumulator summation order -> bit-identical).
#define FQH 0                 // 6*8192 = 49152
#define FQL 49152
#define FKB 98304             // stage s at FKB + s*49152; KH +0, KL +24576
#define FVB 196608            // VH +0, VL +16384
#define FLASH_SMEM 229376

__global__ __launch_bounds__(256) void flash_tc(
    const float* __restrict__ q,
    const __nv_bfloat16* __restrict__ kvh, const __nv_bfloat16* __restrict__ kvl,
    const __nv_bfloat16* __restrict__ kpeh, const __nv_bfloat16* __restrict__ kpel,
    __nv_bfloat16* __restrict__ atth, __nv_bfloat16* __restrict__ attl)
{
    extern __shared__ char sm[];
    const uint32_t sb = smem_u32(sm);

    // longest-first: big causal tiles (high qb) launch first
    const int qb = (int)gridDim.x - 1 - (int)blockIdx.x;
    const int h = blockIdx.y, b = blockIdx.z;
    const int tid = threadIdx.x;
    const int w = tid >> 5, lane = tid & 31;
    const int g = lane >> 2, t4 = lane & 3;
    const int mi  = lane >> 3;
    const int aro = (lane & 7) + (mi & 1) * 8;
    const int aks = (mi >> 1) * 8;
    const int bro = (lane & 7) + ((mi >> 1) & 1) * 8;
    const int bks = (mi & 1) * 8;
    const int hoff = h * (DN + DV);

    const int q0 = qb * 128;
    const int row0 = b * SS + q0;
    const int brow = b * SS;
    const float scale = rsqrtf((float)QD);
    const int n_tiles = 2 * qb + 2;

    auto issueK = [&](int kt) {
        const uint32_t base = sb + FKB + (kt & 1) * 49152;
        const int krow = brow + kt * 64;
        #pragma unroll
        for (int t = 0; t < 12; t++) {
            const int idx = t * 256 + tid;
            const int half = idx >= 1536;
            const int cidx = half ? idx - 1536 : idx;
            const int key = cidx / 24;
            const int c = cidx % 24;
            const int d = (c < 16) ? c * 8 : 128 + (c - 16) * 8;
            const uint32_t dst = base + (half ? 24576u : 0u) + (uint32_t)(d >> 5) * 4096
                               + sw64((uint32_t)(key * 64 + (d & 31) * 2));
            const __nv_bfloat16* src;
            if (c < 16) src = (half ? kvl : kvh) + (size_t)(krow + key) * KVW + hoff + d;
            else        src = (half ? kpel : kpeh) + (size_t)(krow + key) * DR + (d - 128);
            cpa16(dst, src);
        }
    };
    auto issueV = [&](int kt) {
        const int krow = brow + kt * 64;
        #pragma unroll
        for (int t = 0; t < 8; t++) {
            const int idx = t * 256 + tid;
            const int half = idx >= 1024;
            const int cidx = idx & 1023;
            const int key = cidx >> 4;
            const int d = (cidx & 15) * 8;
            const uint32_t dst = sb + FVB + (half ? 16384u : 0u)
                               + swz256((uint32_t)(key * 256 + d * 2));
            const __nv_bfloat16* src = (half ? kvl : kvh) + (size_t)(krow + key) * KVW + hoff + DN + d;
            cpa16(dst, src);
        }
    };

    #pragma unroll
    for (int t = 0; t < 24; t++) {
        const int idx = t * 256 + tid;
        const int r = idx / 48;
        const int c4 = (idx % 48) * 4;
        float4 v = *reinterpret_cast<const float4*>(&q[(size_t)(row0 + r) * QW + h * QD + c4]);
        v.x *= scale; v.y *= scale; v.z *= scale; v.w *= scale;
        const uint32_t off = (uint32_t)(c4 >> 5) * 8192 + sw64((uint32_t)(r * 64 + (c4 & 31) * 2));
        uint32_t h0, l0, h1, l1;
        split2(v.x, v.y, h0, l0);
        split2(v.z, v.w, h1, l1);
        *reinterpret_cast<uint2*>(sm + FQH + off) = make_uint2(h0, h1);
        *reinterpret_cast<uint2*>(sm + FQL + off) = make_uint2(l0, l1);
    }

    issueK(0);
    issueV(0);
    CPA_COMMIT();

    float of[16][4] = {};
    float m0 = -INFINITY, m1 = -INFINITY, l0 = 0.f, l1 = 0.f;

    for (int kt = 0; kt < n_tiles; kt++) {
        if (kt + 1 < n_tiles) { issueK(kt + 1); CPA_COMMIT(); CPA_WAIT1(); }
        else                  { CPA_WAIT0(); }
        __syncthreads();

        const int k0 = kt * 64;
        const uint32_t kbase = sb + FKB + (kt & 1) * 49152;

        // S = Q @ K^T  — pass-major, 8 independent accumulators per pass
        float sf[8][4] = {};
        const uint32_t qax = (uint32_t)((w * 16 + aro) * 64 + aks * 2);
        #pragma unroll
        for (int s = 0; s < 12; s++) {
            uint32_t ah[4], al[4];
            const uint32_t qoff = (uint32_t)(s >> 1) * 8192 + sw64(qax + (s & 1) * 32);
            ldsm4(ah, sb + FQH + qoff);
            ldsm4(al, sb + FQL + qoff);
            uint32_t bh[4][4], bl[4][4];
            #pragma unroll
            for (int g2 = 0; g2 < 4; g2++) {
                const uint32_t kx = (uint32_t)((g2 * 16 + bro) * 64 + bks * 2);
                const uint32_t koff = (uint32_t)(s >> 1) * 4096 + sw64(kx + (s & 1) * 32);
                ldsm4(bh[g2], kbase + koff);
                ldsm4(bl[g2], kbase + 24576 + koff);
            }
            #pragma unroll
            for (int g2 = 0; g2 < 4; g2++)
                #pragma unroll
                for (int sub = 0; sub < 2; sub++)
                    mma_bf16(sf[g2 * 2 + sub], ah, bh[g2][sub * 2], bh[g2][sub * 2 + 1]);
            #pragma unroll
            for (int g2 = 0; g2 < 4; g2++)
                #pragma unroll
                for (int sub = 0; sub < 2; sub++)
                    mma_bf16(sf[g2 * 2 + sub], ah, bl[g2][sub * 2], bl[g2][sub * 2 + 1]);
            #pragma unroll
            for (int g2 = 0; g2 < 4; g2++)
                #pragma unroll
                for (int sub = 0; sub < 2; sub++)
                    mma_bf16(sf[g2 * 2 + sub], al, bh[g2][sub * 2], bh[g2][sub * 2 + 1]);
        }

        if (kt >= 2 * qb) {
            const int qr0 = q0 + w * 16 + g;
            const int qr8 = qr0 + 8;
            #pragma unroll
            for (int ni = 0; ni < 8; ni++) {
                const int kp0 = k0 + ni * 8 + 2 * t4;
                const int kp1 = kp0 + 1;
                if (kp0 > qr0) sf[ni][0] = -1e30f;
                if (kp1 > qr0) sf[ni][1] = -1e30f;
                if (kp0 > qr8) sf[ni][2] = -1e30f;
                if (kp1 > qr8) sf[ni][3] = -1e30f;
            }
        }

        float tm0 = -INFINITY, tm1 = -INFINITY;
        #pragma unroll
        for (int ni = 0; ni < 8; ni++) {
            tm0 = fmaxf(tm0, fmaxf(sf[ni][0], sf[ni][1]));
            tm1 = fmaxf(tm1, fmaxf(sf[ni][2], sf[ni][3]));
        }
        #pragma unroll
        for (int o = 1; o < 4; o <<= 1) {
            tm0 = fmaxf(tm0, __shfl_xor_sync(0xffffffffu, tm0, o));
            tm1 = fmaxf(tm1, __shfl_xor_sync(0xffffffffu, tm1, o));
        }
        const float mn0 = fmaxf(m0, tm0), mn1 = fmaxf(m1, tm1);
        const float a0 = __expf(m0 - mn0), a1 = __expf(m1 - mn1);
        float ls0 = 0.f, ls1 = 0.f;
        #pragma unroll
        for (int ni = 0; ni < 8; ni++) {
            sf[ni][0] = __expf(sf[ni][0] - mn0); ls0 += sf[ni][0];
            sf[ni][1] = __expf(sf[ni][1] - mn0); ls0 += sf[ni][1];
            sf[ni][2] = __expf(sf[ni][2] - mn1); ls1 += sf[ni][2];
            sf[ni][3] = __expf(sf[ni][3] - mn1); ls1 += sf[ni][3];
        }
        #pragma unroll
        for (int o = 1; o < 4; o <<= 1) {
            ls0 += __shfl_xor_sync(0xffffffffu, ls0, o);
            ls1 += __shfl_xor_sync(0xffffffffu, ls1, o);
        }
        l0 = l0 * a0 + ls0; l1 = l1 * a1 + ls1;
        m0 = mn0; m1 = mn1;
        #pragma unroll
        for (int ni = 0; ni < 16; ni++) {
            of[ni][0] *= a0; of[ni][1] *= a0;
            of[ni][2] *= a1; of[ni][3] *= a1;
        }

        // O += P @ V — pass-major over g2 pairs (4 accumulators rotating)
        #pragma unroll
        for (int ks = 0; ks < 4; ks++) {
            uint32_t ph[4], pl[4];
            split2(sf[2*ks][0],   sf[2*ks][1],   ph[0], pl[0]);
            split2(sf[2*ks][2],   sf[2*ks][3],   ph[1], pl[1]);
            split2(sf[2*ks+1][0], sf[2*ks+1][1], ph[2], pl[2]);
            split2(sf[2*ks+1][2], sf[2*ks+1][3], ph[3], pl[3]);
            const int vkey = ks * 16 + (mi & 1) * 8 + (lane & 7);
            const int vdvo = (mi >> 1) * 8;
            #pragma unroll
            for (int gp = 0; gp < 4; gp++) {
                uint32_t vh[2][4], vl[2][4];
                #pragma unroll
                for (int j = 0; j < 2; j++) {
                    const int g2 = gp * 2 + j;
                    const uint32_t vo = swz256((uint32_t)(vkey * 256 + (g2 * 16 + vdvo) * 2));
                    ldsm4t(vh[j], sb + FVB + vo);
                    ldsm4t(vl[j], sb + FVB + 16384 + vo);
                }
                #pragma unroll
                for (int j = 0; j < 2; j++)
                    #pragma unroll
                    for (int sub = 0; sub < 2; sub++)
                        mma_bf16(of[(gp * 2 + j) * 2 + sub], ph, vh[j][sub * 2], vh[j][sub * 2 + 1]);
                #pragma unroll
                for (int j = 0; j < 2; j++)
                    #pragma unroll
                    for (int sub = 0; sub < 2; sub++)
                        mma_bf16(of[(gp * 2 + j) * 2 + sub], ph, vl[j][sub * 2], vl[j][sub * 2 + 1]);
                #pragma unroll
                for (int j = 0; j < 2; j++)
                    #pragma unroll
                    for (int sub = 0; sub < 2; sub++)
                        mma_bf16(of[(gp * 2 + j) * 2 + sub], pl, vh[j][sub * 2], vh[j][sub * 2 + 1]);
            }
        }
        __syncthreads();
        if (kt + 1 < n_tiles) { issueV(kt + 1); CPA_COMMIT(); }
    }

    const float il0 = 1.f / l0, il1 = 1.f / l1;
    const int rg = row0 + w * 16 + g;
    #pragma unroll
    for (int ni = 0; ni < 16; ni++) {
        const int col = h * DV + ni * 8 + t4 * 2;
        uint32_t hp, lp;
        split2(of[ni][0] * il0, of[ni][1] * il0, hp, lp);
        *reinterpret_cast<uint32_t*>(&atth[(size_t)rg * OW + col]) = hp;
        *reinterpret_cast<uint32_t*>(&attl[(size_t)rg * OW + col]) = lp;
        split2(of[ni][2] * il1, of[ni][3] * il1, hp, lp);
        *reinterpret_cast<uint32_t*>(&atth[(size_t)(rg + 8) * OW + col]) = hp;
        *reinterpret_cast<uint32_t*>(&attl[(size_t)(rg + 8) * OW + col]) = lp;
    }
}

// ---------------- launch ----------------
extern "C" void kernel_launch(void* const* d_in, const int* in_sizes, int n_in,
                              void* d_out, int out_size)
{
    (void)in_sizes; (void)n_in; (void)out_size;
    const float* hidden = (const float*)d_in[0];
    const float* w_qa   = (const float*)d_in[1];
    const float* g_qa   = (const float*)d_in[2];
    const float* w_qb   = (const float*)d_in[3];
    const float* w_kva  = (const float*)d_in[4];
    const float* g_kva  = (const float*)d_in[5];
    const float* w_kvb  = (const float*)d_in[6];
    const float* w_o    = (const float*)d_in[7];
    float* out = (float*)d_out;

    float *qa, *q, *ckv;
    cudaGetSymbolAddress((void**)&qa,   d_qa);
    cudaGetSymbolAddress((void**)&q,    d_q);
    cudaGetSymbolAddress((void**)&ckv,  d_ckv);

    __nv_bfloat16 *hidh,*hidl,*wqah,*wqal,*wkvah,*wkval,*wqbh,*wqbl,*wkvbh,*wkvbl,*woh,*wol;
    __nv_bfloat16 *qanh,*qanl,*ckvnh,*ckvnl,*kvh,*kvl,*kpeh,*kpel,*atth,*attl;
    cudaGetSymbolAddress((void**)&hidh, d_hidh);   cudaGetSymbolAddress((void**)&hidl, d_hidl);
    cudaGetSymbolAddress((void**)&wqah, d_wqah);   cudaGetSymbolAddress((void**)&wqal, d_wqal);
    cudaGetSymbolAddress((void**)&wkvah, d_wkvah); cudaGetSymbolAddress((void**)&wkval, d_wkval);
    cudaGetSymbolAddress((void**)&wqbh, d_wqbh);   cudaGetSymbolAddress((void**)&wqbl, d_wqbl);
    cudaGetSymbolAddress((void**)&wkvbh, d_wkvbh); cudaGetSymbolAddress((void**)&wkvbl, d_wkvbl);
    cudaGetSymbolAddress((void**)&woh, d_woh);     cudaGetSymbolAddress((void**)&wol, d_wol);
    cudaGetSymbolAddress((void**)&qanh, d_qanh);   cudaGetSymbolAddress((void**)&qanl, d_qanl);
    cudaGetSymbolAddress((void**)&ckvnh, d_ckvnh); cudaGetSymbolAddress((void**)&ckvnl, d_ckvnl);
    cudaGetSymbolAddress((void**)&kvh, d_kvh);     cudaGetSymbolAddress((void**)&kvl, d_kvl);
    cudaGetSymbolAddress((void**)&kpeh, d_kpeh);   cudaGetSymbolAddress((void**)&kpel, d_kpel);
    cudaGetSymbolAddress((void**)&atth, d_atth);   cudaGetSymbolAddress((void**)&attl, d_attl);

    cudaFuncSetAttribute(gemm_bf, cudaFuncAttributeMaxDynamicSharedMemorySize, GEMM_SMEM);
    cudaFuncSetAttribute(gemm_dual, cudaFuncAttributeMaxDynamicSharedMemorySize, GEMM_SMEM);
    cudaFuncSetAttribute(gemm_dual2, cudaFuncAttributeMaxDynamicSharedMemorySize, GEMM_SMEM);
    cudaFuncSetAttribute(flash_tc, cudaFuncAttributeMaxDynamicSharedMemorySize, FLASH_SMEM);

    const dim3 blk(256);

    // 1: all input splits
    splitAll_kernel<<<SPLITALL_ROWS, 256>>>(
        hidden, hidh, hidl, w_qa, wqah, wqal, w_kva, wkvah, wkval,
        w_qb, wqbh, wqbl, w_kvb, wkvbh, wkvbl, w_o, woh, wol);
    // 2: merged qa + ckv GEMM (shared A, K=2048)
    gemm_dual<<<dim3(QLORA/128 + (CKVW+127)/128, MTOT/128), blk, GEMM_SMEM>>>(
        hidh, hidl,
        wqah, wqal, qa, QLORA, QLORA/128,
        wkvah, wkval, ckv, CKVW, HDIM);
    // 3: both rmsnorm+split in one launch
    rmsnorm2_kernel<<<2 * MTOT, 256>>>(qa, g_qa, qanh, qanl, ckv, g_kva, ckvnh, ckvnl);
    // 4: merged q + kv GEMM
    gemm_dual2<<<dim3(QW/128 + KVW/128, MTOT/128), blk, GEMM_SMEM>>>(
        qanh, qanl, wqbh, wqbl, q, QW, QLORA, QW/128,
        ckvnh, ckvnl, wkvbh, wkvbl, kvh, kvl, KVW, KVLORA);
    // 5-6: rope
    rope_q_kernel<<<MTOT * NH, 32>>>(q);
    rope_k_split<<<MTOT, 32>>>(ckv, kpeh, kpel);
    // 7: flash attention (longest-first qb order, pass-major MMAs)
    flash_tc<<<dim3(SS/128, NH, BB), 256, FLASH_SMEM>>>(q, kvh, kvl, kpeh, kpel, atth, attl);
    // 8: out = attn @ w_o^T  [4096,2048]
    gemm_bf<<<dim3(HDIM/128, MTOT/128), blk, GEMM_SMEM>>>(atth, attl, woh, wol, out, nullptr, nullptr, HDIM, OW);
}